// round 12
// baseline (speedup 1.0000x reference)
#include <cuda_runtime.h>
#include <cuda_bf16.h>
#include <math.h>
#include <stdint.h>

// ---------------- static problem sizes ----------------
#define CC    768
#define D0    16
#define H0    32
#define W0    32
#define NQ    16384
#define NDQ   2048
#define NAQ   14336
#define RQ    8192
#define UQ    6144
#define MQ    8192
#define N2    2048
#define NDK   256
#define NAK   1792
#define RK    1024
#define UK    768
#define MK    1024
#define HEADS 8
#define HD    96

typedef __nv_bfloat16 bf16;
typedef unsigned long long u64;

// ---------------- device scratch ----------------
__device__ float g_xk[N2 * CC];
__device__ float g_mnq[NQ * CC];
__device__ float g_mnk[N2 * CC];
__device__ u64   g_keyq[NAQ];
__device__ u64   g_keyk[NAK];
__device__ float g_nvq[NAQ];
__device__ float g_nvk[NAK];
__device__ uint32_t g_rmaxu[NAQ];
__device__ int g_permq[NAQ];
__device__ int g_permk[NAK];
__device__ int g_dstq[RQ];
__device__ int g_dstk[RK];
__device__ int g_cntq[NDQ];
__device__ int g_cntk[NDK];
__device__ int g_aq[NAQ];
__device__ int g_bq[NDQ];
__device__ int g_ak[NAK];
__device__ int g_bk[NDK];
__device__ int g_ctok[8 * N2];
__device__ float g_xq[MQ * CC];
__device__ float g_xkm[MK * CC];
__device__ float g_kvm[MK * 2 * CC];
__device__ float g_S[(long)HEADS * MQ * MK];
__device__ float g_proj[MQ * CC];

// bf16 planes
__device__ bf16 g_x3[3][NQ * CC];
__device__ bf16 g_bt3[3][8 * CC * CC];
__device__ bf16 g_mq1[NQ * CC];
__device__ bf16 g_mk1[N2 * CC];
__device__ bf16 g_xq2[2][MQ * CC];
__device__ bf16 g_xkm2[2][MK * CC];
__device__ bf16 g_wq2[2][CC * CC];
__device__ bf16 g_wkv2[2][2 * CC * CC];
__device__ bf16 g_wp2[2][CC * CC];
__device__ bf16 g_qp2[2][HEADS * MQ * HD];
__device__ bf16 g_kp2[2][HEADS * MK * HD];
__device__ bf16 g_vp2[2][HEADS * HD * MK];
__device__ bf16 g_ao2[2][MQ * CC];
__device__ bf16 g_sh[(long)HEADS * MQ * MK];
__device__ bf16 g_sl[(long)HEADS * MQ * MK];

__device__ __forceinline__ uint32_t smem_u32(const void* p) {
    uint32_t a;
    asm("{ .reg .u64 t; cvta.to.shared.u64 t, %1; cvt.u32.u64 %0, t; }" : "=r"(a) : "l"(p));
    return a;
}
__device__ __forceinline__ uint32_t pkbf(bf16 a, bf16 b) {
    return (uint32_t)__bfloat16_as_ushort(a) | ((uint32_t)__bfloat16_as_ushort(b) << 16);
}
__device__ __forceinline__ uint32_t encf(float f) {
    uint32_t u = __float_as_uint(f);
    return (u & 0x80000000u) ? ~u : (u | 0x80000000u);
}
__device__ __forceinline__ float decf(uint32_t o) {
    uint32_t u = (o & 0x80000000u) ? (o ^ 0x80000000u) : ~o;
    return __uint_as_float(u);
}
#define SWZ(o) ((o) ^ (((o) >> 3) & 0x70))
#define MMA16816(d, a, b0v, b1v) \
    asm volatile("mma.sync.aligned.m16n8k16.row.col.f32.bf16.bf16.f32 " \
        "{%0,%1,%2,%3}, {%4,%5,%6,%7}, {%8,%9}, {%0,%1,%2,%3};" \
        : "+f"((d)[0]), "+f"((d)[1]), "+f"((d)[2]), "+f"((d)[3]) \
        : "r"((a)[0]), "r"((a)[1]), "r"((a)[2]), "r"((a)[3]), "r"(b0v), "r"(b1v))
#define LDSM4(r, a) \
    asm volatile("ldmatrix.sync.aligned.m8n8.x4.shared.b16 {%0,%1,%2,%3}, [%4];" \
        : "=r"((r)[0]), "=r"((r)[1]), "=r"((r)[2]), "=r"((r)[3]) : "r"(a))
#define CPA(dst, src, sz) \
    asm volatile("cp.async.cg.shared.global [%0], [%1], 16, %2;" :: "r"(dst), "l"(src), "r"(sz) : "memory")
#define CPCOMMIT() asm volatile("cp.async.commit_group;" ::: "memory")
#define CPWAIT1()  asm volatile("cp.async.wait_group 1;" ::: "memory")

// ---------------- pipelined ldmatrix mma.sync split-bf16 GEMM ----------------
// C[M,N] = scale * A[M,K] @ B[N,K]^T (+bias), over ntap segments.
// Block 64 x TN, k-tile 64 (K may be mult of 32; tail zero-filled & skipped;
// all cp.async source addresses clamped valid even at size 0),
// STAGES-deep cp.async pipeline, 16 warps (4m x 4n), warp tile 16 x (TN/4).
// EPI: 0 fp32 C; 1 fp32 C + atomicMax ordered-uint rowmax; 2 head-major bf16
// hi/lo split (P0/P1, per-head stride phs, 96-wide rows); 3 bf16 hi/lo split
// at C-addressing into P0/P1.
template <int NPR, int TN, int STAGES, int EPI>
__global__ void __launch_bounds__(512, 2) mmg(
    const bf16* A0, const bf16* A1, const bf16* A2, long lda, long ahs,
    const bf16* B0, const bf16* B1, const bf16* B2, long ldb, long bhs, long bseg,
    float* C, long ldc, long chs, const float* bias, float scale,
    bf16* P0, bf16* P1, long phs, uint32_t* rmaxu,
    int N, int K, int ntap, const int* gA, int gAs, const int* gB)
{
    constexpr int nA = (NPR == 6) ? 3 : (NPR == 3) ? 2 : 1;
    constexpr int nB = nA;
    constexpr int PLA = 8192;          // 64 rows x 128 B
    constexpr int PLB = TN * 128;
    constexpr int STG = nA * PLA + nB * PLB;
    constexpr int NJ = TN / 32;
    extern __shared__ char sm[];
    const uint32_t su = smem_u32(sm);

    const int tid = threadIdx.x, lane = tid & 31, wid = tid >> 5;
    const int wm = wid >> 2, wn = wid & 3;
    const int m0 = blockIdx.y * 64, n0 = blockIdx.x * TN, z = blockIdx.z;
    const int lq = lane >> 2, lr = lane & 3;

    const int lrA = tid >> 3, secA = tid & 7;
    const int lrB = (TN == 128) ? (tid >> 2) : (tid >> 3);
    const int secB = (TN == 128) ? (tid & 3) : (tid & 7);
    const int nrow = n0 + lrB;
    const bool bval = nrow < N;
    const long brow = bval ? (gB ? (long)gB[nrow] : (long)nrow) : 0;
    const uint32_t bsz = bval ? 16u : 0u;

    const uint32_t dA0 = SWZ((uint32_t)(lrA * 128 + secA * 16));
    const uint32_t dB0 = (TN == 128) ? SWZ((uint32_t)(lrB * 128 + secB * 32))
                                     : SWZ((uint32_t)(lrB * 128 + secB * 16));
    const uint32_t dB1 = (TN == 128) ? SWZ((uint32_t)(lrB * 128 + secB * 32 + 16)) : 0u;

    const int kcd = (K + 63) >> 6;
    const int nch = ntap * kcd;
    const bf16* Ap[3] = {A0, A1, A2};
    const bf16* Bp[3] = {B0, B1, B2};

    float acc[NJ][4];
#pragma unroll
    for (int j = 0; j < NJ; j++)
#pragma unroll
        for (int t = 0; t < 4; t++) acc[j][t] = 0.f;

    auto issue = [&](int c) {
        const int stg = c % STAGES;
        const uint32_t sb = su + stg * STG;
        const int tap = c / kcd;
        const int k0 = (c - tap * kcd) << 6;
        const long arow = gA ? (long)gA[tap * gAs + m0 + lrA] : (long)(m0 + lrA);
        const uint32_t szA = (k0 + secA * 8 < K) ? 16u : 0u;
        const int kaA = szA ? (k0 + secA * 8) : 0;   // clamp addr when size 0
#pragma unroll
        for (int p = 0; p < nA; p++) {
            const bf16* s0 = Ap[p] + (long)z * ahs + arow * lda + kaA;
            CPA(sb + p * PLA + dA0, s0, szA);
        }
        if (TN == 128) {
            const uint32_t sz0 = (k0 + secB * 16 < K) ? bsz : 0u;
            const uint32_t sz1 = (k0 + secB * 16 + 8 < K) ? bsz : 0u;
            const int kb0 = sz0 ? (k0 + secB * 16) : 0;
            const int kb1 = sz1 ? (k0 + secB * 16 + 8) : 0;
#pragma unroll
            for (int p = 0; p < nB; p++) {
                const bf16* s0 = Bp[p] + (long)z * bhs + (long)tap * bseg + brow * ldb;
                CPA(sb + nA * PLA + p * PLB + dB0, s0 + kb0, sz0);
                CPA(sb + nA * PLA + p * PLB + dB1, s0 + kb1, sz1);
            }
        } else {
            const uint32_t sz0 = (k0 + secB * 8 < K) ? bsz : 0u;
            const int kb0 = sz0 ? (k0 + secB * 8) : 0;
#pragma unroll
            for (int p = 0; p < nB; p++) {
                const bf16* s0 = Bp[p] + (long)z * bhs + (long)tap * bseg + brow * ldb;
                CPA(sb + nA * PLA + p * PLB + dB0, s0 + kb0, sz0);
            }
        }
        CPCOMMIT();
    };

    auto compute = [&](int stg, int kslim) {
        const uint32_t sb = su + stg * STG;
        const int pa6[6] = {0, 0, 1, 1, 0, 2}, pb6[6] = {0, 1, 0, 1, 2, 0};
#pragma unroll
        for (int ks = 0; ks < 4; ks++) {
            if (ks >= kslim) break;
            uint32_t af[nA][4];
#pragma unroll
            for (int p = 0; p < nA; p++) {
                uint32_t off = (uint32_t)((wm * 16 + (lane & 15)) * 128
                                          + ks * 32 + ((lane >> 4) << 4));
                LDSM4(af[p], sb + p * PLA + SWZ(off));
            }
            uint32_t bl[nB][NJ], bh[nB][NJ];
            if constexpr (TN == 128) {
#pragma unroll
                for (int p = 0; p < nB; p++) {
                    uint32_t r0[4], r1[4];
                    uint32_t off0 = (uint32_t)((wn * 32 + (lane >> 3) * 8 + (lane & 7)) * 128 + ks * 32);
                    LDSM4(r0, sb + nA * PLA + p * PLB + SWZ(off0));
                    LDSM4(r1, sb + nA * PLA + p * PLB + SWZ(off0 + 16));
#pragma unroll
                    for (int j = 0; j < 4; j++) { bl[p][j] = r0[j]; bh[p][j] = r1[j]; }
                }
            } else {
#pragma unroll
                for (int p = 0; p < nB; p++) {
                    uint32_t r[4];
                    const int tileB = (lane >> 3) & 1, khB = lane >> 4;
                    uint32_t off = (uint32_t)((wn * 16 + tileB * 8 + (lane & 7)) * 128
                                              + ks * 32 + khB * 16);
                    LDSM4(r, sb + nA * PLA + p * PLB + SWZ(off));
                    bl[p][0] = r[0]; bl[p][1] = r[1]; bh[p][0] = r[2]; bh[p][1] = r[3];
                }
            }
#pragma unroll
            for (int pr = 0; pr < NPR; pr++) {
                const int pA = (NPR == 1) ? 0 : pa6[pr];
                const int pB = (NPR == 1) ? 0 : pb6[pr];
#pragma unroll
                for (int j = 0; j < NJ; j++)
                    MMA16816(acc[j], af[pA], bl[pB][j], bh[pB][j]);
            }
        }
    };

    issue(0);
    for (int c = 0; c < nch; c++) {
        if (c + 1 < nch) issue(c + 1);
        else CPCOMMIT();
        CPWAIT1();
        __syncthreads();
        const int k0c = (c % kcd) << 6;
        int kslim = (K - k0c + 15) >> 4; if (kslim > 4) kslim = 4;
        compute(c % STAGES, kslim);
        if (STAGES == 2) __syncthreads();
    }

    // ---- epilogue ----
    const int r = m0 + wm * 16 + lq;
    if constexpr (EPI == 0 || EPI == 1) {
        float mx0 = -3.4e38f, mx1 = -3.4e38f;
#pragma unroll
        for (int j = 0; j < NJ; j++) {
            const int cb = n0 + wn * (TN / 4) + j * 8 + lr * 2;
            if (cb < N) {
                float bb0 = bias ? bias[cb] : 0.f;
                float bb1 = bias ? bias[cb + 1] : 0.f;
                float v0 = acc[j][0] * scale + bb0, v1 = acc[j][1] * scale + bb1;
                float v2 = acc[j][2] * scale + bb0, v3 = acc[j][3] * scale + bb1;
                float* p0 = C + (long)z * chs + (long)r * ldc + cb;
                float* p1 = C + (long)z * chs + (long)(r + 8) * ldc + cb;
                p0[0] = v0; p0[1] = v1; p1[0] = v2; p1[1] = v3;
                if (EPI == 1) {
                    mx0 = fmaxf(mx0, fmaxf(v0, v1));
                    mx1 = fmaxf(mx1, fmaxf(v2, v3));
                }
            }
        }
        if constexpr (EPI == 1) {
            mx0 = fmaxf(mx0, __shfl_xor_sync(0xffffffffu, mx0, 1));
            mx0 = fmaxf(mx0, __shfl_xor_sync(0xffffffffu, mx0, 2));
            mx1 = fmaxf(mx1, __shfl_xor_sync(0xffffffffu, mx1, 1));
            mx1 = fmaxf(mx1, __shfl_xor_sync(0xffffffffu, mx1, 2));
            if (lr == 0) {
                atomicMax(&rmaxu[r], encf(mx0));
                atomicMax(&rmaxu[r + 8], encf(mx1));
            }
        }
    } else if constexpr (EPI == 2) {
#pragma unroll
        for (int j = 0; j < NJ; j++) {
            const int cb = n0 + wn * (TN / 4) + j * 8 + lr * 2;
            if (cb < N) {
                int h = cb / HD, k = cb - h * HD;
                float v0 = acc[j][0] * scale, v1 = acc[j][1] * scale;
                float v2 = acc[j][2] * scale, v3 = acc[j][3] * scale;
                bf16 h0 = __float2bfloat16(v0), h1 = __float2bfloat16(v1);
                bf16 h2 = __float2bfloat16(v2), h3 = __float2bfloat16(v3);
                bf16* q0 = P0 + (long)h * phs + (long)r * HD + k;
                bf16* l0 = P1 + (long)h * phs + (long)r * HD + k;
                q0[0] = h0; q0[1] = h1;
                l0[0] = __float2bfloat16(v0 - __bfloat162float(h0));
                l0[1] = __float2bfloat16(v1 - __bfloat162float(h1));
                bf16* q1 = P0 + (long)h * phs + (long)(r + 8) * HD + k;
                bf16* l1 = P1 + (long)h * phs + (long)(r + 8) * HD + k;
                q1[0] = h2; q1[1] = h3;
                l1[0] = __float2bfloat16(v2 - __bfloat162float(h2));
                l1[1] = __float2bfloat16(v3 - __bfloat162float(h3));
            }
        }
    } else {   // EPI == 3
#pragma unroll
        for (int j = 0; j < NJ; j++) {
            const int cb = n0 + wn * (TN / 4) + j * 8 + lr * 2;
            if (cb < N) {
                float v0 = acc[j][0] * scale, v1 = acc[j][1] * scale;
                float v2 = acc[j][2] * scale, v3 = acc[j][3] * scale;
                bf16 h0 = __float2bfloat16(v0), h1 = __float2bfloat16(v1);
                bf16 h2 = __float2bfloat16(v2), h3 = __float2bfloat16(v3);
                long o0 = (long)z * chs + (long)r * ldc + cb;
                long o1 = (long)z * chs + (long)(r + 8) * ldc + cb;
                P0[o0] = h0; P0[o0 + 1] = h1;
                P1[o0] = __float2bfloat16(v0 - __bfloat162float(h0));
                P1[o0 + 1] = __float2bfloat16(v1 - __bfloat162float(h1));
                P0[o1] = h2; P0[o1 + 1] = h3;
                P1[o1] = __float2bfloat16(v2 - __bfloat162float(h2));
                P1[o1 + 1] = __float2bfloat16(v3 - __bfloat162float(h3));
            }
        }
    }
}

// ---------------- utility / prep kernels ----------------
__global__ void set_int_kernel(int* p, int n, int v) {
    int i = blockIdx.x * 256 + threadIdx.x;
    if (i < n) p[i] = v;
}
__global__ void set_u32_kernel(uint32_t* p, int n, uint32_t v) {
    int i = blockIdx.x * 256 + threadIdx.x;
    if (i < n) p[i] = v;
}
__global__ void build_idx_kernel(int D, int H, int W, int* a_idx, int* b_idx) {
    int n = D * H * W;
    int t = blockIdx.x * 256 + threadIdx.x;
    if (t >= n) return;
    int z = t / (H * W), y = (t / W) % H, xx = t % W;
    int hw2 = (H >> 1) * (W >> 1);
    if (((z | y | xx) & 1) == 0) {
        b_idx[(z >> 1) * hw2 + (y >> 1) * (W >> 1) + (xx >> 1)] = t;
    } else {
        int cez = (z + 1) >> 1, cey = (y + 1) >> 1, cex = (xx + 1) >> 1;
        int before = cez * hw2;
        if ((z & 1) == 0) { before += cey * (W >> 1); if ((y & 1) == 0) before += cex; }
        a_idx[t - before] = t;
    }
}
__global__ void conv_tok_kernel(int* t) {
    int i = blockIdx.x * 256 + threadIdx.x;
    if (i >= 8 * N2) return;
    int tap = i >> 11, m = i & 2047;
    int kz = tap >> 2, ky = (tap >> 1) & 1, kx = tap & 1;
    int z2 = m >> 8, y2 = (m >> 4) & 15, x2 = m & 15;
    t[i] = (2 * z2 + kz) * (H0 * W0) + (2 * y2 + ky) * W0 + (2 * x2 + kx);
}
__global__ void split3_kernel(const float* __restrict__ s, bf16* p0, bf16* p1, bf16* p2, long n) {
    long i = (long)blockIdx.x * 256 + threadIdx.x;
    if (i >= n) return;
    float v = s[i];
    bf16 h = __float2bfloat16(v); float r = v - __bfloat162float(h);
    bf16 m = __float2bfloat16(r); float r2 = r - __bfloat162float(m);
    p0[i] = h; p1[i] = m; p2[i] = __float2bfloat16(r2);
}
__global__ void split2_kernel(const float* __restrict__ s, bf16* p0, bf16* p1, long n) {
    long i = (long)blockIdx.x * 256 + threadIdx.x;
    if (i >= n) return;
    float v = s[i];
    bf16 h = __float2bfloat16(v);
    p0[i] = h; p1[i] = __float2bfloat16(v - __bfloat162float(h));
}
__global__ void split3_bt_kernel(const float* __restrict__ w, bf16* p0, bf16* p1, bf16* p2) {
    long i = (long)blockIdx.x * 256 + threadIdx.x;
    if (i >= (long)8 * CC * CC) return;
    int tap = (int)(i / (CC * CC));
    int rem = (int)(i - (long)tap * CC * CC);
    int n = rem / CC, k = rem - n * CC;
    float v = w[(long)n * (CC * 8) + k * 8 + tap];
    bf16 h = __float2bfloat16(v); float r = v - __bfloat162float(h);
    bf16 m = __float2bfloat16(r);
    p0[i] = h; p1[i] = m; p2[i] = __float2bfloat16(r - __bfloat162float(m));
}
// kvm k-part -> [8][MK][96] hi/lo
__global__ void split_kpad_kernel(const float* __restrict__ kvm, bf16* p0, bf16* p1) {
    long i = (long)blockIdx.x * 256 + threadIdx.x;
    if (i >= (long)HEADS * MK * HD) return;
    int h = (int)(i / (MK * HD));
    int rem = (int)(i - (long)h * MK * HD);
    int m = rem / HD, k = rem - m * HD;
    float v = kvm[(long)m * (2 * CC) + h * HD + k];
    bf16 hi = __float2bfloat16(v);
    p0[i] = hi; p1[i] = __float2bfloat16(v - __bfloat162float(hi));
}
// kvm v-part transposed -> [8][96][MK] hi/lo
__global__ void split_vT_kernel(const float* __restrict__ kvm, bf16* p0, bf16* p1) {
    long i = (long)blockIdx.x * 256 + threadIdx.x;
    if (i >= (long)HEADS * HD * MK) return;
    int h = (int)(i / (HD * MK));
    int rem = (int)(i - (long)h * HD * MK);
    int n = rem >> 10, k = rem & (MK - 1);
    float v = kvm[(long)k * (2 * CC) + CC + h * HD + n];
    bf16 hi = __float2bfloat16(v);
    p0[i] = hi; p1[i] = __float2bfloat16(v - __bfloat162float(hi));
}

// ---------------- fused LN -> xk, mnk, mk1 ----------------
__global__ void __launch_bounds__(256) ln_norm_kernel(float* __restrict__ xk,
    const float* __restrict__ g, const float* __restrict__ b,
    float* __restrict__ mnk, bf16* __restrict__ mk1)
{
    int row = blockIdx.x;
    float* p = xk + (long)row * CC;
    __shared__ float red[256];
    int tid = threadIdx.x;
    float v0 = p[tid], v1 = p[tid + 256], v2 = p[tid + 512];
    red[tid] = v0 + v1 + v2; __syncthreads();
    for (int off = 128; off; off >>= 1) { if (tid < off) red[tid] += red[tid + off]; __syncthreads(); }
    float mean = red[0] / (float)CC;
    __syncthreads();
    float d0 = v0 - mean, d1 = v1 - mean, d2 = v2 - mean;
    red[tid] = d0 * d0 + d1 * d1 + d2 * d2; __syncthreads();
    for (int off = 128; off; off >>= 1) { if (tid < off) red[tid] += red[tid + off]; __syncthreads(); }
    float var = red[0] / (float)CC;
    float inv = (float)(1.0 / sqrt((double)var + 1e-5));
    __syncthreads();
    float y0 = d0 * inv * g[tid] + b[tid];
    float y1 = d1 * inv * g[tid + 256] + b[tid + 256];
    float y2 = d2 * inv * g[tid + 512] + b[tid + 512];
    p[tid] = y0; p[tid + 256] = y1; p[tid + 512] = y2;
    red[tid] = y0 * y0 + y1 * y1 + y2 * y2; __syncthreads();
    for (int off = 128; off; off >>= 1) { if (tid < off) red[tid] += red[tid + off]; __syncthreads(); }
    float nrm = (float)(1.0 / sqrt((double)red[0]));
    float* q = mnk + (long)row * CC;
    bf16* q1 = mk1 + (long)row * CC;
    float n0 = y0 * nrm, n1 = y1 * nrm, n2 = y2 * nrm;
    q[tid] = n0; q[tid + 256] = n1; q[tid + 512] = n2;
    q1[tid] = __float2bfloat16(n0); q1[tid + 256] = __float2bfloat16(n1); q1[tid + 512] = __float2bfloat16(n2);
}
__global__ void __launch_bounds__(256) rownorm_cvt_kernel(const float* __restrict__ src,
    float* __restrict__ dst, bf16* __restrict__ dst1)
{
    int row = blockIdx.x;
    const float* p = src + (long)row * CC;
    __shared__ float red[256];
    int tid = threadIdx.x;
    float v0 = p[tid], v1 = p[tid + 256], v2 = p[tid + 512];
    red[tid] = v0 * v0 + v1 * v1 + v2 * v2; __syncthreads();
    for (int off = 128; off; off >>= 1) { if (tid < off) red[tid] += red[tid + off]; __syncthreads(); }
    float inv = (float)(1.0 / sqrt((double)red[0]));
    float* q = dst + (long)row * CC;
    bf16* q1 = dst1 + (long)row * CC;
    float n0 = v0 * inv, n1 = v1 * inv, n2 = v2 * inv;
    q[tid] = n0; q[tid + 256] = n1; q[tid + 512] = n2;
    q1[tid] = __float2bfloat16(n0); q1[tid + 256] = __float2bfloat16(n1); q1[tid + 512] = __float2bfloat16(n2);
}

// ---------------- refine (candidates from fused rowmax) ----------------
__global__ void __launch_bounds__(256) refine_kernel(
    const float* __restrict__ S, int ncol, const float* __restrict__ mn,
    const int* __restrict__ a_idx, const int* __restrict__ b_idx,
    const uint32_t* __restrict__ rmaxu, u64* __restrict__ key, float margin)
{
    int row = blockIdx.x * 8 + (threadIdx.x >> 5);
    int lane = threadIdx.x & 31;
    const float* p = S + (long)row * ncol;
    float thr = decf(rmaxu[row]) - margin;
    const float* av = mn + (long)a_idx[row] * CC;
    float bestv = -3.4e38f;
    int bestd = 0;
    for (int base = 0; base < ncol; base += 32) {
        float s = p[base + lane];
        unsigned m = __ballot_sync(0xffffffffu, s >= thr);
        while (m) {
            int b = __ffs(m) - 1;
            m &= m - 1;
            int dst = base + b;
            const float* bv = mn + (long)b_idx[dst] * CC;
            float part = 0.f;
            for (int c = lane; c < CC; c += 32) part += av[c] * bv[c];
            for (int off = 16; off; off >>= 1) part += __shfl_xor_sync(0xffffffffu, part, off);
            if (part > bestv) { bestv = part; bestd = dst; }
        }
    }
    if (lane == 0) {
        unsigned u = __float_as_uint(bestv);
        unsigned o = (u & 0x80000000u) ? ~u : (u | 0x80000000u);
        key[row] = ((u64)o << 32) | (unsigned)(~bestd);
    }
}

// ---------------- BSM index machinery ----------------
__global__ void unpack_val_kernel(const u64* __restrict__ key, float* __restrict__ val, int n) {
    int i = blockIdx.x * 256 + threadIdx.x;
    if (i >= n) return;
    uint32_t o = (uint32_t)(key[i] >> 32);
    uint32_t u = (o & 0x80000000u) ? (o ^ 0x80000000u) : ~o;
    val[i] = __uint_as_float(u);
}
__global__ void __launch_bounds__(256) rank_kernel(const float* __restrict__ v, int* __restrict__ perm, int n) {
    int i = blockIdx.x * 256 + threadIdx.x;
    float vi = (i < n) ? v[i] : 0.f;
    int r = 0;
    __shared__ float sv[256];
    for (int base = 0; base < n; base += 256) {
        int j = base + threadIdx.x;
        sv[threadIdx.x] = (j < n) ? v[j] : -3.4e38f;
        __syncthreads();
        int lim = min(256, n - base);
        for (int t = 0; t < lim; t++) {
            float vj = sv[t];
            int j2 = base + t;
            if (vj > vi || (vj == vi && j2 < i)) r++;
        }
        __syncthreads();
    }
    if (i < n) perm[r] = i;
}
__global__ void fill_dst_kernel(const int* __restrict__ perm, const u64* __restrict__ key,
                                int* __restrict__ dst, int* __restrict__ cnt, int R) {
    int e = blockIdx.x * 256 + threadIdx.x;
    if (e >= R) return;
    int s = perm[e];
    uint32_t low = (uint32_t)(key[s]);
    int dd = (int)(~low);
    dst[e] = dd;
    atomicAdd(&cnt[dd], 1);
}
__global__ void __launch_bounds__(256) merge_gather_kernel(const float* __restrict__ src, float* __restrict__ buf,
    const int* __restrict__ a_idx, const int* __restrict__ b_idx,
    const int* __restrict__ perm, int U, int R)
{
    int row = blockIdx.x;
    int tok = (row < U) ? a_idx[perm[R + row]] : b_idx[row - U];
    const float* s = src + (long)tok * CC;
    float* d = buf + (long)row * CC;
    for (int c = threadIdx.x; c < CC; c += 256) d[c] = s[c];
}
__global__ void __launch_bounds__(256) scatter_add_kernel(const float* __restrict__ src, float* __restrict__ buf,
    const int* __restrict__ a_idx, const int* __restrict__ perm, const int* __restrict__ dst, int U)
{
    int e = blockIdx.x;
    int tok = a_idx[perm[e]];
    float* d = buf + (long)(U + dst[e]) * CC;
    const float* s = src + (long)tok * CC;
    for (int c = threadIdx.x; c < CC; c += 256) atomicAdd(&d[c], s[c]);
}
__global__ void __launch_bounds__(256) div_cnt_kernel(float* __restrict__ buf, const int* __restrict__ cnt, int U) {
    int dr = blockIdx.x;
    float cf = (float)cnt[dr];
    float* p = buf + (long)(U + dr) * CC;
    for (int c = threadIdx.x; c < CC; c += 256) p[c] = p[c] / cf;
}

// ---------------- single-pass softmax -> bf16 hi/lo planes ----------------
__global__ void __launch_bounds__(256) softmax_b_kernel(const float* __restrict__ S,
    bf16* __restrict__ sh, bf16* __restrict__ sl)
{
    long row = blockIdx.x;
    const float4 v4 = ((const float4*)(S + row * MK))[threadIdx.x];
    float v[4] = {v4.x, v4.y, v4.z, v4.w};
    __shared__ float red[256];
    int tid = threadIdx.x;
    float m = fmaxf(fmaxf(v[0], v[1]), fmaxf(v[2], v[3]));
    red[tid] = m; __syncthreads();
    for (int off = 128; off; off >>= 1) { if (tid < off) red[tid] = fmaxf(red[tid], red[tid + off]); __syncthreads(); }
    float mx = red[0];
    __syncthreads();
    float e[4], s = 0.f;
#pragma unroll
    for (int i = 0; i < 4; i++) { e[i] = expf(v[i] - mx); s += e[i]; }
    red[tid] = s; __syncthreads();
    for (int off = 128; off; off >>= 1) { if (tid < off) red[tid] += red[tid + off]; __syncthreads(); }
    float inv = 1.0f / red[0];
    uint32_t hp[2], lp[2];
#pragma unroll
    for (int i = 0; i < 2; i++) {
        float a = e[2 * i] * inv, b = e[2 * i + 1] * inv;
        bf16 ha = __float2bfloat16(a), hb = __float2bfloat16(b);
        hp[i] = pkbf(ha, hb);
        lp[i] = pkbf(__float2bfloat16(a - __bfloat162float(ha)),
                     __float2bfloat16(b - __bfloat162float(hb)));
    }
    ((uint2*)(sh + row * MK))[tid] = make_uint2(hp[0], hp[1]);
    ((uint2*)(sl + row * MK))[tid] = make_uint2(lp[0], lp[1]);
}

// ---------------- unmerge ----------------
__global__ void __launch_bounds__(256) unmerge_kernel(const float* __restrict__ proj, float* __restrict__ out,
    const int* __restrict__ a_idx, const int* __restrict__ b_idx,
    const int* __restrict__ perm, const int* __restrict__ dst)
{
    int rid = blockIdx.x;
    int srcrow, tok;
    if (rid < NDQ) { srcrow = UQ + rid; tok = b_idx[rid]; }
    else if (rid < NDQ + UQ) { int u = rid - NDQ; srcrow = u; tok = a_idx[perm[RQ + u]]; }
    else { int e = rid - (NDQ + UQ); srcrow = UQ + dst[e]; tok = a_idx[perm[e]]; }
    const float* s = proj + (long)srcrow * CC;
    float* d = out + (long)tok * CC;
    for (int c = threadIdx.x; c < CC; c += 256) d[c] = s[c];
}

// ---------------- host launcher ----------------
#define SM_6_64_2  (2 * (3 * 8192 + 3 * 8192))   // 96 KB
#define SM_3_64_3  (3 * (2 * 8192 + 2 * 8192))   // 96 KB
#define SM_1_128_3 (3 * (8192 + 16384))          // 72 KB
#define SM_1_64_3  (3 * (8192 + 8192))           // 48 KB

extern "C" void kernel_launch(void* const* d_in, const int* in_sizes, int n_in,
                              void* d_out, int out_size)
{
    (void)in_sizes; (void)n_in; (void)out_size;
    const float* x   = (const float*)d_in[0];
    const float* srw = (const float*)d_in[1];
    const float* srb = (const float*)d_in[2];
    const float* lng = (const float*)d_in[3];
    const float* lnb = (const float*)d_in[4];
    const float* Wq  = (const float*)d_in[5];
    const float* Wkv = (const float*)d_in[6];
    const float* Wp  = (const float*)d_in[7];
    const float* bp  = (const float*)d_in[8];
    float* out = (float*)d_out;

    cudaFuncSetAttribute(mmg<6, 64, 2, 0>,  cudaFuncAttributeMaxDynamicSharedMemorySize, SM_6_64_2);
    cudaFuncSetAttribute(mmg<3, 64, 3, 0>,  cudaFuncAttributeMaxDynamicSharedMemorySize, SM_3_64_3);
    cudaFuncSetAttribute(mmg<3, 64, 3, 2>,  cudaFuncAttributeMaxDynamicSharedMemorySize, SM_3_64_3);
    cudaFuncSetAttribute(mmg<3, 64, 3, 3>,  cudaFuncAttributeMaxDynamicSharedMemorySize, SM_3_64_3);
    cudaFuncSetAttribute(mmg<1, 128, 3, 1>, cudaFuncAttributeMaxDynamicSharedMemorySize, SM_1_128_3);
    cudaFuncSetAttribute(mmg<1, 64, 3, 1>,  cudaFuncAttributeMaxDynamicSharedMemorySize, SM_1_64_3);

    float *xk, *mnq, *mnk, *nvq, *nvk, *xq, *xkm, *kvm, *S, *proj;
    uint32_t* rmaxu;
    u64 *keyq, *keyk;
    int *permq, *permk, *dstq, *dstk, *cntq, *cntk, *aq, *bq, *ak, *bk, *ctok;
    bf16 *x3, *bt3, *mq1, *mk1, *xq2, *xkm2, *wq2, *wkv2, *wp2, *qp2, *kp2, *vp2, *ao2, *sh, *sl;
    cudaGetSymbolAddress((void**)&xk, g_xk);
    cudaGetSymbolAddress((void**)&mnq, g_mnq);
    cudaGetSymbolAddress((void**)&mnk, g_mnk);
    cudaGetSymbolAddress((void**)&nvq, g_nvq);
    cudaGetSymbolAddress((void**)&nvk, g_nvk);
    cudaGetSymbolAddress((void**)&rmaxu, g_rmaxu);
    cudaGetSymbolAddress((void**)&xq, g_xq);
    cudaGetSymbolAddress((void**)&xkm, g_xkm);
    cudaGetSymbolAddress((void**)&kvm, g_kvm);
    cudaGetSymbolAddress((void**)&S, g_S);
    cudaGetSymbolAddress((void**)&proj, g_proj);
    cudaGetSymbolAddress((void**)&keyq, g_keyq);
    cudaGetSymbolAddress((void**)&keyk, g_keyk);
    cudaGetSymbolAddress((void**)&permq, g_permq);
    cudaGetSymbolAddress((void**)&permk, g_permk);
    cudaGetSymbolAddress((void**)&dstq, g_dstq);
    cudaGetSymbolAddress((void**)&dstk, g_dstk);
    cudaGetSymbolAddress((void**)&cntq, g_cntq);
    cudaGetSymbolAddress((void**)&cntk, g_cntk);
    cudaGetSymbolAddress((void**)&aq, g_aq);
    cudaGetSymbolAddress((void**)&bq, g_bq);
    cudaGetSymbolAddress((void**)&ak, g_ak);
    cudaGetSymbolAddress((void**)&bk, g_bk);
    cudaGetSymbolAddress((void**)&ctok, g_ctok);
    cudaGetSymbolAddress((void**)&x3, g_x3);
    cudaGetSymbolAddress((void**)&bt3, g_bt3);
    cudaGetSymbolAddress((void**)&mq1, g_mq1);
    cudaGetSymbolAddress((void**)&mk1, g_mk1);
    cudaGetSymbolAddress((void**)&xq2, g_xq2);
    cudaGetSymbolAddress((void**)&xkm2, g_xkm2);
    cudaGetSymbolAddress((void**)&wq2, g_wq2);
    cudaGetSymbolAddress((void**)&wkv2, g_wkv2);
    cudaGetSymbolAddress((void**)&wp2, g_wp2);
    cudaGetSymbolAddress((void**)&qp2, g_qp2);
    cudaGetSymbolAddress((void**)&kp2, g_kp2);
    cudaGetSymbolAddress((void**)&vp2, g_vp2);
    cudaGetSymbolAddress((void**)&ao2, g_ao2);
    cudaGetSymbolAddress((void**)&sh, g_sh);
    cudaGetSymbolAddress((void**)&sl, g_sl);

    const long PXQ = (long)NQ * CC;
    const long PBT = (long)8 * CC * CC;
    const long PQ2 = (long)MQ * CC;
    const long PK2 = (long)MK * CC;
    const long PWQ = (long)CC * CC;
    const long PWKV = (long)2 * CC * CC;
    const long PQP = (long)HEADS * MQ * HD;
    const long PKP = (long)HEADS * MK * HD;
    const long PVP = (long)HEADS * HD * MK;
    float* Skv = S + (long)NAQ * NDQ;

    // 1-3: conv prerequisites
    split3_kernel<<<(int)((PXQ + 255) / 256), 256>>>(x, x3, x3 + PXQ, x3 + 2 * PXQ, PXQ);
    split3_bt_kernel<<<(int)((PBT + 255) / 256), 256>>>(srw, bt3, bt3 + PBT, bt3 + 2 * PBT);
    conv_tok_kernel<<<(8 * N2 + 255) / 256, 256>>>(ctok);
    // 4: conv GEMM (profiled slot)
    mmg<6, 64, 2, 0><<<dim3(CC / 64, N2 / 64, 1), 512, SM_6_64_2>>>(
        x3, x3 + PXQ, x3 + 2 * PXQ, CC, 0,
        bt3, bt3 + PBT, bt3 + 2 * PBT, CC, 0, (long)CC * CC,
        xk, CC, 0, srb, 1.f, nullptr, nullptr, 0, nullptr,
        CC, CC, 8, ctok, N2, nullptr);
    // 5: fused LN + rownorm + cvt
    ln_norm_kernel<<<N2, 256>>>(xk, lng, lnb, mnk, mk1);
    build_idx_kernel<<<(NQ + 255) / 256, 256>>>(D0, H0, W0, aq, bq);
    build_idx_kernel<<<(N2 + 255) / 256, 256>>>(D0 / 2, H0 / 2, W0 / 2, ak, bk);

    // ---- q-side BSM ----
    rownorm_cvt_kernel<<<NQ, 256>>>(x, mnq, mq1);
    set_u32_kernel<<<(NAQ + 255) / 256, 256>>>(rmaxu, NAQ, 0u);
    mmg<1, 128, 3, 1><<<dim3(NDQ / 128, NAQ / 64, 1), 512, SM_1_128_3>>>(
        mq1, nullptr, nullptr, CC, 0,
        mq1, nullptr, nullptr, CC, 0, 0,
        S, NDQ, 0, nullptr, 1.f, nullptr, nullptr, 0, rmaxu,
        NDQ, CC, 1, aq, 0, bq);
    refine_kernel<<<NAQ / 8, 256>>>(S, NDQ, mnq, aq, bq, rmaxu, keyq, 2e-3f);
    unpack_val_kernel<<<(NAQ + 255) / 256, 256>>>(keyq, nvq, NAQ);
    rank_kernel<<<NAQ / 256, 256>>>(nvq, permq, NAQ);
    set_int_kernel<<<(NDQ + 255) / 256, 256>>>(cntq, NDQ, 1);
    fill_dst_kernel<<<(RQ + 255) / 256, 256>>>(permq, keyq, dstq, cntq, RQ);
    merge_gather_kernel<<<MQ, 256>>>(x, xq, aq, bq, permq, UQ, RQ);
    scatter_add_kernel<<<RQ, 256>>>(x, xq, aq, permq, dstq, UQ);
    div_cnt_kernel<<<NDQ, 256>>>(xq, cntq, UQ);

    // ---- kv-side BSM ----
    set_u32_kernel<<<(NAK + 255) / 256, 256>>>(rmaxu, NAK, 0u);
    mmg<1, 64, 3, 1><<<dim3(NDK / 64, NAK / 64, 1), 512, SM_1_64_3>>>(
        mk1, nullptr, nullptr, CC, 0,
        mk1, nullptr, nullptr, CC, 0, 0,
        Skv, NDK, 0, nullptr, 1.f, nullptr, nullptr, 0, rmaxu,
        NDK, CC, 1, ak, 0, bk);
    refine_kernel<<<NAK / 8, 256>>>(Skv, NDK, mnk, ak, bk, rmaxu, keyk, 2e-3f);
    unpack_val_kernel<<<(NAK + 255) / 256, 256>>>(keyk, nvk, NAK);
    rank_kernel<<<NAK / 256, 256>>>(nvk, permk, NAK);
    set_int_kernel<<<1, 256>>>(cntk, NDK, 1);
    fill_dst_kernel<<<(RK + 255) / 256, 256>>>(permk, keyk, dstk, cntk, RK);
    merge_gather_kernel<<<MK, 256>>>(xk, xkm, ak, bk, permk, UK, RK);
    scatter_add_kernel<<<RK, 256>>>(xk, xkm, ak, permk, dstk, UK);
    div_cnt_kernel<<<NDK, 256>>>(xkm, cntk, UK);

    // ---- projections ----
    split2_kernel<<<(int)((PWQ + 255) / 256), 256>>>(Wq, wq2, wq2 + PWQ, PWQ);
    split2_kernel<<<(int)((PWKV + 255) / 256), 256>>>(Wkv, wkv2, wkv2 + PWKV, PWKV);
    split2_kernel<<<(int)((PWQ + 255) / 256), 256>>>(Wp, wp2, wp2 + PWQ, PWQ);
    split2_kernel<<<(int)((PQ2 + 255) / 256), 256>>>(xq, xq2, xq2 + PQ2, PQ2);
    split2_kernel<<<(int)((PK2 + 255) / 256), 256>>>(xkm, xkm2, xkm2 + PK2, PK2);
    // Wq -> head-major bf16 Q planes directly (EPI2)
    mmg<3, 64, 3, 2><<<dim3(CC / 64, MQ / 64, 1), 512, SM_3_64_3>>>(
        xq2, xq2 + PQ2, nullptr, CC, 0,
        wq2, wq2 + PWQ, nullptr, CC, 0, 0,
        nullptr, 0, 0, nullptr, 1.f, qp2, qp2 + PQP, (long)MQ * HD, nullptr,
        CC, CC, 1, nullptr, 0, nullptr);
    mmg<3, 64, 3, 0><<<dim3(2 * CC / 64, MK / 64, 1), 512, SM_3_64_3>>>(
        xkm2, xkm2 + PK2, nullptr, CC, 0,
        wkv2, wkv2 + PWKV, nullptr, CC, 0, 0,
        kvm, 2 * CC, 0, nullptr, 1.f, nullptr, nullptr, 0, nullptr,
        2 * CC, CC, 1, nullptr, 0, nullptr);

    // ---- head prep ----
    split_kpad_kernel<<<(int)((PKP + 255) / 256), 256>>>(kvm, kp2, kp2 + PKP);
    split_vT_kernel<<<(int)((PVP + 255) / 256), 256>>>(kvm, vp2, vp2 + PVP);

    // ---- attention (K = 96, unpadded) ----
    float scl = 1.0f / sqrtf((float)HD);
    mmg<3, 64, 3, 0><<<dim3(MK / 64, MQ / 64, HEADS), 512, SM_3_64_3>>>(
        qp2, qp2 + PQP, nullptr, HD, (long)MQ * HD,
        kp2, kp2 + PKP, nullptr, HD, (long)MK * HD, 0,
        S, MK, (long)MQ * MK, nullptr, scl, nullptr, nullptr, 0, nullptr,
        MK, HD, 1, nullptr, 0, nullptr);
    softmax_b_kernel<<<HEADS * MQ, 256>>>(S, sh, sl);
    // AV -> bf16 ao planes directly (EPI3)
    mmg<3, 64, 3, 3><<<dim3(2, MQ / 64, HEADS), 512, SM_3_64_3>>>(
        sh, sl, nullptr, MK, (long)MQ * MK,
        vp2, vp2 + PVP, nullptr, MK, (long)HD * MK, 0,
        nullptr, CC, HD, nullptr, 1.f, ao2, ao2 + PQ2, 0, nullptr,
        HD, MK, 1, nullptr, 0, nullptr);

    // ---- output projection + unmerge ----
    mmg<3, 64, 3, 0><<<dim3(CC / 64, MQ / 64, 1), 512, SM_3_64_3>>>(
        ao2, ao2 + PQ2, nullptr, CC, 0,
        wp2, wp2 + PWQ, nullptr, CC, 0, 0,
        proj, CC, 0, bp, 1.f, nullptr, nullptr, 0, nullptr,
        CC, CC, 1, nullptr, 0, nullptr);
    unmerge_kernel<<<NQ, 256>>>(proj, out, aq, bq, permq, dstq);
}

// round 13
// speedup vs baseline: 1.0506x; 1.0506x over previous
#include <cuda_runtime.h>
#include <cuda_bf16.h>
#include <math.h>
#include <stdint.h>

// ---------------- static problem sizes ----------------
#define CC    768
#define D0    16
#define H0    32
#define W0    32
#define NQ    16384
#define NDQ   2048
#define NAQ   14336
#define RQ    8192
#define UQ    6144
#define MQ    8192
#define N2    2048
#define NDK   256
#define NAK   1792
#define RK    1024
#define UK    768
#define MK    1024
#define HEADS 8
#define HD    96

typedef __nv_bfloat16 bf16;
typedef unsigned long long u64;

// ---------------- device scratch ----------------
__device__ float g_xk[N2 * CC];
__device__ float g_mnq[NQ * CC];
__device__ float g_mnk[N2 * CC];
__device__ u64   g_keyq[NAQ];
__device__ u64   g_keyk[NAK];
__device__ float g_nvq[NAQ];
__device__ float g_nvk[NAK];
__device__ uint32_t g_rmaxu[NAQ];
__device__ int g_permq[NAQ];
__device__ int g_permk[NAK];
__device__ int g_dstq[RQ];
__device__ int g_dstk[RK];
__device__ int g_cntq[NDQ];
__device__ int g_cntk[NDK];
__device__ int g_aq[NAQ];
__device__ int g_bq[NDQ];
__device__ int g_ak[NAK];
__device__ int g_bk[NDK];
__device__ int g_ctok[8 * N2];
__device__ float g_xq[MQ * CC];
__device__ float g_xkm[MK * CC];
__device__ float g_kvm[MK * 2 * CC];
__device__ float g_S[(long)HEADS * MQ * MK];
__device__ float g_proj[MQ * CC];

// bf16 planes
__device__ bf16 g_x3[3][NQ * CC];
__device__ bf16 g_bt3[3][8 * CC * CC];
__device__ bf16 g_mq1[NQ * CC];
__device__ bf16 g_mk1[N2 * CC];
__device__ bf16 g_xq2[2][MQ * CC];
__device__ bf16 g_xkm2[2][MK * CC];
__device__ bf16 g_wq2[2][CC * CC];
__device__ bf16 g_wkv2[2][2 * CC * CC];
__device__ bf16 g_wp2[2][CC * CC];
__device__ bf16 g_qp2[2][HEADS * MQ * HD];
__device__ bf16 g_kp2[2][HEADS * MK * HD];
__device__ bf16 g_vp2[2][HEADS * HD * MK];
__device__ bf16 g_ao2[2][MQ * CC];
__device__ bf16 g_sh[(long)HEADS * MQ * MK];
__device__ bf16 g_sl[(long)HEADS * MQ * MK];

__device__ __forceinline__ uint32_t smem_u32(const void* p) {
    uint32_t a;
    asm("{ .reg .u64 t; cvta.to.shared.u64 t, %1; cvt.u32.u64 %0, t; }" : "=r"(a) : "l"(p));
    return a;
}
__device__ __forceinline__ uint32_t pkbf(bf16 a, bf16 b) {
    return (uint32_t)__bfloat16_as_ushort(a) | ((uint32_t)__bfloat16_as_ushort(b) << 16);
}
__device__ __forceinline__ uint32_t encf(float f) {
    uint32_t u = __float_as_uint(f);
    return (u & 0x80000000u) ? ~u : (u | 0x80000000u);
}
__device__ __forceinline__ float decf(uint32_t o) {
    uint32_t u = (o & 0x80000000u) ? (o ^ 0x80000000u) : ~o;
    return __uint_as_float(u);
}
#define SWZ(o) ((o) ^ (((o) >> 3) & 0x70))
#define MMA16816(d, a, b0v, b1v) \
    asm volatile("mma.sync.aligned.m16n8k16.row.col.f32.bf16.bf16.f32 " \
        "{%0,%1,%2,%3}, {%4,%5,%6,%7}, {%8,%9}, {%0,%1,%2,%3};" \
        : "+f"((d)[0]), "+f"((d)[1]), "+f"((d)[2]), "+f"((d)[3]) \
        : "r"((a)[0]), "r"((a)[1]), "r"((a)[2]), "r"((a)[3]), "r"(b0v), "r"(b1v))
#define LDSM4(r, a) \
    asm volatile("ldmatrix.sync.aligned.m8n8.x4.shared.b16 {%0,%1,%2,%3}, [%4];" \
        : "=r"((r)[0]), "=r"((r)[1]), "=r"((r)[2]), "=r"((r)[3]) : "r"(a))
#define CPA(dst, src, sz) \
    asm volatile("cp.async.cg.shared.global [%0], [%1], 16, %2;" :: "r"(dst), "l"(src), "r"(sz) : "memory")
#define CPCOMMIT() asm volatile("cp.async.commit_group;" ::: "memory")
#define CPWAIT1()  asm volatile("cp.async.wait_group 1;" ::: "memory")

// ---------------- pipelined ldmatrix mma.sync split-bf16 GEMM ----------------
// C[M,N] = scale * A[M,K] @ B[N,K]^T (+bias), over ntap segments.
// Block 64 x TN, k-tile 64, STAGES-deep cp.async pipeline, 16 warps (4m x 4n),
// warp tile 16 x (TN/4). TK=false: K % 64 == 0, zero runtime tail logic
// (fully unrolled, unconditional copy sizes). TK=true: K % 32 == 0 allowed,
// tail zero-filled & skipped, cp.async source addrs clamped valid at size 0.
// EPI: 0 fp32 C; 1 fp32 C + atomicMax ordered-uint rowmax; 2 head-major bf16
// hi/lo split (P0/P1, per-head stride phs, 96-wide rows); 3 bf16 hi/lo split
// at C-addressing into P0/P1.
template <int NPR, int TN, int STAGES, int EPI, bool TK>
__global__ void __launch_bounds__(512, 2) mmg(
    const bf16* A0, const bf16* A1, const bf16* A2, long lda, long ahs,
    const bf16* B0, const bf16* B1, const bf16* B2, long ldb, long bhs, long bseg,
    float* C, long ldc, long chs, const float* bias, float scale,
    bf16* P0, bf16* P1, long phs, uint32_t* rmaxu,
    int N, int K, int ntap, const int* gA, int gAs, const int* gB)
{
    constexpr int nA = (NPR == 6) ? 3 : (NPR == 3) ? 2 : 1;
    constexpr int nB = nA;
    constexpr int PLA = 8192;          // 64 rows x 128 B
    constexpr int PLB = TN * 128;
    constexpr int STG = nA * PLA + nB * PLB;
    constexpr int NJ = TN / 32;
    extern __shared__ char sm[];
    const uint32_t su = smem_u32(sm);

    const int tid = threadIdx.x, lane = tid & 31, wid = tid >> 5;
    const int wm = wid >> 2, wn = wid & 3;
    const int m0 = blockIdx.y * 64, n0 = blockIdx.x * TN, z = blockIdx.z;
    const int lq = lane >> 2, lr = lane & 3;

    const int lrA = tid >> 3, secA = tid & 7;
    const int lrB = (TN == 128) ? (tid >> 2) : (tid >> 3);
    const int secB = (TN == 128) ? (tid & 3) : (tid & 7);
    const int nrow = n0 + lrB;
    const bool bval = nrow < N;
    const long brow = bval ? (gB ? (long)gB[nrow] : (long)nrow) : 0;
    const uint32_t bsz = bval ? 16u : 0u;

    const uint32_t dA0 = SWZ((uint32_t)(lrA * 128 + secA * 16));
    const uint32_t dB0 = (TN == 128) ? SWZ((uint32_t)(lrB * 128 + secB * 32))
                                     : SWZ((uint32_t)(lrB * 128 + secB * 16));
    const uint32_t dB1 = (TN == 128) ? SWZ((uint32_t)(lrB * 128 + secB * 32 + 16)) : 0u;

    const int kcd = (K + 63) >> 6;
    const int nch = ntap * kcd;
    const bf16* Ap[3] = {A0, A1, A2};
    const bf16* Bp[3] = {B0, B1, B2};

    float acc[NJ][4];
#pragma unroll
    for (int j = 0; j < NJ; j++)
#pragma unroll
        for (int t = 0; t < 4; t++) acc[j][t] = 0.f;

    auto issue = [&](int c) {
        const int stg = c % STAGES;
        const uint32_t sb = su + stg * STG;
        const int tap = c / kcd;
        const int k0 = (c - tap * kcd) << 6;
        const long arow = gA ? (long)gA[tap * gAs + m0 + lrA] : (long)(m0 + lrA);
        if constexpr (!TK) {
#pragma unroll
            for (int p = 0; p < nA; p++) {
                const bf16* s0 = Ap[p] + (long)z * ahs + arow * lda + k0 + secA * 8;
                CPA(sb + p * PLA + dA0, s0, 16u);
            }
#pragma unroll
            for (int p = 0; p < nB; p++) {
                const bf16* s0 = Bp[p] + (long)z * bhs + (long)tap * bseg + brow * ldb + k0
                               + secB * (TN == 128 ? 16 : 8);
                CPA(sb + nA * PLA + p * PLB + dB0, s0, bsz);
                if (TN == 128) CPA(sb + nA * PLA + p * PLB + dB1, s0 + 8, bsz);
            }
        } else {
            const uint32_t szA = (k0 + secA * 8 < K) ? 16u : 0u;
            const int kaA = szA ? (k0 + secA * 8) : 0;
#pragma unroll
            for (int p = 0; p < nA; p++) {
                const bf16* s0 = Ap[p] + (long)z * ahs + arow * lda + kaA;
                CPA(sb + p * PLA + dA0, s0, szA);
            }
            if (TN == 128) {
                const uint32_t sz0 = (k0 + secB * 16 < K) ? bsz : 0u;
                const uint32_t sz1 = (k0 + secB * 16 + 8 < K) ? bsz : 0u;
                const int kb0 = sz0 ? (k0 + secB * 16) : 0;
                const int kb1 = sz1 ? (k0 + secB * 16 + 8) : 0;
#pragma unroll
                for (int p = 0; p < nB; p++) {
                    const bf16* s0 = Bp[p] + (long)z * bhs + (long)tap * bseg + brow * ldb;
                    CPA(sb + nA * PLA + p * PLB + dB0, s0 + kb0, sz0);
                    CPA(sb + nA * PLA + p * PLB + dB1, s0 + kb1, sz1);
                }
            } else {
                const uint32_t sz0 = (k0 + secB * 8 < K) ? bsz : 0u;
                const int kb0 = sz0 ? (k0 + secB * 8) : 0;
#pragma unroll
                for (int p = 0; p < nB; p++) {
                    const bf16* s0 = Bp[p] + (long)z * bhs + (long)tap * bseg + brow * ldb;
                    CPA(sb + nA * PLA + p * PLB + dB0, s0 + kb0, sz0);
                }
            }
        }
        CPCOMMIT();
    };

    auto compute = [&](int stg, int kslim) {
        const uint32_t sb = su + stg * STG;
        const int pa6[6] = {0, 0, 1, 1, 0, 2}, pb6[6] = {0, 1, 0, 1, 2, 0};
#pragma unroll
        for (int ks = 0; ks < 4; ks++) {
            if constexpr (TK) { if (ks >= kslim) break; }
            uint32_t af[nA][4];
#pragma unroll
            for (int p = 0; p < nA; p++) {
                uint32_t off = (uint32_t)((wm * 16 + (lane & 15)) * 128
                                          + ks * 32 + ((lane >> 4) << 4));
                LDSM4(af[p], sb + p * PLA + SWZ(off));
            }
            uint32_t bl[nB][NJ], bh[nB][NJ];
            if constexpr (TN == 128) {
#pragma unroll
                for (int p = 0; p < nB; p++) {
                    uint32_t r0[4], r1[4];
                    uint32_t off0 = (uint32_t)((wn * 32 + (lane >> 3) * 8 + (lane & 7)) * 128 + ks * 32);
                    LDSM4(r0, sb + nA * PLA + p * PLB + SWZ(off0));
                    LDSM4(r1, sb + nA * PLA + p * PLB + SWZ(off0 + 16));
#pragma unroll
                    for (int j = 0; j < 4; j++) { bl[p][j] = r0[j]; bh[p][j] = r1[j]; }
                }
            } else {
#pragma unroll
                for (int p = 0; p < nB; p++) {
                    uint32_t r[4];
                    const int tileB = (lane >> 3) & 1, khB = lane >> 4;
                    uint32_t off = (uint32_t)((wn * 16 + tileB * 8 + (lane & 7)) * 128
                                              + ks * 32 + khB * 16);
                    LDSM4(r, sb + nA * PLA + p * PLB + SWZ(off));
                    bl[p][0] = r[0]; bl[p][1] = r[1]; bh[p][0] = r[2]; bh[p][1] = r[3];
                }
            }
#pragma unroll
            for (int pr = 0; pr < NPR; pr++) {
                const int pA = (NPR == 1) ? 0 : pa6[pr];
                const int pB = (NPR == 1) ? 0 : pb6[pr];
#pragma unroll
                for (int j = 0; j < NJ; j++)
                    MMA16816(acc[j], af[pA], bl[pB][j], bh[pB][j]);
            }
        }
    };

    issue(0);
    for (int c = 0; c < nch; c++) {
        if (c + 1 < nch) issue(c + 1);
        else CPCOMMIT();
        CPWAIT1();
        __syncthreads();
        if constexpr (TK) {
            const int k0c = (c % kcd) << 6;
            int kslim = (K - k0c + 15) >> 4; if (kslim > 4) kslim = 4;
            compute(c % STAGES, kslim);
        } else {
            compute(c % STAGES, 4);
        }
        if (STAGES == 2) __syncthreads();
    }

    // ---- epilogue ----
    const int r = m0 + wm * 16 + lq;
    if constexpr (EPI == 0 || EPI == 1) {
        float mx0 = -3.4e38f, mx1 = -3.4e38f;
#pragma unroll
        for (int j = 0; j < NJ; j++) {
            const int cb = n0 + wn * (TN / 4) + j * 8 + lr * 2;
            if (cb < N) {
                float bb0 = bias ? bias[cb] : 0.f;
                float bb1 = bias ? bias[cb + 1] : 0.f;
                float v0 = acc[j][0] * scale + bb0, v1 = acc[j][1] * scale + bb1;
                float v2 = acc[j][2] * scale + bb0, v3 = acc[j][3] * scale + bb1;
                float* p0 = C + (long)z * chs + (long)r * ldc + cb;
                float* p1 = C + (long)z * chs + (long)(r + 8) * ldc + cb;
                p0[0] = v0; p0[1] = v1; p1[0] = v2; p1[1] = v3;
                if (EPI == 1) {
                    mx0 = fmaxf(mx0, fmaxf(v0, v1));
                    mx1 = fmaxf(mx1, fmaxf(v2, v3));
                }
            }
        }
        if constexpr (EPI == 1) {
            mx0 = fmaxf(mx0, __shfl_xor_sync(0xffffffffu, mx0, 1));
            mx0 = fmaxf(mx0, __shfl_xor_sync(0xffffffffu, mx0, 2));
            mx1 = fmaxf(mx1, __shfl_xor_sync(0xffffffffu, mx1, 1));
            mx1 = fmaxf(mx1, __shfl_xor_sync(0xffffffffu, mx1, 2));
            if (lr == 0) {
                atomicMax(&rmaxu[r], encf(mx0));
                atomicMax(&rmaxu[r + 8], encf(mx1));
            }
        }
    } else if constexpr (EPI == 2) {
#pragma unroll
        for (int j = 0; j < NJ; j++) {
            const int cb = n0 + wn * (TN / 4) + j * 8 + lr * 2;
            if (cb < N) {
                int h = cb / HD, k = cb - h * HD;
                float v0 = acc[j][0] * scale, v1 = acc[j][1] * scale;
                float v2 = acc[j][2] * scale, v3 = acc[j][3] * scale;
                bf16 h0 = __float2bfloat16(v0), h1 = __float2bfloat16(v1);
                bf16 h2 = __float2bfloat16(v2), h3 = __float2bfloat16(v3);
                bf16* q0 = P0 + (long)h * phs + (long)r * HD + k;
                bf16* l0 = P1 + (long)h * phs + (long)r * HD + k;
                q0[0] = h0; q0[1] = h1;
                l0[0] = __float2bfloat16(v0 - __bfloat162float(h0));
                l0[1] = __float2bfloat16(v1 - __bfloat162float(h1));
                bf16* q1 = P0 + (long)h * phs + (long)(r + 8) * HD + k;
                bf16* l1 = P1 + (long)h * phs + (long)(r + 8) * HD + k;
                q1[0] = h2; q1[1] = h3;
                l1[0] = __float2bfloat16(v2 - __bfloat162float(h2));
                l1[1] = __float2bfloat16(v3 - __bfloat162float(h3));
            }
        }
    } else {   // EPI == 3
#pragma unroll
        for (int j = 0; j < NJ; j++) {
            const int cb = n0 + wn * (TN / 4) + j * 8 + lr * 2;
            if (cb < N) {
                float v0 = acc[j][0] * scale, v1 = acc[j][1] * scale;
                float v2 = acc[j][2] * scale, v3 = acc[j][3] * scale;
                bf16 h0 = __float2bfloat16(v0), h1 = __float2bfloat16(v1);
                bf16 h2 = __float2bfloat16(v2), h3 = __float2bfloat16(v3);
                long o0 = (long)z * chs + (long)r * ldc + cb;
                long o1 = (long)z * chs + (long)(r + 8) * ldc + cb;
                P0[o0] = h0; P0[o0 + 1] = h1;
                P1[o0] = __float2bfloat16(v0 - __bfloat162float(h0));
                P1[o0 + 1] = __float2bfloat16(v1 - __bfloat162float(h1));
                P0[o1] = h2; P0[o1 + 1] = h3;
                P1[o1] = __float2bfloat16(v2 - __bfloat162float(h2));
                P1[o1 + 1] = __float2bfloat16(v3 - __bfloat162float(h3));
            }
        }
    }
}

// ---------------- utility / prep kernels ----------------
__global__ void set_int_kernel(int* p, int n, int v) {
    int i = blockIdx.x * 256 + threadIdx.x;
    if (i < n) p[i] = v;
}
__global__ void set_u32_kernel(uint32_t* p, int n, uint32_t v) {
    int i = blockIdx.x * 256 + threadIdx.x;
    if (i < n) p[i] = v;
}
__global__ void build_idx_kernel(int D, int H, int W, int* a_idx, int* b_idx) {
    int n = D * H * W;
    int t = blockIdx.x * 256 + threadIdx.x;
    if (t >= n) return;
    int z = t / (H * W), y = (t / W) % H, xx = t % W;
    int hw2 = (H >> 1) * (W >> 1);
    if (((z | y | xx) & 1) == 0) {
        b_idx[(z >> 1) * hw2 + (y >> 1) * (W >> 1) + (xx >> 1)] = t;
    } else {
        int cez = (z + 1) >> 1, cey = (y + 1) >> 1, cex = (xx + 1) >> 1;
        int before = cez * hw2;
        if ((z & 1) == 0) { before += cey * (W >> 1); if ((y & 1) == 0) before += cex; }
        a_idx[t - before] = t;
    }
}
__global__ void conv_tok_kernel(int* t) {
    int i = blockIdx.x * 256 + threadIdx.x;
    if (i >= 8 * N2) return;
    int tap = i >> 11, m = i & 2047;
    int kz = tap >> 2, ky = (tap >> 1) & 1, kx = tap & 1;
    int z2 = m >> 8, y2 = (m >> 4) & 15, x2 = m & 15;
    t[i] = (2 * z2 + kz) * (H0 * W0) + (2 * y2 + ky) * W0 + (2 * x2 + kx);
}
__global__ void split3_kernel(const float* __restrict__ s, bf16* p0, bf16* p1, bf16* p2, long n) {
    long i = (long)blockIdx.x * 256 + threadIdx.x;
    if (i >= n) return;
    float v = s[i];
    bf16 h = __float2bfloat16(v); float r = v - __bfloat162float(h);
    bf16 m = __float2bfloat16(r); float r2 = r - __bfloat162float(m);
    p0[i] = h; p1[i] = m; p2[i] = __float2bfloat16(r2);
}
__global__ void split2_kernel(const float* __restrict__ s, bf16* p0, bf16* p1, long n) {
    long i = (long)blockIdx.x * 256 + threadIdx.x;
    if (i >= n) return;
    float v = s[i];
    bf16 h = __float2bfloat16(v);
    p0[i] = h; p1[i] = __float2bfloat16(v - __bfloat162float(h));
}
__global__ void split3_bt_kernel(const float* __restrict__ w, bf16* p0, bf16* p1, bf16* p2) {
    long i = (long)blockIdx.x * 256 + threadIdx.x;
    if (i >= (long)8 * CC * CC) return;
    int tap = (int)(i / (CC * CC));
    int rem = (int)(i - (long)tap * CC * CC);
    int n = rem / CC, k = rem - n * CC;
    float v = w[(long)n * (CC * 8) + k * 8 + tap];
    bf16 h = __float2bfloat16(v); float r = v - __bfloat162float(h);
    bf16 m = __float2bfloat16(r);
    p0[i] = h; p1[i] = m; p2[i] = __float2bfloat16(r - __bfloat162float(m));
}
// kvm k-part -> [8][MK][96] hi/lo
__global__ void split_kpad_kernel(const float* __restrict__ kvm, bf16* p0, bf16* p1) {
    long i = (long)blockIdx.x * 256 + threadIdx.x;
    if (i >= (long)HEADS * MK * HD) return;
    int h = (int)(i / (MK * HD));
    int rem = (int)(i - (long)h * MK * HD);
    int m = rem / HD, k = rem - m * HD;
    float v = kvm[(long)m * (2 * CC) + h * HD + k];
    bf16 hi = __float2bfloat16(v);
    p0[i] = hi; p1[i] = __float2bfloat16(v - __bfloat162float(hi));
}
// kvm v-part transposed -> [8][96][MK] hi/lo
__global__ void split_vT_kernel(const float* __restrict__ kvm, bf16* p0, bf16* p1) {
    long i = (long)blockIdx.x * 256 + threadIdx.x;
    if (i >= (long)HEADS * HD * MK) return;
    int h = (int)(i / (HD * MK));
    int rem = (int)(i - (long)h * HD * MK);
    int n = rem >> 10, k = rem & (MK - 1);
    float v = kvm[(long)k * (2 * CC) + CC + h * HD + n];
    bf16 hi = __float2bfloat16(v);
    p0[i] = hi; p1[i] = __float2bfloat16(v - __bfloat162float(hi));
}

// ---------------- fused LN -> xk, mnk, mk1 ----------------
__global__ void __launch_bounds__(256) ln_norm_kernel(float* __restrict__ xk,
    const float* __restrict__ g, const float* __restrict__ b,
    float* __restrict__ mnk, bf16* __restrict__ mk1)
{
    int row = blockIdx.x;
    float* p = xk + (long)row * CC;
    __shared__ float red[256];
    int tid = threadIdx.x;
    float v0 = p[tid], v1 = p[tid + 256], v2 = p[tid + 512];
    red[tid] = v0 + v1 + v2; __syncthreads();
    for (int off = 128; off; off >>= 1) { if (tid < off) red[tid] += red[tid + off]; __syncthreads(); }
    float mean = red[0] / (float)CC;
    __syncthreads();
    float d0 = v0 - mean, d1 = v1 - mean, d2 = v2 - mean;
    red[tid] = d0 * d0 + d1 * d1 + d2 * d2; __syncthreads();
    for (int off = 128; off; off >>= 1) { if (tid < off) red[tid] += red[tid + off]; __syncthreads(); }
    float var = red[0] / (float)CC;
    float inv = (float)(1.0 / sqrt((double)var + 1e-5));
    __syncthreads();
    float y0 = d0 * inv * g[tid] + b[tid];
    float y1 = d1 * inv * g[tid + 256] + b[tid + 256];
    float y2 = d2 * inv * g[tid + 512] + b[tid + 512];
    p[tid] = y0; p[tid + 256] = y1; p[tid + 512] = y2;
    red[tid] = y0 * y0 + y1 * y1 + y2 * y2; __syncthreads();
    for (int off = 128; off; off >>= 1) { if (tid < off) red[tid] += red[tid + off]; __syncthreads(); }
    float nrm = (float)(1.0 / sqrt((double)red[0]));
    float* q = mnk + (long)row * CC;
    bf16* q1 = mk1 + (long)row * CC;
    float n0 = y0 * nrm, n1 = y1 * nrm, n2 = y2 * nrm;
    q[tid] = n0; q[tid + 256] = n1; q[tid + 512] = n2;
    q1[tid] = __float2bfloat16(n0); q1[tid + 256] = __float2bfloat16(n1); q1[tid + 512] = __float2bfloat16(n2);
}
__global__ void __launch_bounds__(256) rownorm_cvt_kernel(const float* __restrict__ src,
    float* __restrict__ dst, bf16* __restrict__ dst1)
{
    int row = blockIdx.x;
    const float* p = src + (long)row * CC;
    __shared__ float red[256];
    int tid = threadIdx.x;
    float v0 = p[tid], v1 = p[tid + 256], v2 = p[tid + 512];
    red[tid] = v0 * v0 + v1 * v1 + v2 * v2; __syncthreads();
    for (int off = 128; off; off >>= 1) { if (tid < off) red[tid] += red[tid + off]; __syncthreads(); }
    float inv = (float)(1.0 / sqrt((double)red[0]));
    float* q = dst + (long)row * CC;
    bf16* q1 = dst1 + (long)row * CC;
    float n0 = v0 * inv, n1 = v1 * inv, n2 = v2 * inv;
    q[tid] = n0; q[tid + 256] = n1; q[tid + 512] = n2;
    q1[tid] = __float2bfloat16(n0); q1[tid + 256] = __float2bfloat16(n1); q1[tid + 512] = __float2bfloat16(n2);
}

// ---------------- refine (candidates from fused rowmax) ----------------
__global__ void __launch_bounds__(256) refine_kernel(
    const float* __restrict__ S, int ncol, const float* __restrict__ mn,
    const int* __restrict__ a_idx, const int* __restrict__ b_idx,
    const uint32_t* __restrict__ rmaxu, u64* __restrict__ key, float margin)
{
    int row = blockIdx.x * 8 + (threadIdx.x >> 5);
    int lane = threadIdx.x & 31;
    const float* p = S + (long)row * ncol;
    float thr = decf(rmaxu[row]) - margin;
    const float* av = mn + (long)a_idx[row] * CC;
    float bestv = -3.4e38f;
    int bestd = 0;
    for (int base = 0; base < ncol; base += 32) {
        float s = p[base + lane];
        unsigned m = __ballot_sync(0xffffffffu, s >= thr);
        while (m) {
            int b = __ffs(m) - 1;
            m &= m - 1;
            int dst = base + b;
            const float* bv = mn + (long)b_idx[dst] * CC;
            float part = 0.f;
            for (int c = lane; c < CC; c += 32) part += av[c] * bv[c];
            for (int off = 16; off; off >>= 1) part += __shfl_xor_sync(0xffffffffu, part, off);
            if (part > bestv) { bestv = part; bestd = dst; }
        }
    }
    if (lane == 0) {
        unsigned u = __float_as_uint(bestv);
        unsigned o = (u & 0x80000000u) ? ~u : (u | 0x80000000u);
        key[row] = ((u64)o << 32) | (unsigned)(~bestd);
    }
}

// ---------------- BSM index machinery ----------------
__global__ void unpack_val_kernel(const u64* __restrict__ key, float* __restrict__ val, int n) {
    int i = blockIdx.x * 256 + threadIdx.x;
    if (i >= n) return;
    uint32_t o = (uint32_t)(key[i] >> 32);
    uint32_t u = (o & 0x80000000u) ? (o ^ 0x80000000u) : ~o;
    val[i] = __uint_as_float(u);
}
__global__ void __launch_bounds__(256) rank_kernel(const float* __restrict__ v, int* __restrict__ perm, int n) {
    int i = blockIdx.x * 256 + threadIdx.x;
    float vi = (i < n) ? v[i] : 0.f;
    int r = 0;
    __shared__ float sv[256];
    for (int base = 0; base < n; base += 256) {
        int j = base + threadIdx.x;
        sv[threadIdx.x] = (j < n) ? v[j] : -3.4e38f;
        __syncthreads();
        int lim = min(256, n - base);
        for (int t = 0; t < lim; t++) {
            float vj = sv[t];
            int j2 = base + t;
            if (vj > vi || (vj == vi && j2 < i)) r++;
        }
        __syncthreads();
    }
    if (i < n) perm[r] = i;
}
__global__ void fill_dst_kernel(const int* __restrict__ perm, const u64* __restrict__ key,
                                int* __restrict__ dst, int* __restrict__ cnt, int R) {
    int e = blockIdx.x * 256 + threadIdx.x;
    if (e >= R) return;
    int s = perm[e];
    uint32_t low = (uint32_t)(key[s]);
    int dd = (int)(~low);
    dst[e] = dd;
    atomicAdd(&cnt[dd], 1);
}
__global__ void __launch_bounds__(256) merge_gather_kernel(const float* __restrict__ src, float* __restrict__ buf,
    const int* __restrict__ a_idx, const int* __restrict__ b_idx,
    const int* __restrict__ perm, int U, int R)
{
    int row = blockIdx.x;
    int tok = (row < U) ? a_idx[perm[R + row]] : b_idx[row - U];
    const float* s = src + (long)tok * CC;
    float* d = buf + (long)row * CC;
    for (int c = threadIdx.x; c < CC; c += 256) d[c] = s[c];
}
__global__ void __launch_bounds__(256) scatter_add_kernel(const float* __restrict__ src, float* __restrict__ buf,
    const int* __restrict__ a_idx, const int* __restrict__ perm, const int* __restrict__ dst, int U)
{
    int e = blockIdx.x;
    int tok = a_idx[perm[e]];
    float* d = buf + (long)(U + dst[e]) * CC;
    const float* s = src + (long)tok * CC;
    for (int c = threadIdx.x; c < CC; c += 256) atomicAdd(&d[c], s[c]);
}
__global__ void __launch_bounds__(256) div_cnt_kernel(float* __restrict__ buf, const int* __restrict__ cnt, int U) {
    int dr = blockIdx.x;
    float cf = (float)cnt[dr];
    float* p = buf + (long)(U + dr) * CC;
    for (int c = threadIdx.x; c < CC; c += 256) p[c] = p[c] / cf;
}

// ---------------- single-pass softmax -> bf16 hi/lo planes ----------------
__global__ void __launch_bounds__(256) softmax_b_kernel(const float* __restrict__ S,
    bf16* __restrict__ sh, bf16* __restrict__ sl)
{
    long row = blockIdx.x;
    const float4 v4 = ((const float4*)(S + row * MK))[threadIdx.x];
    float v[4] = {v4.x, v4.y, v4.z, v4.w};
    __shared__ float red[256];
    int tid = threadIdx.x;
    float m = fmaxf(fmaxf(v[0], v[1]), fmaxf(v[2], v[3]));
    red[tid] = m; __syncthreads();
    for (int off = 128; off; off >>= 1) { if (tid < off) red[tid] = fmaxf(red[tid], red[tid + off]); __syncthreads(); }
    float mx = red[0];
    __syncthreads();
    float e[4], s = 0.f;
#pragma unroll
    for (int i = 0; i < 4; i++) { e[i] = expf(v[i] - mx); s += e[i]; }
    red[tid] = s; __syncthreads();
    for (int off = 128; off; off >>= 1) { if (tid < off) red[tid] += red[tid + off]; __syncthreads(); }
    float inv = 1.0f / red[0];
    uint32_t hp[2], lp[2];
#pragma unroll
    for (int i = 0; i < 2; i++) {
        float a = e[2 * i] * inv, b = e[2 * i + 1] * inv;
        bf16 ha = __float2bfloat16(a), hb = __float2bfloat16(b);
        hp[i] = pkbf(ha, hb);
        lp[i] = pkbf(__float2bfloat16(a - __bfloat162float(ha)),
                     __float2bfloat16(b - __bfloat162float(hb)));
    }
    ((uint2*)(sh + row * MK))[tid] = make_uint2(hp[0], hp[1]);
    ((uint2*)(sl + row * MK))[tid] = make_uint2(lp[0], lp[1]);
}

// ---------------- unmerge ----------------
__global__ void __launch_bounds__(256) unmerge_kernel(const float* __restrict__ proj, float* __restrict__ out,
    const int* __restrict__ a_idx, const int* __restrict__ b_idx,
    const int* __restrict__ perm, const int* __restrict__ dst)
{
    int rid = blockIdx.x;
    int srcrow, tok;
    if (rid < NDQ) { srcrow = UQ + rid; tok = b_idx[rid]; }
    else if (rid < NDQ + UQ) { int u = rid - NDQ; srcrow = u; tok = a_idx[perm[RQ + u]]; }
    else { int e = rid - (NDQ + UQ); srcrow = UQ + dst[e]; tok = a_idx[perm[e]]; }
    const float* s = proj + (long)srcrow * CC;
    float* d = out + (long)tok * CC;
    for (int c = threadIdx.x; c < CC; c += 256) d[c] = s[c];
}

// ---------------- host launcher ----------------
#define SM_6_64_2  (2 * (3 * 8192 + 3 * 8192))   // 96 KB
#define SM_3_64_3  (3 * (2 * 8192 + 2 * 8192))   // 96 KB
#define SM_1_128_3 (3 * (8192 + 16384))          // 72 KB
#define SM_1_64_3  (3 * (8192 + 8192))           // 48 KB

extern "C" void kernel_launch(void* const* d_in, const int* in_sizes, int n_in,
                              void* d_out, int out_size)
{
    (void)in_sizes; (void)n_in; (void)out_size;
    const float* x   = (const float*)d_in[0];
    const float* srw = (const float*)d_in[1];
    const float* srb = (const float*)d_in[2];
    const float* lng = (const float*)d_in[3];
    const float* lnb = (const float*)d_in[4];
    const float* Wq  = (const float*)d_in[5];
    const float* Wkv = (const float*)d_in[6];
    const float* Wp  = (const float*)d_in[7];
    const float* bp  = (const float*)d_in[8];
    float* out = (float*)d_out;

    cudaFuncSetAttribute(mmg<6, 64, 2, 0, false>,  cudaFuncAttributeMaxDynamicSharedMemorySize, SM_6_64_2);
    cudaFuncSetAttribute(mmg<3, 64, 3, 0, false>,  cudaFuncAttributeMaxDynamicSharedMemorySize, SM_3_64_3);
    cudaFuncSetAttribute(mmg<3, 64, 3, 0, true>,   cudaFuncAttributeMaxDynamicSharedMemorySize, SM_3_64_3);
    cudaFuncSetAttribute(mmg<3, 64, 3, 2, false>,  cudaFuncAttributeMaxDynamicSharedMemorySize, SM_3_64_3);
    cudaFuncSetAttribute(mmg<3, 64, 3, 3, false>,  cudaFuncAttributeMaxDynamicSharedMemorySize, SM_3_64_3);
    cudaFuncSetAttribute(mmg<1, 128, 3, 1, false>, cudaFuncAttributeMaxDynamicSharedMemorySize, SM_1_128_3);
    cudaFuncSetAttribute(mmg<1, 64, 3, 1, false>,  cudaFuncAttributeMaxDynamicSharedMemorySize, SM_1_64_3);

    float *xk, *mnq, *mnk, *nvq, *nvk, *xq, *xkm, *kvm, *S, *proj;
    uint32_t* rmaxu;
    u64 *keyq, *keyk;
    int *permq, *permk, *dstq, *dstk, *cntq, *cntk, *aq, *bq, *ak, *bk, *ctok;
    bf16 *x3, *bt3, *mq1, *mk1, *xq2, *xkm2, *wq2, *wkv2, *wp2, *qp2, *kp2, *vp2, *ao2, *sh, *sl;
    cudaGetSymbolAddress((void**)&xk, g_xk);
    cudaGetSymbolAddress((void**)&mnq, g_mnq);
    cudaGetSymbolAddress((void**)&mnk, g_mnk);
    cudaGetSymbolAddress((void**)&nvq, g_nvq);
    cudaGetSymbolAddress((void**)&nvk, g_nvk);
    cudaGetSymbolAddress((void**)&rmaxu, g_rmaxu);
    cudaGetSymbolAddress((void**)&xq, g_xq);
    cudaGetSymbolAddress((void**)&xkm, g_xkm);
    cudaGetSymbolAddress((void**)&kvm, g_kvm);
    cudaGetSymbolAddress((void**)&S, g_S);
    cudaGetSymbolAddress((void**)&proj, g_proj);
    cudaGetSymbolAddress((void**)&keyq, g_keyq);
    cudaGetSymbolAddress((void**)&keyk, g_keyk);
    cudaGetSymbolAddress((void**)&permq, g_permq);
    cudaGetSymbolAddress((void**)&permk, g_permk);
    cudaGetSymbolAddress((void**)&dstq, g_dstq);
    cudaGetSymbolAddress((void**)&dstk, g_dstk);
    cudaGetSymbolAddress((void**)&cntq, g_cntq);
    cudaGetSymbolAddress((void**)&cntk, g_cntk);
    cudaGetSymbolAddress((void**)&aq, g_aq);
    cudaGetSymbolAddress((void**)&bq, g_bq);
    cudaGetSymbolAddress((void**)&ak, g_ak);
    cudaGetSymbolAddress((void**)&bk, g_bk);
    cudaGetSymbolAddress((void**)&ctok, g_ctok);
    cudaGetSymbolAddress((void**)&x3, g_x3);
    cudaGetSymbolAddress((void**)&bt3, g_bt3);
    cudaGetSymbolAddress((void**)&mq1, g_mq1);
    cudaGetSymbolAddress((void**)&mk1, g_mk1);
    cudaGetSymbolAddress((void**)&xq2, g_xq2);
    cudaGetSymbolAddress((void**)&xkm2, g_xkm2);
    cudaGetSymbolAddress((void**)&wq2, g_wq2);
    cudaGetSymbolAddress((void**)&wkv2, g_wkv2);
    cudaGetSymbolAddress((void**)&wp2, g_wp2);
    cudaGetSymbolAddress((void**)&qp2, g_qp2);
    cudaGetSymbolAddress((void**)&kp2, g_kp2);
    cudaGetSymbolAddress((void**)&vp2, g_vp2);
    cudaGetSymbolAddress((void**)&ao2, g_ao2);
    cudaGetSymbolAddress((void**)&sh, g_sh);
    cudaGetSymbolAddress((void**)&sl, g_sl);

    const long PXQ = (long)NQ * CC;
    const long PBT = (long)8 * CC * CC;
    const long PQ2 = (long)MQ * CC;
    const long PK2 = (long)MK * CC;
    const long PWQ = (long)CC * CC;
    const long PWKV = (long)2 * CC * CC;
    const long PQP = (long)HEADS * MQ * HD;
    const long PKP = (long)HEADS * MK * HD;
    const long PVP = (long)HEADS * HD * MK;
    float* Skv = S + (long)NAQ * NDQ;

    // 1-3: conv prerequisites
    split3_kernel<<<(int)((PXQ + 255) / 256), 256>>>(x, x3, x3 + PXQ, x3 + 2 * PXQ, PXQ);
    split3_bt_kernel<<<(int)((PBT + 255) / 256), 256>>>(srw, bt3, bt3 + PBT, bt3 + 2 * PBT);
    conv_tok_kernel<<<(8 * N2 + 255) / 256, 256>>>(ctok);
    // 4: conv GEMM (profiled slot)
    mmg<6, 64, 2, 0, false><<<dim3(CC / 64, N2 / 64, 1), 512, SM_6_64_2>>>(
        x3, x3 + PXQ, x3 + 2 * PXQ, CC, 0,
        bt3, bt3 + PBT, bt3 + 2 * PBT, CC, 0, (long)CC * CC,
        xk, CC, 0, srb, 1.f, nullptr, nullptr, 0, nullptr,
        CC, CC, 8, ctok, N2, nullptr);
    // 5: fused LN + rownorm + cvt
    ln_norm_kernel<<<N2, 256>>>(xk, lng, lnb, mnk, mk1);
    build_idx_kernel<<<(NQ + 255) / 256, 256>>>(D0, H0, W0, aq, bq);
    build_idx_kernel<<<(N2 + 255) / 256, 256>>>(D0 / 2, H0 / 2, W0 / 2, ak, bk);

    // ---- q-side BSM ----
    rownorm_cvt_kernel<<<NQ, 256>>>(x, mnq, mq1);
    set_u32_kernel<<<(NAQ + 255) / 256, 256>>>(rmaxu, NAQ, 0u);
    mmg<1, 128, 3, 1, false><<<dim3(NDQ / 128, NAQ / 64, 1), 512, SM_1_128_3>>>(
        mq1, nullptr, nullptr, CC, 0,
        mq1, nullptr, nullptr, CC, 0, 0,
        S, NDQ, 0, nullptr, 1.f, nullptr, nullptr, 0, rmaxu,
        NDQ, CC, 1, aq, 0, bq);
    refine_kernel<<<NAQ / 8, 256>>>(S, NDQ, mnq, aq, bq, rmaxu, keyq, 2e-3f);
    unpack_val_kernel<<<(NAQ + 255) / 256, 256>>>(keyq, nvq, NAQ);
    rank_kernel<<<NAQ / 256, 256>>>(nvq, permq, NAQ);
    set_int_kernel<<<(NDQ + 255) / 256, 256>>>(cntq, NDQ, 1);
    fill_dst_kernel<<<(RQ + 255) / 256, 256>>>(permq, keyq, dstq, cntq, RQ);
    merge_gather_kernel<<<MQ, 256>>>(x, xq, aq, bq, permq, UQ, RQ);
    scatter_add_kernel<<<RQ, 256>>>(x, xq, aq, permq, dstq, UQ);
    div_cnt_kernel<<<NDQ, 256>>>(xq, cntq, UQ);

    // ---- kv-side BSM ----
    set_u32_kernel<<<(NAK + 255) / 256, 256>>>(rmaxu, NAK, 0u);
    mmg<1, 64, 3, 1, false><<<dim3(NDK / 64, NAK / 64, 1), 512, SM_1_64_3>>>(
        mk1, nullptr, nullptr, CC, 0,
        mk1, nullptr, nullptr, CC, 0, 0,
        Skv, NDK, 0, nullptr, 1.f, nullptr, nullptr, 0, rmaxu,
        NDK, CC, 1, ak, 0, bk);
    refine_kernel<<<NAK / 8, 256>>>(Skv, NDK, mnk, ak, bk, rmaxu, keyk, 2e-3f);
    unpack_val_kernel<<<(NAK + 255) / 256, 256>>>(keyk, nvk, NAK);
    rank_kernel<<<NAK / 256, 256>>>(nvk, permk, NAK);
    set_int_kernel<<<1, 256>>>(cntk, NDK, 1);
    fill_dst_kernel<<<(RK + 255) / 256, 256>>>(permk, keyk, dstk, cntk, RK);
    merge_gather_kernel<<<MK, 256>>>(xk, xkm, ak, bk, permk, UK, RK);
    scatter_add_kernel<<<RK, 256>>>(xk, xkm, ak, permk, dstk, UK);
    div_cnt_kernel<<<NDK, 256>>>(xkm, cntk, UK);

    // ---- projections ----
    split2_kernel<<<(int)((PWQ + 255) / 256), 256>>>(Wq, wq2, wq2 + PWQ, PWQ);
    split2_kernel<<<(int)((PWKV + 255) / 256), 256>>>(Wkv, wkv2, wkv2 + PWKV, PWKV);
    split2_kernel<<<(int)((PWQ + 255) / 256), 256>>>(Wp, wp2, wp2 + PWQ, PWQ);
    split2_kernel<<<(int)((PQ2 + 255) / 256), 256>>>(xq, xq2, xq2 + PQ2, PQ2);
    split2_kernel<<<(int)((PK2 + 255) / 256), 256>>>(xkm, xkm2, xkm2 + PK2, PK2);
    // Wq -> head-major bf16 Q planes directly (EPI2)
    mmg<3, 64, 3, 2, false><<<dim3(CC / 64, MQ / 64, 1), 512, SM_3_64_3>>>(
        xq2, xq2 + PQ2, nullptr, CC, 0,
        wq2, wq2 + PWQ, nullptr, CC, 0, 0,
        nullptr, 0, 0, nullptr, 1.f, qp2, qp2 + PQP, (long)MQ * HD, nullptr,
        CC, CC, 1, nullptr, 0, nullptr);
    mmg<3, 64, 3, 0, false><<<dim3(2 * CC / 64, MK / 64, 1), 512, SM_3_64_3>>>(
        xkm2, xkm2 + PK2, nullptr, CC, 0,
        wkv2, wkv2 + PWKV, nullptr, CC, 0, 0,
        kvm, 2 * CC, 0, nullptr, 1.f, nullptr, nullptr, 0, nullptr,
        2 * CC, CC, 1, nullptr, 0, nullptr);

    // ---- head prep ----
    split_kpad_kernel<<<(int)((PKP + 255) / 256), 256>>>(kvm, kp2, kp2 + PKP);
    split_vT_kernel<<<(int)((PVP + 255) / 256), 256>>>(kvm, vp2, vp2 + PVP);

    // ---- attention (K = 96, unpadded; TK path only here) ----
    float scl = 1.0f / sqrtf((float)HD);
    mmg<3, 64, 3, 0, true><<<dim3(MK / 64, MQ / 64, HEADS), 512, SM_3_64_3>>>(
        qp2, qp2 + PQP, nullptr, HD, (long)MQ * HD,
        kp2, kp2 + PKP, nullptr, HD, (long)MK * HD, 0,
        S, MK, (long)MQ * MK, nullptr, scl, nullptr, nullptr, 0, nullptr,
        MK, HD, 1, nullptr, 0, nullptr);
    softmax_b_kernel<<<HEADS * MQ, 256>>>(S, sh, sl);
    // AV -> bf16 ao planes directly (EPI3, K = MK = 1024 -> no tail)
    mmg<3, 64, 3, 3, false><<<dim3(2, MQ / 64, HEADS), 512, SM_3_64_3>>>(
        sh, sl, nullptr, MK, (long)MQ * MK,
        vp2, vp2 + PVP, nullptr, MK, (long)HD * MK, 0,
        nullptr, CC, HD, nullptr, 1.f, ao2, ao2 + PQ2, 0, nullptr,
        HD, MK, 1, nullptr, 0, nullptr);

    // ---- output projection + unmerge ----
    mmg<3, 64, 3, 0, false><<<dim3(CC / 64, MQ / 64, 1), 512, SM_3_64_3>>>(
        ao2, ao2 + PQ2, nullptr, CC, 0,
        wp2, wp2 + PWQ, nullptr, CC, 0, 0,
        proj, CC, 0, bp, 1.f, nullptr, nullptr, 0, nullptr,
        CC, CC, 1, nullptr, 0, nullptr);
    unmerge_kernel<<<NQ, 256>>>(proj, out, aq, bq, permq, dstq);
}

// round 15
// speedup vs baseline: 1.0794x; 1.0274x over previous
#include <cuda_runtime.h>
#include <cuda_bf16.h>
#include <math.h>
#include <stdint.h>

// ---------------- static problem sizes ----------------
#define CC    768
#define D0    16
#define H0    32
#define W0    32
#define NQ    16384
#define NDQ   2048
#define NAQ   14336
#define RQ    8192
#define UQ    6144
#define MQ    8192
#define N2    2048
#define NDK   256
#define NAK   1792
#define RK    1024
#define UK    768
#define MK    1024
#define HEADS 8
#define HD    96
#define VN    97            // V rows incl. ones row
#define OLD   104           // padded ldc for O_unnorm

typedef __nv_bfloat16 bf16;
typedef unsigned long long u64;

// ---------------- device scratch ----------------
__device__ float g_xk[N2 * CC];
__device__ float g_mnq[NQ * CC];
__device__ float g_mnk[N2 * CC];
__device__ u64   g_keyq[NAQ];
__device__ u64   g_keyk[NAK];
__device__ float g_nvq[NAQ];
__device__ float g_nvk[NAK];
__device__ uint32_t g_rmaxu[HEADS * MQ];
__device__ int g_permq[NAQ];
__device__ int g_permk[NAK];
__device__ int g_dstq[RQ];
__device__ int g_dstk[RK];
__device__ int g_cntq[NDQ];
__device__ int g_cntk[NDK];
__device__ int g_aq[NAQ];
__device__ int g_bq[NDQ];
__device__ int g_ak[NAK];
__device__ int g_bk[NDK];
__device__ int g_ctok[8 * N2];
__device__ float g_xq[MQ * CC];
__device__ float g_xkm[MK * CC];
__device__ float g_kvm[MK * 2 * CC];
__device__ float g_S[(long)HEADS * MQ * MK];
__device__ float g_ou[(long)HEADS * MQ * OLD];
__device__ float g_proj[MQ * CC];

// bf16 planes
__device__ bf16 g_x3[3][NQ * CC];
__device__ bf16 g_bt3[3][8 * CC * CC];
__device__ bf16 g_mq1[NQ * CC];
__device__ bf16 g_mk1[N2 * CC];
__device__ bf16 g_xq2[2][MQ * CC];
__device__ bf16 g_xkm2[2][MK * CC];
__device__ bf16 g_wq2[2][CC * CC];
__device__ bf16 g_wkv2[2][2 * CC * CC];
__device__ bf16 g_wp2[2][CC * CC];
__device__ bf16 g_qp2[2][HEADS * MQ * HD];
__device__ bf16 g_kp2[2][HEADS * MK * HD];
__device__ bf16 g_vp2[2][HEADS * VN * MK];
__device__ bf16 g_ao2[2][MQ * CC];

__device__ __forceinline__ uint32_t smem_u32(const void* p) {
    uint32_t a;
    asm("{ .reg .u64 t; cvta.to.shared.u64 t, %1; cvt.u32.u64 %0, t; }" : "=r"(a) : "l"(p));
    return a;
}
__device__ __forceinline__ uint32_t pkbf(bf16 a, bf16 b) {
    return (uint32_t)__bfloat16_as_ushort(a) | ((uint32_t)__bfloat16_as_ushort(b) << 16);
}
__device__ __forceinline__ uint32_t encf(float f) {
    uint32_t u = __float_as_uint(f);
    return (u & 0x80000000u) ? ~u : (u | 0x80000000u);
}
__device__ __forceinline__ float decf(uint32_t o) {
    uint32_t u = (o & 0x80000000u) ? (o ^ 0x80000000u) : ~o;
    return __uint_as_float(u);
}
#define SWZ(o) ((o) ^ (((o) >> 3) & 0x70))
#define MMA16816(d, a, b0v, b1v) \
    asm volatile("mma.sync.aligned.m16n8k16.row.col.f32.bf16.bf16.f32 " \
        "{%0,%1,%2,%3}, {%4,%5,%6,%7}, {%8,%9}, {%0,%1,%2,%3};" \
        : "+f"((d)[0]), "+f"((d)[1]), "+f"((d)[2]), "+f"((d)[3]) \
        : "r"((a)[0]), "r"((a)[1]), "r"((a)[2]), "r"((a)[3]), "r"(b0v), "r"(b1v))
#define LDSM4(r, a) \
    asm volatile("ldmatrix.sync.aligned.m8n8.x4.shared.b16 {%0,%1,%2,%3}, [%4];" \
        : "=r"((r)[0]), "=r"((r)[1]), "=r"((r)[2]), "=r"((r)[3]) : "r"(a))
#define CPA(dst, src, sz) \
    asm volatile("cp.async.cg.shared.global [%0], [%1], 16, %2;" :: "r"(dst), "l"(src), "r"(sz) : "memory")
#define CPCOMMIT() asm volatile("cp.async.commit_group;" ::: "memory")
#define CPWAIT1()  asm volatile("cp.async.wait_group 1;" ::: "memory")

// ---------------- pipelined ldmatrix mma.sync split-bf16 GEMM ----------------
// C[M,N] = scale * A[M,K] @ B[N,K]^T (+bias), over ntap segments.
// Block 64 x TN, k-tile 64, STAGES pipeline, 16 warps (4m x 4n), warp 16 x TN/4.
// TK=false: K%64==0, no tail logic. TK=true: K%32==0, tail zero-fill/skip.
// AEXP (NPR=3 only): A is fp32; load, exp(a - rmax[z*phs + row]) (__expf),
// split hi/lo, STS into the two A planes (B stays cp.async).
// EPI: 0 fp32 C; 1 fp32 C + atomicMax rowmax at rmaxu[z*phs + r];
// 2 head-major bf16 hi/lo split (phs = per-head plane stride, HD-wide rows);
// 3 bf16 hi/lo split at C-addressing.
template <int NPR, int TN, int STAGES, int EPI, bool TK, bool AEXP = false>
__global__ void __launch_bounds__(512, 2) mmg(
    const bf16* A0, const bf16* A1, const bf16* A2, long lda, long ahs,
    const bf16* B0, const bf16* B1, const bf16* B2, long ldb, long bhs, long bseg,
    float* C, long ldc, long chs, const float* bias, float scale,
    bf16* P0, bf16* P1, long phs, uint32_t* rmaxu,
    int N, int K, int ntap, const int* gA, int gAs, const int* gB)
{
    constexpr int nA = (NPR == 6) ? 3 : (NPR == 3) ? 2 : 1;
    constexpr int nB = nA;
    constexpr int PLA = 8192;          // 64 rows x 128 B
    constexpr int PLB = TN * 128;
    constexpr int STG = nA * PLA + nB * PLB;
    constexpr int NJ = TN / 32;
    extern __shared__ char sm[];
    const uint32_t su = smem_u32(sm);

    const int tid = threadIdx.x, lane = tid & 31, wid = tid >> 5;
    const int wm = wid >> 2, wn = wid & 3;
    const int m0 = blockIdx.y * 64, n0 = blockIdx.x * TN, z = blockIdx.z;
    const int lq = lane >> 2, lr = lane & 3;

    const int lrA = tid >> 3, secA = tid & 7;
    const int lrB = (TN == 128) ? (tid >> 2) : (tid >> 3);
    const int secB = (TN == 128) ? (tid & 3) : (tid & 7);
    const int nrow = n0 + lrB;
    const bool bval = nrow < N;
    const long brow = bval ? (gB ? (long)gB[nrow] : (long)nrow) : 0;
    const uint32_t bsz = bval ? 16u : 0u;

    const uint32_t dA0 = SWZ((uint32_t)(lrA * 128 + secA * 16));
    const uint32_t dB0 = (TN == 128) ? SWZ((uint32_t)(lrB * 128 + secB * 32))
                                     : SWZ((uint32_t)(lrB * 128 + secB * 16));
    const uint32_t dB1 = (TN == 128) ? SWZ((uint32_t)(lrB * 128 + secB * 32 + 16)) : 0u;

    const int kcd = (K + 63) >> 6;
    const int nch = ntap * kcd;
    const bf16* Ap[3] = {A0, A1, A2};
    const bf16* Bp[3] = {B0, B1, B2};

    float acc[NJ][4];
#pragma unroll
    for (int j = 0; j < NJ; j++)
#pragma unroll
        for (int t = 0; t < 4; t++) acc[j][t] = 0.f;

    auto issue = [&](int c) {
        const int stg = c % STAGES;
        const uint32_t sb = su + stg * STG;
        const int tap = c / kcd;
        const int k0 = (c - tap * kcd) << 6;
        if constexpr (AEXP) {
            const long arow = m0 + lrA;
            const float rm = decf(rmaxu[(long)z * phs + arow]);
            const float* Af = reinterpret_cast<const float*>(A0)
                              + (long)z * ahs + arow * lda + k0 + secA * 8;
            float4 va = *(const float4*)(Af);
            float4 vb = *(const float4*)(Af + 4);
            float e0 = __expf(va.x - rm), e1 = __expf(va.y - rm);
            float e2 = __expf(va.z - rm), e3 = __expf(va.w - rm);
            float e4 = __expf(vb.x - rm), e5 = __expf(vb.y - rm);
            float e6 = __expf(vb.z - rm), e7 = __expf(vb.w - rm);
            bf16 h0 = __float2bfloat16(e0), h1 = __float2bfloat16(e1);
            bf16 h2 = __float2bfloat16(e2), h3 = __float2bfloat16(e3);
            bf16 h4 = __float2bfloat16(e4), h5 = __float2bfloat16(e5);
            bf16 h6 = __float2bfloat16(e6), h7 = __float2bfloat16(e7);
            uint4 hv = make_uint4(pkbf(h0, h1), pkbf(h2, h3), pkbf(h4, h5), pkbf(h6, h7));
            uint4 lv = make_uint4(
                pkbf(__float2bfloat16(e0 - __bfloat162float(h0)), __float2bfloat16(e1 - __bfloat162float(h1))),
                pkbf(__float2bfloat16(e2 - __bfloat162float(h2)), __float2bfloat16(e3 - __bfloat162float(h3))),
                pkbf(__float2bfloat16(e4 - __bfloat162float(h4)), __float2bfloat16(e5 - __bfloat162float(h5))),
                pkbf(__float2bfloat16(e6 - __bfloat162float(h6)), __float2bfloat16(e7 - __bfloat162float(h7))));
            *(uint4*)(sm + stg * STG + dA0) = hv;
            *(uint4*)(sm + stg * STG + PLA + dA0) = lv;
        } else if constexpr (!TK) {
            const long arow = gA ? (long)gA[tap * gAs + m0 + lrA] : (long)(m0 + lrA);
#pragma unroll
            for (int p = 0; p < nA; p++) {
                const bf16* s0 = Ap[p] + (long)z * ahs + arow * lda + k0 + secA * 8;
                CPA(sb + p * PLA + dA0, s0, 16u);
            }
        } else {
            const long arow = gA ? (long)gA[tap * gAs + m0 + lrA] : (long)(m0 + lrA);
            const uint32_t szA = (k0 + secA * 8 < K) ? 16u : 0u;
            const int kaA = szA ? (k0 + secA * 8) : 0;
#pragma unroll
            for (int p = 0; p < nA; p++) {
                const bf16* s0 = Ap[p] + (long)z * ahs + arow * lda + kaA;
                CPA(sb + p * PLA + dA0, s0, szA);
            }
        }
        if constexpr (!TK) {
            if constexpr (!AEXP) {
#pragma unroll
                for (int p = 0; p < nB; p++) {
                    const bf16* s0 = Bp[p] + (long)z * bhs + (long)tap * bseg + brow * ldb + k0
                                   + secB * (TN == 128 ? 16 : 8);
                    CPA(sb + nA * PLA + p * PLB + dB0, s0, bsz);
                    if (TN == 128) CPA(sb + nA * PLA + p * PLB + dB1, s0 + 8, bsz);
                }
            } else {
#pragma unroll
                for (int p = 0; p < nB; p++) {
                    const bf16* s0 = Bp[p] + (long)z * bhs + (long)tap * bseg + brow * ldb + k0
                                   + secB * (TN == 128 ? 16 : 8);
                    CPA(sb + nA * PLA + p * PLB + dB0, s0, bsz);
                    if (TN == 128) CPA(sb + nA * PLA + p * PLB + dB1, s0 + 8, bsz);
                }
            }
        } else {
            if (TN == 128) {
                const uint32_t sz0 = (k0 + secB * 16 < K) ? bsz : 0u;
                const uint32_t sz1 = (k0 + secB * 16 + 8 < K) ? bsz : 0u;
                const int kb0 = sz0 ? (k0 + secB * 16) : 0;
                const int kb1 = sz1 ? (k0 + secB * 16 + 8) : 0;
#pragma unroll
                for (int p = 0; p < nB; p++) {
                    const bf16* s0 = Bp[p] + (long)z * bhs + (long)tap * bseg + brow * ldb;
                    CPA(sb + nA * PLA + p * PLB + dB0, s0 + kb0, sz0);
                    CPA(sb + nA * PLA + p * PLB + dB1, s0 + kb1, sz1);
                }
            } else {
                const uint32_t sz0 = (k0 + secB * 8 < K) ? bsz : 0u;
                const int kb0 = sz0 ? (k0 + secB * 8) : 0;
#pragma unroll
                for (int p = 0; p < nB; p++) {
                    const bf16* s0 = Bp[p] + (long)z * bhs + (long)tap * bseg + brow * ldb;
                    CPA(sb + nA * PLA + p * PLB + dB0, s0 + kb0, sz0);
                }
            }
        }
        CPCOMMIT();
    };

    auto compute = [&](int stg, int kslim) {
        const uint32_t sb = su + stg * STG;
        const int pa6[6] = {0, 0, 1, 1, 0, 2}, pb6[6] = {0, 1, 0, 1, 2, 0};
#pragma unroll
        for (int ks = 0; ks < 4; ks++) {
            if constexpr (TK) { if (ks >= kslim) break; }
            uint32_t af[nA][4];
#pragma unroll
            for (int p = 0; p < nA; p++) {
                uint32_t off = (uint32_t)((wm * 16 + (lane & 15)) * 128
                                          + ks * 32 + ((lane >> 4) << 4));
                LDSM4(af[p], sb + p * PLA + SWZ(off));
            }
            uint32_t bl[nB][NJ], bh[nB][NJ];
            if constexpr (TN == 128) {
#pragma unroll
                for (int p = 0; p < nB; p++) {
                    uint32_t r0[4], r1[4];
                    uint32_t off0 = (uint32_t)((wn * 32 + (lane >> 3) * 8 + (lane & 7)) * 128 + ks * 32);
                    LDSM4(r0, sb + nA * PLA + p * PLB + SWZ(off0));
                    LDSM4(r1, sb + nA * PLA + p * PLB + SWZ(off0 + 16));
#pragma unroll
                    for (int j = 0; j < 4; j++) { bl[p][j] = r0[j]; bh[p][j] = r1[j]; }
                }
            } else {
#pragma unroll
                for (int p = 0; p < nB; p++) {
                    uint32_t r[4];
                    const int tileB = (lane >> 3) & 1, khB = lane >> 4;
                    uint32_t off = (uint32_t)((wn * 16 + tileB * 8 + (lane & 7)) * 128
                                              + ks * 32 + khB * 16);
                    LDSM4(r, sb + nA * PLA + p * PLB + SWZ(off));
                    bl[p][0] = r[0]; bl[p][1] = r[1]; bh[p][0] = r[2]; bh[p][1] = r[3];
                }
            }
#pragma unroll
            for (int pr = 0; pr < NPR; pr++) {
                const int pA = (NPR == 1) ? 0 : pa6[pr];
                const int pB = (NPR == 1) ? 0 : pb6[pr];
#pragma unroll
                for (int j = 0; j < NJ; j++)
                    MMA16816(acc[j], af[pA], bl[pB][j], bh[pB][j]);
            }
        }
    };

    issue(0);
    for (int c = 0; c < nch; c++) {
        if (c + 1 < nch) issue(c + 1);
        else CPCOMMIT();
        CPWAIT1();
        __syncthreads();
        if constexpr (TK) {
            const int k0c = (c % kcd) << 6;
            int kslim = (K - k0c + 15) >> 4; if (kslim > 4) kslim = 4;
            compute(c % STAGES, kslim);
        } else {
            compute(c % STAGES, 4);
        }
        if (STAGES == 2) __syncthreads();
    }

    // ---- epilogue ----
    const int r = m0 + wm * 16 + lq;
    if constexpr (EPI == 0 || EPI == 1) {
        float mx0 = -3.4e38f, mx1 = -3.4e38f;
#pragma unroll
        for (int j = 0; j < NJ; j++) {
            const int cb = n0 + wn * (TN / 4) + j * 8 + lr * 2;
            if (cb < N) {
                float bb0 = bias ? bias[cb] : 0.f;
                float bb1 = bias ? bias[cb + 1] : 0.f;
                float v0 = acc[j][0] * scale + bb0, v1 = acc[j][1] * scale + bb1;
                float v2 = acc[j][2] * scale + bb0, v3 = acc[j][3] * scale + bb1;
                float* p0 = C + (long)z * chs + (long)r * ldc + cb;
                float* p1 = C + (long)z * chs + (long)(r + 8) * ldc + cb;
                p0[0] = v0; p0[1] = v1; p1[0] = v2; p1[1] = v3;
                if (EPI == 1) {
                    mx0 = fmaxf(mx0, fmaxf(v0, v1));
                    mx1 = fmaxf(mx1, fmaxf(v2, v3));
                }
            }
        }
        if constexpr (EPI == 1) {
            mx0 = fmaxf(mx0, __shfl_xor_sync(0xffffffffu, mx0, 1));
            mx0 = fmaxf(mx0, __shfl_xor_sync(0xffffffffu, mx0, 2));
            mx1 = fmaxf(mx1, __shfl_xor_sync(0xffffffffu, mx1, 1));
            mx1 = fmaxf(mx1, __shfl_xor_sync(0xffffffffu, mx1, 2));
            if (lr == 0) {
                atomicMax(&rmaxu[(long)z * phs + r], encf(mx0));
                atomicMax(&rmaxu[(long)z * phs + r + 8], encf(mx1));
            }
        }
    } else if constexpr (EPI == 2) {
#pragma unroll
        for (int j = 0; j < NJ; j++) {
            const int cb = n0 + wn * (TN / 4) + j * 8 + lr * 2;
            if (cb < N) {
                int h = cb / HD, k = cb - h * HD;
                float v0 = acc[j][0] * scale, v1 = acc[j][1] * scale;
                float v2 = acc[j][2] * scale, v3 = acc[j][3] * scale;
                bf16 h0 = __float2bfloat16(v0), h1 = __float2bfloat16(v1);
                bf16 h2 = __float2bfloat16(v2), h3 = __float2bfloat16(v3);
                bf16* q0 = P0 + (long)h * phs + (long)r * HD + k;
                bf16* l0 = P1 + (long)h * phs + (long)r * HD + k;
                q0[0] = h0; q0[1] = h1;
                l0[0] = __float2bfloat16(v0 - __bfloat162float(h0));
                l0[1] = __float2bfloat16(v1 - __bfloat162float(h1));
                bf16* q1 = P0 + (long)h * phs + (long)(r + 8) * HD + k;
                bf16* l1 = P1 + (long)h * phs + (long)(r + 8) * HD + k;
                q1[0] = h2; q1[1] = h3;
                l1[0] = __float2bfloat16(v2 - __bfloat162float(h2));
                l1[1] = __float2bfloat16(v3 - __bfloat162float(h3));
            }
        }
    } else {   // EPI == 3
#pragma unroll
        for (int j = 0; j < NJ; j++) {
            const int cb = n0 + wn * (TN / 4) + j * 8 + lr * 2;
            if (cb < N) {
                float v0 = acc[j][0] * scale, v1 = acc[j][1] * scale;
                float v2 = acc[j][2] * scale, v3 = acc[j][3] * scale;
                bf16 h0 = __float2bfloat16(v0), h1 = __float2bfloat16(v1);
                bf16 h2 = __float2bfloat16(v2), h3 = __float2bfloat16(v3);
                long o0 = (long)z * chs + (long)r * ldc + cb;
                long o1 = (long)z * chs + (long)(r + 8) * ldc + cb;
                P0[o0] = h0; P0[o0 + 1] = h1;
                P1[o0] = __float2bfloat16(v0 - __bfloat162float(h0));
                P1[o0 + 1] = __float2bfloat16(v1 - __bfloat162float(h1));
                P0[o1] = h2; P0[o1 + 1] = h3;
                P1[o1] = __float2bfloat16(v2 - __bfloat162float(h2));
                P1[o1 + 1] = __float2bfloat16(v3 - __bfloat162float(h3));
            }
        }
    }
}

// ---------------- utility / prep kernels ----------------
__global__ void set_int_kernel(int* p, int n, int v) {
    int i = blockIdx.x * 256 + threadIdx.x;
    if (i < n) p[i] = v;
}
__global__ void set_u32_kernel(uint32_t* p, int n, uint32_t v) {
    int i = blockIdx.x * 256 + threadIdx.x;
    if (i < n) p[i] = v;
}
__global__ void build_idx_kernel(int D, int H, int W, int* a_idx, int* b_idx) {
    int n = D * H * W;
    int t = blockIdx.x * 256 + threadIdx.x;
    if (t >= n) return;
    int z = t / (H * W), y = (t / W) % H, xx = t % W;
    int hw2 = (H >> 1) * (W >> 1);
    if (((z | y | xx) & 1) == 0) {
        b_idx[(z >> 1) * hw2 + (y >> 1) * (W >> 1) + (xx >> 1)] = t;
    } else {
        int cez = (z + 1) >> 1, cey = (y + 1) >> 1, cex = (xx + 1) >> 1;
        int before = cez * hw2;
        if ((z & 1) == 0) { before += cey * (W >> 1); if ((y & 1) == 0) before += cex; }
        a_idx[t - before] = t;
    }
}
__global__ void conv_tok_kernel(int* t) {
    int i = blockIdx.x * 256 + threadIdx.x;
    if (i >= 8 * N2) return;
    int tap = i >> 11, m = i & 2047;
    int kz = tap >> 2, ky = (tap >> 1) & 1, kx = tap & 1;
    int z2 = m >> 8, y2 = (m >> 4) & 15, x2 = m & 15;
    t[i] = (2 * z2 + kz) * (H0 * W0) + (2 * y2 + ky) * W0 + (2 * x2 + kx);
}
__global__ void split3_kernel(const float* __restrict__ s, bf16* p0, bf16* p1, bf16* p2, long n) {
    long i = (long)blockIdx.x * 256 + threadIdx.x;
    if (i >= n) return;
    float v = s[i];
    bf16 h = __float2bfloat16(v); float r = v - __bfloat162float(h);
    bf16 m = __float2bfloat16(r); float r2 = r - __bfloat162float(m);
    p0[i] = h; p1[i] = m; p2[i] = __float2bfloat16(r2);
}
__global__ void split2_kernel(const float* __restrict__ s, bf16* p0, bf16* p1, long n) {
    long i = (long)blockIdx.x * 256 + threadIdx.x;
    if (i >= n) return;
    float v = s[i];
    bf16 h = __float2bfloat16(v);
    p0[i] = h; p1[i] = __float2bfloat16(v - __bfloat162float(h));
}
__global__ void split3_bt_kernel(const float* __restrict__ w, bf16* p0, bf16* p1, bf16* p2) {
    long i = (long)blockIdx.x * 256 + threadIdx.x;
    if (i >= (long)8 * CC * CC) return;
    int tap = (int)(i / (CC * CC));
    int rem = (int)(i - (long)tap * CC * CC);
    int n = rem / CC, k = rem - n * CC;
    float v = w[(long)n * (CC * 8) + k * 8 + tap];
    bf16 h = __float2bfloat16(v); float r = v - __bfloat162float(h);
    bf16 m = __float2bfloat16(r);
    p0[i] = h; p1[i] = m; p2[i] = __float2bfloat16(r - __bfloat162float(m));
}
// kvm k-part -> [8][MK][96] hi/lo
__global__ void split_kpad_kernel(const float* __restrict__ kvm, bf16* p0, bf16* p1) {
    long i = (long)blockIdx.x * 256 + threadIdx.x;
    if (i >= (long)HEADS * MK * HD) return;
    int h = (int)(i / (MK * HD));
    int rem = (int)(i - (long)h * MK * HD);
    int m = rem / HD, k = rem - m * HD;
    float v = kvm[(long)m * (2 * CC) + h * HD + k];
    bf16 hi = __float2bfloat16(v);
    p0[i] = hi; p1[i] = __float2bfloat16(v - __bfloat162float(hi));
}
// kvm v-part transposed -> [8][97][MK] hi/lo (row 96 = ones for row-sum)
__global__ void split_vT_kernel(const float* __restrict__ kvm, bf16* p0, bf16* p1) {
    long i = (long)blockIdx.x * 256 + threadIdx.x;
    if (i >= (long)HEADS * VN * MK) return;
    int h = (int)(i / (VN * MK));
    int rem = (int)(i - (long)h * VN * MK);
    int n = rem >> 10, k = rem & (MK - 1);
    float v = (n < HD) ? kvm[(long)k * (2 * CC) + CC + h * HD + n] : 1.0f;
    bf16 hi = __float2bfloat16(v);
    p0[i] = hi; p1[i] = __float2bfloat16(v - __bfloat162float(hi));
}

// ---------------- fused LN -> xk, mnk, mk1 ----------------
__global__ void __launch_bounds__(256) ln_norm_kernel(float* __restrict__ xk,
    const float* __restrict__ g, const float* __restrict__ b,
    float* __restrict__ mnk, bf16* __restrict__ mk1)
{
    int row = blockIdx.x;
    float* p = xk + (long)row * CC;
    __shared__ float red[256];
    int tid = threadIdx.x;
    float v0 = p[tid], v1 = p[tid + 256], v2 = p[tid + 512];
    red[tid] = v0 + v1 + v2; __syncthreads();
    for (int off = 128; off; off >>= 1) { if (tid < off) red[tid] += red[tid + off]; __syncthreads(); }
    float mean = red[0] / (float)CC;
    __syncthreads();
    float d0 = v0 - mean, d1 = v1 - mean, d2 = v2 - mean;
    red[tid] = d0 * d0 + d1 * d1 + d2 * d2; __syncthreads();
    for (int off = 128; off; off >>= 1) { if (tid < off) red[tid] += red[tid + off]; __syncthreads(); }
    float var = red[0] / (float)CC;
    float inv = (float)(1.0 / sqrt((double)var + 1e-5));
    __syncthreads();
    float y0 = d0 * inv * g[tid] + b[tid];
    float y1 = d1 * inv * g[tid + 256] + b[tid + 256];
    float y2 = d2 * inv * g[tid + 512] + b[tid + 512];
    p[tid] = y0; p[tid + 256] = y1; p[tid + 512] = y2;
    red[tid] = y0 * y0 + y1 * y1 + y2 * y2; __syncthreads();
    for (int off = 128; off; off >>= 1) { if (tid < off) red[tid] += red[tid + off]; __syncthreads(); }
    float nrm = (float)(1.0 / sqrt((double)red[0]));
    float* q = mnk + (long)row * CC;
    bf16* q1 = mk1 + (long)row * CC;
    float n0 = y0 * nrm, n1 = y1 * nrm, n2 = y2 * nrm;
    q[tid] = n0; q[tid + 256] = n1; q[tid + 512] = n2;
    q1[tid] = __float2bfloat16(n0); q1[tid + 256] = __float2bfloat16(n1); q1[tid + 512] = __float2bfloat16(n2);
}
__global__ void __launch_bounds__(256) rownorm_cvt_kernel(const float* __restrict__ src,
    float* __restrict__ dst, bf16* __restrict__ dst1)
{
    int row = blockIdx.x;
    const float* p = src + (long)row * CC;
    __shared__ float red[256];
    int tid = threadIdx.x;
    float v0 = p[tid], v1 = p[tid + 256], v2 = p[tid + 512];
    red[tid] = v0 * v0 + v1 * v1 + v2 * v2; __syncthreads();
    for (int off = 128; off; off >>= 1) { if (tid < off) red[tid] += red[tid + off]; __syncthreads(); }
    float inv = (float)(1.0 / sqrt((double)red[0]));
    float* q = dst + (long)row * CC;
    bf16* q1 = dst1 + (long)row * CC;
    float n0 = v0 * inv, n1 = v1 * inv, n2 = v2 * inv;
    q[tid] = n0; q[tid + 256] = n1; q[tid + 512] = n2;
    q1[tid] = __float2bfloat16(n0); q1[tid + 256] = __float2bfloat16(n1); q1[tid + 512] = __float2bfloat16(n2);
}

// ---------------- refine (candidates from fused rowmax) ----------------
__global__ void __launch_bounds__(256) refine_kernel(
    const float* __restrict__ S, int ncol, const float* __restrict__ mn,
    const int* __restrict__ a_idx, const int* __restrict__ b_idx,
    const uint32_t* __restrict__ rmaxu, u64* __restrict__ key, float margin)
{
    int row = blockIdx.x * 8 + (threadIdx.x >> 5);
    int lane = threadIdx.x & 31;
    const float* p = S + (long)row * ncol;
    float thr = decf(rmaxu[row]) - margin;
    const float* av = mn + (long)a_idx[row] * CC;
    float bestv = -3.4e38f;
    int bestd = 0;
    for (int base = 0; base < ncol; base += 32) {
        float s = p[base + lane];
        unsigned m = __ballot_sync(0xffffffffu, s >= thr);
        while (m) {
            int b = __ffs(m) - 1;
            m &= m - 1;
            int dst = base + b;
            const float* bv = mn + (long)b_idx[dst] * CC;
            float part = 0.f;
            for (int c = lane; c < CC; c += 32) part += av[c] * bv[c];
            for (int off = 16; off; off >>= 1) part += __shfl_xor_sync(0xffffffffu, part, off);
            if (part > bestv) { bestv = part; bestd = dst; }
        }
    }
    if (lane == 0) {
        unsigned u = __float_as_uint(bestv);
        unsigned o = (u & 0x80000000u) ? ~u : (u | 0x80000000u);
        key[row] = ((u64)o << 32) | (unsigned)(~bestd);
    }
}

// ---------------- BSM index machinery ----------------
__global__ void unpack_val_kernel(const u64* __restrict__ key, float* __restrict__ val, int n) {
    int i = blockIdx.x * 256 + threadIdx.x;
    if (i >= n) return;
    uint32_t o = (uint32_t)(key[i] >> 32);
    uint32_t u = (o & 0x80000000u) ? (o ^ 0x80000000u) : ~o;
    val[i] = __uint_as_float(u);
}
__global__ void __launch_bounds__(256) rank_kernel(const float* __restrict__ v, int* __restrict__ perm, int n) {
    int i = blockIdx.x * 256 + threadIdx.x;
    float vi = (i < n) ? v[i] : 0.f;
    int r = 0;
    __shared__ float sv[256];
    for (int base = 0; base < n; base += 256) {
        int j = base + threadIdx.x;
        sv[threadIdx.x] = (j < n) ? v[j] : -3.4e38f;
        __syncthreads();
        int lim = min(256, n - base);
        for (int t = 0; t < lim; t++) {
            float vj = sv[t];
            int j2 = base + t;
            if (vj > vi || (vj == vi && j2 < i)) r++;
        }
        __syncthreads();
    }
    if (i < n) perm[r] = i;
}
__global__ void fill_dst_kernel(const int* __restrict__ perm, const u64* __restrict__ key,
                                int* __restrict__ dst, int* __restrict__ cnt, int R) {
    int e = blockIdx.x * 256 + threadIdx.x;
    if (e >= R) return;
    int s = perm[e];
    uint32_t low = (uint32_t)(key[s]);
    int dd = (int)(~low);
    dst[e] = dd;
    atomicAdd(&cnt[dd], 1);
}
__global__ void __launch_bounds__(256) merge_gather_kernel(const float* __restrict__ src, float* __restrict__ buf,
    const int* __restrict__ a_idx, const int* __restrict__ b_idx,
    const int* __restrict__ perm, int U, int R)
{
    int row = blockIdx.x;
    int tok = (row < U) ? a_idx[perm[R + row]] : b_idx[row - U];
    const float* s = src + (long)tok * CC;
    float* d = buf + (long)row * CC;
    for (int c = threadIdx.x; c < CC; c += 256) d[c] = s[c];
}
__global__ void __launch_bounds__(256) scatter_add_kernel(const float* __restrict__ src, float* __restrict__ buf,
    const int* __restrict__ a_idx, const int* __restrict__ perm, const int* __restrict__ dst, int U)
{
    int e = blockIdx.x;
    int tok = a_idx[perm[e]];
    float* d = buf + (long)(U + dst[e]) * CC;
    const float* s = src + (long)tok * CC;
    for (int c = threadIdx.x; c < CC; c += 256) atomicAdd(&d[c], s[c]);
}
__global__ void __launch_bounds__(256) div_cnt_kernel(float* __restrict__ buf, const int* __restrict__ cnt, int U) {
    int dr = blockIdx.x;
    float cf = (float)cnt[dr];
    float* p = buf + (long)(U + dr) * CC;
    for (int c = threadIdx.x; c < CC; c += 256) p[c] = p[c] / cf;
}

// ---------------- normalize O_unnorm -> ao2 hi/lo planes ----------------
__global__ void __launch_bounds__(256) normalize_kernel(const float* __restrict__ O,
    bf16* __restrict__ p0, bf16* __restrict__ p1)
{
    int r = blockIdx.x, tid = threadIdx.x;
    for (int i = tid; i < CC; i += 256) {
        int h = i / HD, k = i - h * HD;
        const float* Orow = O + (long)h * MQ * OLD + (long)r * OLD;
        float inv = 1.0f / Orow[HD];       // ones-column sum (>= 1)
        float v = Orow[k] * inv;
        bf16 hi = __float2bfloat16(v);
        p0[(long)r * CC + i] = hi;
        p1[(long)r * CC + i] = __float2bfloat16(v - __bfloat162float(hi));
    }
}

// ---------------- unmerge ----------------
__global__ void __launch_bounds__(256) unmerge_kernel(const float* __restrict__ proj, float* __restrict__ out,
    const int* __restrict__ a_idx, const int* __restrict__ b_idx,
    const int* __restrict__ perm, const int* __restrict__ dst)
{
    int rid = blockIdx.x;
    int srcrow, tok;
    if (rid < NDQ) { srcrow = UQ + rid; tok = b_idx[rid]; }
    else if (rid < NDQ + UQ) { int u = rid - NDQ; srcrow = u; tok = a_idx[perm[RQ + u]]; }
    else { int e = rid - (NDQ + UQ); srcrow = UQ + dst[e]; tok = a_idx[perm[e]]; }
    const float* s = proj + (long)srcrow * CC;
    float* d = out + (long)tok * CC;
    for (int c = threadIdx.x; c < CC; c += 256) d[c] = s[c];
}

// ---------------- host launcher ----------------
#define SM_6_64_2  (2 * (3 * 8192 + 3 * 8192))   // 96 KB
#define SM_3_64_3  (3 * (2 * 8192 + 2 * 8192))   // 96 KB
#define SM_1_128_3 (3 * (8192 + 16384))          // 72 KB
#define SM_1_64_3  (3 * (8192 + 8192))           // 48 KB

extern "C" void kernel_launch(void* const* d_in, const int* in_sizes, int n_in,
                              void* d_out, int out_size)
{
    (void)in_sizes; (void)n_in; (void)out_size;
    const float* x   = (const float*)d_in[0];
    const float* srw = (const float*)d_in[1];
    const float* srb = (const float*)d_in[2];
    const float* lng = (const float*)d_in[3];
    const float* lnb = (const float*)d_in[4];
    const float* Wq  = (const float*)d_in[5];
    const float* Wkv = (const float*)d_in[6];
    const float* Wp  = (const float*)d_in[7];
    const float* bp  = (const float*)d_in[8];
    float* out = (float*)d_out;

    cudaFuncSetAttribute(mmg<6, 64, 2, 0, false>,        cudaFuncAttributeMaxDynamicSharedMemorySize, SM_6_64_2);
    cudaFuncSetAttribute(mmg<3, 64, 3, 0, false>,        cudaFuncAttributeMaxDynamicSharedMemorySize, SM_3_64_3);
    cudaFuncSetAttribute(mmg<3, 64, 3, 1, true>,         cudaFuncAttributeMaxDynamicSharedMemorySize, SM_3_64_3);
    cudaFuncSetAttribute(mmg<3, 64, 3, 0, false, true>,  cudaFuncAttributeMaxDynamicSharedMemorySize, SM_3_64_3);
    cudaFuncSetAttribute(mmg<3, 64, 3, 2, false>,        cudaFuncAttributeMaxDynamicSharedMemorySize, SM_3_64_3);
    cudaFuncSetAttribute(mmg<1, 128, 3, 1, false>,       cudaFuncAttributeMaxDynamicSharedMemorySize, SM_1_128_3);
    cudaFuncSetAttribute(mmg<1, 64, 3, 1, false>,        cudaFuncAttributeMaxDynamicSharedMemorySize, SM_1_64_3);

    float *xk, *mnq, *mnk, *nvq, *nvk, *xq, *xkm, *kvm, *S, *ou, *proj;
    uint32_t* rmaxu;
    u64 *keyq, *keyk;
    int *permq, *permk, *dstq, *dstk, *cntq, *cntk, *aq, *bq, *ak, *bk, *ctok;
    bf16 *x3, *bt3, *mq1, *mk1, *xq2, *xkm2, *wq2, *wkv2, *wp2, *qp2, *kp2, *vp2, *ao2;
    cudaGetSymbolAddress((void**)&xk, g_xk);
    cudaGetSymbolAddress((void**)&mnq, g_mnq);
    cudaGetSymbolAddress((void**)&mnk, g_mnk);
    cudaGetSymbolAddress((void**)&nvq, g_nvq);
    cudaGetSymbolAddress((void**)&nvk, g_nvk);
    cudaGetSymbolAddress((void**)&rmaxu, g_rmaxu);
    cudaGetSymbolAddress((void**)&xq, g_xq);
    cudaGetSymbolAddress((void**)&xkm, g_xkm);
    cudaGetSymbolAddress((void**)&kvm, g_kvm);
    cudaGetSymbolAddress((void**)&S, g_S);
    cudaGetSymbolAddress((void**)&ou, g_ou);
    cudaGetSymbolAddress((void**)&proj, g_proj);
    cudaGetSymbolAddress((void**)&keyq, g_keyq);
    cudaGetSymbolAddress((void**)&keyk, g_keyk);
    cudaGetSymbolAddress((void**)&permq, g_permq);
    cudaGetSymbolAddress((void**)&permk, g_permk);
    cudaGetSymbolAddress((void**)&dstq, g_dstq);
    cudaGetSymbolAddress((void**)&dstk, g_dstk);
    cudaGetSymbolAddress((void**)&cntq, g_cntq);
    cudaGetSymbolAddress((void**)&cntk, g_cntk);
    cudaGetSymbolAddress((void**)&aq, g_aq);
    cudaGetSymbolAddress((void**)&bq, g_bq);
    cudaGetSymbolAddress((void**)&ak, g_ak);
    cudaGetSymbolAddress((void**)&bk, g_bk);
    cudaGetSymbolAddress((void**)&ctok, g_ctok);
    cudaGetSymbolAddress((void**)&x3, g_x3);
    cudaGetSymbolAddress((void**)&bt3, g_bt3);
    cudaGetSymbolAddress((void**)&mq1, g_mq1);
    cudaGetSymbolAddress((void**)&mk1, g_mk1);
    cudaGetSymbolAddress((void**)&xq2, g_xq2);
    cudaGetSymbolAddress((void**)&xkm2, g_xkm2);
    cudaGetSymbolAddress((void**)&wq2, g_wq2);
    cudaGetSymbolAddress((void**)&wkv2, g_wkv2);
    cudaGetSymbolAddress((void**)&wp2, g_wp2);
    cudaGetSymbolAddress((void**)&qp2, g_qp2);
    cudaGetSymbolAddress((void**)&kp2, g_kp2);
    cudaGetSymbolAddress((void**)&vp2, g_vp2);
    cudaGetSymbolAddress((void**)&ao2, g_ao2);

    const long PXQ = (long)NQ * CC;
    const long PBT = (long)8 * CC * CC;
    const long PQ2 = (long)MQ * CC;
    const long PK2 = (long)MK * CC;
    const long PWQ = (long)CC * CC;
    const long PWKV = (long)2 * CC * CC;
    const long PQP = (long)HEADS * MQ * HD;
    const long PKP = (long)HEADS * MK * HD;
    const long PVP = (long)HEADS * VN * MK;
    float* Skv = S + (long)NAQ * NDQ;

    // 1-3: conv prerequisites
    split3_kernel<<<(int)((PXQ + 255) / 256), 256>>>(x, x3, x3 + PXQ, x3 + 2 * PXQ, PXQ);
    split3_bt_kernel<<<(int)((PBT + 255) / 256), 256>>>(srw, bt3, bt3 + PBT, bt3 + 2 * PBT);
    conv_tok_kernel<<<(8 * N2 + 255) / 256, 256>>>(ctok);
    // 4: conv GEMM (profiled slot)
    mmg<6, 64, 2, 0, false><<<dim3(CC / 64, N2 / 64, 1), 512, SM_6_64_2>>>(
        x3, x3 + PXQ, x3 + 2 * PXQ, CC, 0,
        bt3, bt3 + PBT, bt3 + 2 * PBT, CC, 0, (long)CC * CC,
        xk, CC, 0, srb, 1.f, nullptr, nullptr, 0, nullptr,
        CC, CC, 8, ctok, N2, nullptr);
    // 5: fused LN + rownorm + cvt
    ln_norm_kernel<<<N2, 256>>>(xk, lng, lnb, mnk, mk1);
    build_idx_kernel<<<(NQ + 255) / 256, 256>>>(D0, H0, W0, aq, bq);
    build_idx_kernel<<<(N2 + 255) / 256, 256>>>(D0 / 2, H0 / 2, W0 / 2, ak, bk);

    // ---- q-side BSM ----
    rownorm_cvt_kernel<<<NQ, 256>>>(x, mnq, mq1);
    set_u32_kernel<<<(NAQ + 255) / 256, 256>>>(rmaxu, NAQ, 0u);
    mmg<1, 128, 3, 1, false><<<dim3(NDQ / 128, NAQ / 64, 1), 512, SM_1_128_3>>>(
        mq1, nullptr, nullptr, CC, 0,
        mq1, nullptr, nullptr, CC, 0, 0,
        S, NDQ, 0, nullptr, 1.f, nullptr, nullptr, 0, rmaxu,
        NDQ, CC, 1, aq, 0, bq);
    refine_kernel<<<NAQ / 8, 256>>>(S, NDQ, mnq, aq, bq, rmaxu, keyq, 2e-3f);
    unpack_val_kernel<<<(NAQ + 255) / 256, 256>>>(keyq, nvq, NAQ);
    rank_kernel<<<NAQ / 256, 256>>>(nvq, permq, NAQ);
    set_int_kernel<<<(NDQ + 255) / 256, 256>>>(cntq, NDQ, 1);
    fill_dst_kernel<<<(RQ + 255) / 256, 256>>>(permq, keyq, dstq, cntq, RQ);
    merge_gather_kernel<<<MQ, 256>>>(x, xq, aq, bq, permq, UQ, RQ);
    scatter_add_kernel<<<RQ, 256>>>(x, xq, aq, permq, dstq, UQ);
    div_cnt_kernel<<<NDQ, 256>>>(xq, cntq, UQ);

    // ---- kv-side BSM ----
    set_u32_kernel<<<(NAK + 255) / 256, 256>>>(rmaxu, NAK, 0u);
    mmg<1, 64, 3, 1, false><<<dim3(NDK / 64, NAK / 64, 1), 512, SM_1_64_3>>>(
        mk1, nullptr, nullptr, CC, 0,
        mk1, nullptr, nullptr, CC, 0, 0,
        Skv, NDK, 0, nullptr, 1.f, nullptr, nullptr, 0, rmaxu,
        NDK, CC, 1, ak, 0, bk);
    refine_kernel<<<NAK / 8, 256>>>(Skv, NDK, mnk, ak, bk, rmaxu, keyk, 2e-3f);
    unpack_val_kernel<<<(NAK + 255) / 256, 256>>>(keyk, nvk, NAK);
    rank_kernel<<<NAK / 256, 256>>>(nvk, permk, NAK);
    set_int_kernel<<<1, 256>>>(cntk, NDK, 1);
    fill_dst_kernel<<<(RK + 255) / 256, 256>>>(permk, keyk, dstk, cntk, RK);
    merge_gather_kernel<<<MK, 256>>>(xk, xkm, ak, bk, permk, UK, RK);
    scatter_add_kernel<<<RK, 256>>>(xk, xkm, ak, permk, dstk, UK);
    div_cnt_kernel<<<NDK, 256>>>(xkm, cntk, UK);

    // ---- projections ----
    split2_kernel<<<(int)((PWQ + 255) / 256), 256>>>(Wq, wq2, wq2 + PWQ, PWQ);
    split2_kernel<<<(int)((PWKV + 255) / 256), 256>>>(Wkv, wkv2, wkv2 + PWKV, PWKV);
    split2_kernel<<<(int)((PWQ + 255) / 256), 256>>>(Wp, wp2, wp2 + PWQ, PWQ);
    split2_kernel<<<(int)((PQ2 + 255) / 256), 256>>>(xq, xq2, xq2 + PQ2, PQ2);
    split2_kernel<<<(int)((PK2 + 255) / 256), 256>>>(xkm, xkm2, xkm2 + PK2, PK2);
    // Wq -> head-major bf16 Q planes directly (EPI2)
    mmg<3, 64, 3, 2, false><<<dim3(CC / 64, MQ / 64, 1), 512, SM_3_64_3>>>(
        xq2, xq2 + PQ2, nullptr, CC, 0,
        wq2, wq2 + PWQ, nullptr, CC, 0, 0,
        nullptr, 0, 0, nullptr, 1.f, qp2, qp2 + PQP, (long)MQ * HD, nullptr,
        CC, CC, 1, nullptr, 0, nullptr);
    mmg<3, 64, 3, 0, false><<<dim3(2 * CC / 64, MK / 64, 1), 512, SM_3_64_3>>>(
        xkm2, xkm2 + PK2, nullptr, CC, 0,
        wkv2, wkv2 + PWKV, nullptr, CC, 0, 0,
        kvm, 2 * CC, 0, nullptr, 1.f, nullptr, nullptr, 0, nullptr,
        2 * CC, CC, 1, nullptr, 0, nullptr);

    // ---- head prep ----
    split_kpad_kernel<<<(int)((PKP + 255) / 256), 256>>>(kvm, kp2, kp2 + PKP);
    split_vT_kernel<<<(int)((PVP + 255) / 256), 256>>>(kvm, vp2, vp2 + PVP);

    // ---- attention: QK (K=96, TK) with fused per-(head,row) rowmax ----
    float scl = 1.0f / sqrtf((float)HD);
    set_u32_kernel<<<(HEADS * MQ + 255) / 256, 256>>>(rmaxu, HEADS * MQ, 0u);
    mmg<3, 64, 3, 1, true><<<dim3(MK / 64, MQ / 64, HEADS), 512, SM_3_64_3>>>(
        qp2, qp2 + PQP, nullptr, HD, (long)MQ * HD,
        kp2, kp2 + PKP, nullptr, HD, (long)MK * HD, 0,
        S, MK, (long)MQ * MK, nullptr, scl, nullptr, nullptr, MQ, rmaxu,
        MK, HD, 1, nullptr, 0, nullptr);
    // ---- AV with inline exp(S - rmax): A = fp32 S, B = V planes (+ones row) ----
    mmg<3, 64, 3, 0, false, true><<<dim3(2, MQ / 64, HEADS), 512, SM_3_64_3>>>(
        (const bf16*)S, nullptr, nullptr, MK, (long)MQ * MK,
        vp2, vp2 + PVP, nullptr, MK, (long)VN * MK, 0,
        ou, OLD, (long)MQ * OLD, nullptr, 1.f, nullptr, nullptr, MQ, rmaxu,
        VN, MK, 1, nullptr, 0, nullptr);
    // ---- normalize + split to ao2 planes ----
    normalize_kernel<<<MQ, 256>>>(ou, ao2, ao2 + PQ2);

    // ---- output projection + unmerge ----
    mmg<3, 64, 3, 0, false><<<dim3(CC / 64, MQ / 64, 1), 512, SM_3_64_3>>>(
        ao2, ao2 + PQ2, nullptr, CC, 0,
        wp2, wp2 + PWQ, nullptr, CC, 0, 0,
        proj, CC, 0, bp, 1.f, nullptr, nullptr, 0, nullptr,
        CC, CC, 1, nullptr, 0, nullptr);
    unmerge_kernel<<<NQ, 256>>>(proj, out, aq, bq, permq, dstq);
}

// round 16
// speedup vs baseline: 1.1075x; 1.0260x over previous
#include <cuda_runtime.h>
#include <cuda_bf16.h>
#include <math.h>
#include <stdint.h>

// ---------------- static problem sizes ----------------
#define CC    768
#define D0    16
#define H0    32
#define W0    32
#define NQ    16384
#define NDQ   2048
#define NAQ   14336
#define RQ    8192
#define UQ    6144
#define MQ    8192
#define N2    2048
#define NDK   256
#define NAK   1792
#define RK    1024
#define UK    768
#define MK    1024
#define HEADS 8
#define HD    96
#define VN    97            // V rows incl. ones row
#define OLD   104           // padded ldc for O_unnorm

typedef __nv_bfloat16 bf16;
typedef unsigned long long u64;

// ---------------- device scratch ----------------
__device__ float g_xk[N2 * CC];
__device__ float g_mnq[NQ * CC];
__device__ float g_mnk[N2 * CC];
__device__ u64   g_keyq[NAQ];
__device__ u64   g_keyk[NAK];
__device__ uint32_t g_rmaxu[HEADS * MQ];
__device__ int g_permq[NAQ];
__device__ int g_permk[NAK];
__device__ int g_dstq[RQ];
__device__ int g_dstk[RK];
__device__ int g_cntq[NDQ];
__device__ int g_cntk[NDK];
__device__ int g_aq[NAQ];
__device__ int g_bq[NDQ];
__device__ int g_ak[NAK];
__device__ int g_bk[NDK];
__device__ int g_ctok[8 * N2];
__device__ float g_xq[MQ * CC];
__device__ float g_xkm[MK * CC];
__device__ float g_kvm[MK * 2 * CC];
__device__ float g_S[(long)HEADS * MQ * MK];
__device__ float g_ou[(long)HEADS * MQ * OLD];
__device__ float g_proj[MQ * CC];

// bf16 planes
__device__ bf16 g_x3[3][NQ * CC];
__device__ bf16 g_bt3[3][8 * CC * CC];
__device__ bf16 g_mq1[NQ * CC];
__device__ bf16 g_mk1[N2 * CC];
__device__ bf16 g_xq2[2][MQ * CC];
__device__ bf16 g_xkm2[2][MK * CC];
__device__ bf16 g_wq2[2][CC * CC];
__device__ bf16 g_wkv2[2][2 * CC * CC];
__device__ bf16 g_wp2[2][CC * CC];
__device__ bf16 g_qp2[2][HEADS * MQ * HD];
__device__ bf16 g_kp2[2][HEADS * MK * HD];
__device__ bf16 g_vp2[2][HEADS * VN * MK];
__device__ bf16 g_ao2[2][MQ * CC];

__device__ __forceinline__ uint32_t smem_u32(const void* p) {
    uint32_t a;
    asm("{ .reg .u64 t; cvta.to.shared.u64 t, %1; cvt.u32.u64 %0, t; }" : "=r"(a) : "l"(p));
    return a;
}
__device__ __forceinline__ uint32_t pkbf(bf16 a, bf16 b) {
    return (uint32_t)__bfloat16_as_ushort(a) | ((uint32_t)__bfloat16_as_ushort(b) << 16);
}
__device__ __forceinline__ uint32_t encf(float f) {
    uint32_t u = __float_as_uint(f);
    return (u & 0x80000000u) ? ~u : (u | 0x80000000u);
}
__device__ __forceinline__ float decf(uint32_t o) {
    uint32_t u = (o & 0x80000000u) ? (o ^ 0x80000000u) : ~o;
    return __uint_as_float(u);
}
__device__ __forceinline__ void wr_split(bf16* p0, bf16* p1, long idx, float v) {
    bf16 h = __float2bfloat16(v);
    p0[idx] = h;
    p1[idx] = __float2bfloat16(v - __bfloat162float(h));
}
#define SWZ(o) ((o) ^ (((o) >> 3) & 0x70))
#define MMA16816(d, a, b0v, b1v) \
    asm volatile("mma.sync.aligned.m16n8k16.row.col.f32.bf16.bf16.f32 " \
        "{%0,%1,%2,%3}, {%4,%5,%6,%7}, {%8,%9}, {%0,%1,%2,%3};" \
        : "+f"((d)[0]), "+f"((d)[1]), "+f"((d)[2]), "+f"((d)[3]) \
        : "r"((a)[0]), "r"((a)[1]), "r"((a)[2]), "r"((a)[3]), "r"(b0v), "r"(b1v))
#define LDSM4(r, a) \
    asm volatile("ldmatrix.sync.aligned.m8n8.x4.shared.b16 {%0,%1,%2,%3}, [%4];" \
        : "=r"((r)[0]), "=r"((r)[1]), "=r"((r)[2]), "=r"((r)[3]) : "r"(a))
#define CPA(dst, src, sz) \
    asm volatile("cp.async.cg.shared.global [%0], [%1], 16, %2;" :: "r"(dst), "l"(src), "r"(sz) : "memory")
#define CPCOMMIT() asm volatile("cp.async.commit_group;" ::: "memory")
#define CPWAIT1()  asm volatile("cp.async.wait_group 1;" ::: "memory")

// ---------------- pipelined ldmatrix mma.sync split-bf16 GEMM ----------------
// (unchanged from R15: TK tail flag, AEXP softmax-A path, EPI variants)
template <int NPR, int TN, int STAGES, int EPI, bool TK, bool AEXP = false>
__global__ void __launch_bounds__(512, 2) mmg(
    const bf16* A0, const bf16* A1, const bf16* A2, long lda, long ahs,
    const bf16* B0, const bf16* B1, const bf16* B2, long ldb, long bhs, long bseg,
    float* C, long ldc, long chs, const float* bias, float scale,
    bf16* P0, bf16* P1, long phs, uint32_t* rmaxu,
    int N, int K, int ntap, const int* gA, int gAs, const int* gB)
{
    constexpr int nA = (NPR == 6) ? 3 : (NPR == 3) ? 2 : 1;
    constexpr int nB = nA;
    constexpr int PLA = 8192;          // 64 rows x 128 B
    constexpr int PLB = TN * 128;
    constexpr int STG = nA * PLA + nB * PLB;
    constexpr int NJ = TN / 32;
    extern __shared__ char sm[];
    const uint32_t su = smem_u32(sm);

    const int tid = threadIdx.x, lane = tid & 31, wid = tid >> 5;
    const int wm = wid >> 2, wn = wid & 3;
    const int m0 = blockIdx.y * 64, n0 = blockIdx.x * TN, z = blockIdx.z;
    const int lq = lane >> 2, lr = lane & 3;

    const int lrA = tid >> 3, secA = tid & 7;
    const int lrB = (TN == 128) ? (tid >> 2) : (tid >> 3);
    const int secB = (TN == 128) ? (tid & 3) : (tid & 7);
    const int nrow = n0 + lrB;
    const bool bval = nrow < N;
    const long brow = bval ? (gB ? (long)gB[nrow] : (long)nrow) : 0;
    const uint32_t bsz = bval ? 16u : 0u;

    const uint32_t dA0 = SWZ((uint32_t)(lrA * 128 + secA * 16));
    const uint32_t dB0 = (TN == 128) ? SWZ((uint32_t)(lrB * 128 + secB * 32))
                                     : SWZ((uint32_t)(lrB * 128 + secB * 16));
    const uint32_t dB1 = (TN == 128) ? SWZ((uint32_t)(lrB * 128 + secB * 32 + 16)) : 0u;

    const int kcd = (K + 63) >> 6;
    const int nch = ntap * kcd;
    const bf16* Ap[3] = {A0, A1, A2};
    const bf16* Bp[3] = {B0, B1, B2};

    float acc[NJ][4];
#pragma unroll
    for (int j = 0; j < NJ; j++)
#pragma unroll
        for (int t = 0; t < 4; t++) acc[j][t] = 0.f;

    auto issue = [&](int c) {
        const int stg = c % STAGES;
        const uint32_t sb = su + stg * STG;
        const int tap = c / kcd;
        const int k0 = (c - tap * kcd) << 6;
        if constexpr (AEXP) {
            const long arow = m0 + lrA;
            const float rm = decf(rmaxu[(long)z * phs + arow]);
            const float* Af = reinterpret_cast<const float*>(A0)
                              + (long)z * ahs + arow * lda + k0 + secA * 8;
            float4 va = *(const float4*)(Af);
            float4 vb = *(const float4*)(Af + 4);
            float e0 = __expf(va.x - rm), e1 = __expf(va.y - rm);
            float e2 = __expf(va.z - rm), e3 = __expf(va.w - rm);
            float e4 = __expf(vb.x - rm), e5 = __expf(vb.y - rm);
            float e6 = __expf(vb.z - rm), e7 = __expf(vb.w - rm);
            bf16 h0 = __float2bfloat16(e0), h1 = __float2bfloat16(e1);
            bf16 h2 = __float2bfloat16(e2), h3 = __float2bfloat16(e3);
            bf16 h4 = __float2bfloat16(e4), h5 = __float2bfloat16(e5);
            bf16 h6 = __float2bfloat16(e6), h7 = __float2bfloat16(e7);
            uint4 hv = make_uint4(pkbf(h0, h1), pkbf(h2, h3), pkbf(h4, h5), pkbf(h6, h7));
            uint4 lv = make_uint4(
                pkbf(__float2bfloat16(e0 - __bfloat162float(h0)), __float2bfloat16(e1 - __bfloat162float(h1))),
                pkbf(__float2bfloat16(e2 - __bfloat162float(h2)), __float2bfloat16(e3 - __bfloat162float(h3))),
                pkbf(__float2bfloat16(e4 - __bfloat162float(h4)), __float2bfloat16(e5 - __bfloat162float(h5))),
                pkbf(__float2bfloat16(e6 - __bfloat162float(h6)), __float2bfloat16(e7 - __bfloat162float(h7))));
            *(uint4*)(sm + stg * STG + dA0) = hv;
            *(uint4*)(sm + stg * STG + PLA + dA0) = lv;
        } else if constexpr (!TK) {
            const long arow = gA ? (long)gA[tap * gAs + m0 + lrA] : (long)(m0 + lrA);
#pragma unroll
            for (int p = 0; p < nA; p++) {
                const bf16* s0 = Ap[p] + (long)z * ahs + arow * lda + k0 + secA * 8;
                CPA(sb + p * PLA + dA0, s0, 16u);
            }
        } else {
            const long arow = gA ? (long)gA[tap * gAs + m0 + lrA] : (long)(m0 + lrA);
            const uint32_t szA = (k0 + secA * 8 < K) ? 16u : 0u;
            const int kaA = szA ? (k0 + secA * 8) : 0;
#pragma unroll
            for (int p = 0; p < nA; p++) {
                const bf16* s0 = Ap[p] + (long)z * ahs + arow * lda + kaA;
                CPA(sb + p * PLA + dA0, s0, szA);
            }
        }
        if constexpr (!TK) {
#pragma unroll
            for (int p = 0; p < nB; p++) {
                const bf16* s0 = Bp[p] + (long)z * bhs + (long)tap * bseg + brow * ldb + k0
                               + secB * (TN == 128 ? 16 : 8);
                CPA(sb + nA * PLA + p * PLB + dB0, s0, bsz);
                if (TN == 128) CPA(sb + nA * PLA + p * PLB + dB1, s0 + 8, bsz);
            }
        } else {
            if (TN == 128) {
                const uint32_t sz0 = (k0 + secB * 16 < K) ? bsz : 0u;
                const uint32_t sz1 = (k0 + secB * 16 + 8 < K) ? bsz : 0u;
                const int kb0 = sz0 ? (k0 + secB * 16) : 0;
                const int kb1 = sz1 ? (k0 + secB * 16 + 8) : 0;
#pragma unroll
                for (int p = 0; p < nB; p++) {
                    const bf16* s0 = Bp[p] + (long)z * bhs + (long)tap * bseg + brow * ldb;
                    CPA(sb + nA * PLA + p * PLB + dB0, s0 + kb0, sz0);
                    CPA(sb + nA * PLA + p * PLB + dB1, s0 + kb1, sz1);
                }
            } else {
                const uint32_t sz0 = (k0 + secB * 8 < K) ? bsz : 0u;
                const int kb0 = sz0 ? (k0 + secB * 8) : 0;
#pragma unroll
                for (int p = 0; p < nB; p++) {
                    const bf16* s0 = Bp[p] + (long)z * bhs + (long)tap * bseg + brow * ldb;
                    CPA(sb + nA * PLA + p * PLB + dB0, s0 + kb0, sz0);
                }
            }
        }
        CPCOMMIT();
    };

    auto compute = [&](int stg, int kslim) {
        const uint32_t sb = su + stg * STG;
        const int pa6[6] = {0, 0, 1, 1, 0, 2}, pb6[6] = {0, 1, 0, 1, 2, 0};
#pragma unroll
        for (int ks = 0; ks < 4; ks++) {
            if constexpr (TK) { if (ks >= kslim) break; }
            uint32_t af[nA][4];
#pragma unroll
            for (int p = 0; p < nA; p++) {
                uint32_t off = (uint32_t)((wm * 16 + (lane & 15)) * 128
                                          + ks * 32 + ((lane >> 4) << 4));
                LDSM4(af[p], sb + p * PLA + SWZ(off));
            }
            uint32_t bl[nB][NJ], bh[nB][NJ];
            if constexpr (TN == 128) {
#pragma unroll
                for (int p = 0; p < nB; p++) {
                    uint32_t r0[4], r1[4];
                    uint32_t off0 = (uint32_t)((wn * 32 + (lane >> 3) * 8 + (lane & 7)) * 128 + ks * 32);
                    LDSM4(r0, sb + nA * PLA + p * PLB + SWZ(off0));
                    LDSM4(r1, sb + nA * PLA + p * PLB + SWZ(off0 + 16));
#pragma unroll
                    for (int j = 0; j < 4; j++) { bl[p][j] = r0[j]; bh[p][j] = r1[j]; }
                }
            } else {
#pragma unroll
                for (int p = 0; p < nB; p++) {
                    uint32_t r[4];
                    const int tileB = (lane >> 3) & 1, khB = lane >> 4;
                    uint32_t off = (uint32_t)((wn * 16 + tileB * 8 + (lane & 7)) * 128
                                              + ks * 32 + khB * 16);
                    LDSM4(r, sb + nA * PLA + p * PLB + SWZ(off));
                    bl[p][0] = r[0]; bl[p][1] = r[1]; bh[p][0] = r[2]; bh[p][1] = r[3];
                }
            }
#pragma unroll
            for (int pr = 0; pr < NPR; pr++) {
                const int pA = (NPR == 1) ? 0 : pa6[pr];
                const int pB = (NPR == 1) ? 0 : pb6[pr];
#pragma unroll
                for (int j = 0; j < NJ; j++)
                    MMA16816(acc[j], af[pA], bl[pB][j], bh[pB][j]);
            }
        }
    };

    issue(0);
    for (int c = 0; c < nch; c++) {
        if (c + 1 < nch) issue(c + 1);
        else CPCOMMIT();
        CPWAIT1();
        __syncthreads();
        if constexpr (TK) {
            const int k0c = (c % kcd) << 6;
            int kslim = (K - k0c + 15) >> 4; if (kslim > 4) kslim = 4;
            compute(c % STAGES, kslim);
        } else {
            compute(c % STAGES, 4);
        }
        if (STAGES == 2) __syncthreads();
    }

    // ---- epilogue ----
    const int r = m0 + wm * 16 + lq;
    if constexpr (EPI == 0 || EPI == 1) {
        float mx0 = -3.4e38f, mx1 = -3.4e38f;
#pragma unroll
        for (int j = 0; j < NJ; j++) {
            const int cb = n0 + wn * (TN / 4) + j * 8 + lr * 2;
            if (cb < N) {
                float bb0 = bias ? bias[cb] : 0.f;
                float bb1 = bias ? bias[cb + 1] : 0.f;
                float v0 = acc[j][0] * scale + bb0, v1 = acc[j][1] * scale + bb1;
                float v2 = acc[j][2] * scale + bb0, v3 = acc[j][3] * scale + bb1;
                float* p0 = C + (long)z * chs + (long)r * ldc + cb;
                float* p1 = C + (long)z * chs + (long)(r + 8) * ldc + cb;
                p0[0] = v0; p0[1] = v1; p1[0] = v2; p1[1] = v3;
                if (EPI == 1) {
                    mx0 = fmaxf(mx0, fmaxf(v0, v1));
                    mx1 = fmaxf(mx1, fmaxf(v2, v3));
                }
            }
        }
        if constexpr (EPI == 1) {
            mx0 = fmaxf(mx0, __shfl_xor_sync(0xffffffffu, mx0, 1));
            mx0 = fmaxf(mx0, __shfl_xor_sync(0xffffffffu, mx0, 2));
            mx1 = fmaxf(mx1, __shfl_xor_sync(0xffffffffu, mx1, 1));
            mx1 = fmaxf(mx1, __shfl_xor_sync(0xffffffffu, mx1, 2));
            if (lr == 0) {
                atomicMax(&rmaxu[(long)z * phs + r], encf(mx0));
                atomicMax(&rmaxu[(long)z * phs + r + 8], encf(mx1));
            }
        }
    } else if constexpr (EPI == 2) {
#pragma unroll
        for (int j = 0; j < NJ; j++) {
            const int cb = n0 + wn * (TN / 4) + j * 8 + lr * 2;
            if (cb < N) {
                int h = cb / HD, k = cb - h * HD;
                float v0 = acc[j][0] * scale, v1 = acc[j][1] * scale;
                float v2 = acc[j][2] * scale, v3 = acc[j][3] * scale;
                wr_split(P0 + (long)h * phs, P1 + (long)h * phs, (long)r * HD + k, v0);
                wr_split(P0 + (long)h * phs, P1 + (long)h * phs, (long)r * HD + k + 1, v1);
                wr_split(P0 + (long)h * phs, P1 + (long)h * phs, (long)(r + 8) * HD + k, v2);
                wr_split(P0 + (long)h * phs, P1 + (long)h * phs, (long)(r + 8) * HD + k + 1, v3);
            }
        }
    } else {   // EPI == 3
#pragma unroll
        for (int j = 0; j < NJ; j++) {
            const int cb = n0 + wn * (TN / 4) + j * 8 + lr * 2;
            if (cb < N) {
                float v0 = acc[j][0] * scale, v1 = acc[j][1] * scale;
                float v2 = acc[j][2] * scale, v3 = acc[j][3] * scale;
                long o0 = (long)z * chs + (long)r * ldc + cb;
                long o1 = (long)z * chs + (long)(r + 8) * ldc + cb;
                wr_split(P0, P1, o0, v0);
                wr_split(P0, P1, o0 + 1, v1);
                wr_split(P0, P1, o1, v2);
                wr_split(P0, P1, o1 + 1, v3);
            }
        }
    }
}

// ---------------- utility / prep kernels ----------------
__global__ void set_int_kernel(int* p, int n, int v) {
    int i = blockIdx.x * 256 + threadIdx.x;
    if (i < n) p[i] = v;
}
__global__ void set_u32_kernel(uint32_t* p, int n, uint32_t v) {
    int i = blockIdx.x * 256 + threadIdx.x;
    if (i < n) p[i] = v;
}
__global__ void build_idx_kernel(int D, int H, int W, int* a_idx, int* b_idx) {
    int n = D * H * W;
    int t = blockIdx.x * 256 + threadIdx.x;
    if (t >= n) return;
    int z = t / (H * W), y = (t / W) % H, xx = t % W;
    int hw2 = (H >> 1) * (W >> 1);
    if (((z | y | xx) & 1) == 0) {
        b_idx[(z >> 1) * hw2 + (y >> 1) * (W >> 1) + (xx >> 1)] = t;
    } else {
        int cez = (z + 1) >> 1, cey = (y + 1) >> 1, cex = (xx + 1) >> 1;
        int before = cez * hw2;
        if ((z & 1) == 0) { before += cey * (W >> 1); if ((y & 1) == 0) before += cex; }
        a_idx[t - before] = t;
    }
}
__global__ void conv_tok_kernel(int* t) {
    int i = blockIdx.x * 256 + threadIdx.x;
    if (i >= 8 * N2) return;
    int tap = i >> 11, m = i & 2047;
    int kz = tap >> 2, ky = (tap >> 1) & 1, kx = tap & 1;
    int z2 = m >> 8, y2 = (m >> 4) & 15, x2 = m & 15;
    t[i] = (2 * z2 + kz) * (H0 * W0) + (2 * y2 + ky) * W0 + (2 * x2 + kx);
}
__device__ __forceinline__ void split3_elem(float v, bf16* p0, bf16* p1, bf16* p2, long i) {
    bf16 h = __float2bfloat16(v); float r = v - __bfloat162float(h);
    bf16 m = __float2bfloat16(r); float r2 = r - __bfloat162float(m);
    p0[i] = h; p1[i] = m; p2[i] = __float2bfloat16(r2);
}
// fused: split3(x) + L2-rownorm -> mnq fp32 + mq1 bf16
__global__ void __launch_bounds__(256) prep_x_kernel(const float* __restrict__ x,
    bf16* p0, bf16* p1, bf16* p2, float* __restrict__ mnq, bf16* __restrict__ mq1)
{
    int row = blockIdx.x;
    const float* p = x + (long)row * CC;
    __shared__ float red[256];
    int tid = threadIdx.x;
    float v0 = p[tid], v1 = p[tid + 256], v2 = p[tid + 512];
    long b = (long)row * CC;
    split3_elem(v0, p0, p1, p2, b + tid);
    split3_elem(v1, p0, p1, p2, b + tid + 256);
    split3_elem(v2, p0, p1, p2, b + tid + 512);
    red[tid] = v0 * v0 + v1 * v1 + v2 * v2; __syncthreads();
    for (int off = 128; off; off >>= 1) { if (tid < off) red[tid] += red[tid + off]; __syncthreads(); }
    float inv = (float)(1.0 / sqrt((double)red[0]));
    float n0 = v0 * inv, n1 = v1 * inv, n2 = v2 * inv;
    mnq[b + tid] = n0; mnq[b + tid + 256] = n1; mnq[b + tid + 512] = n2;
    mq1[b + tid] = __float2bfloat16(n0);
    mq1[b + tid + 256] = __float2bfloat16(n1);
    mq1[b + tid + 512] = __float2bfloat16(n2);
}
__global__ void split2_kernel(const float* __restrict__ s, bf16* p0, bf16* p1, long n) {
    long i = (long)blockIdx.x * 256 + threadIdx.x;
    if (i >= n) return;
    wr_split(p0, p1, i, s[i]);
}
__global__ void split3_bt_kernel(const float* __restrict__ w, bf16* p0, bf16* p1, bf16* p2) {
    long i = (long)blockIdx.x * 256 + threadIdx.x;
    if (i >= (long)8 * CC * CC) return;
    int tap = (int)(i / (CC * CC));
    int rem = (int)(i - (long)tap * CC * CC);
    int n = rem / CC, k = rem - n * CC;
    split3_elem(w[(long)n * (CC * 8) + k * 8 + tap], p0, p1, p2, i);
}
// kvm k-part -> [8][MK][96] hi/lo
__global__ void split_kpad_kernel(const float* __restrict__ kvm, bf16* p0, bf16* p1) {
    long i = (long)blockIdx.x * 256 + threadIdx.x;
    if (i >= (long)HEADS * MK * HD) return;
    int h = (int)(i / (MK * HD));
    int rem = (int)(i - (long)h * MK * HD);
    int m = rem / HD, k = rem - m * HD;
    wr_split(p0, p1, i, kvm[(long)m * (2 * CC) + h * HD + k]);
}
// kvm v-part transposed -> [8][97][MK] hi/lo (row 96 = ones for row-sum)
__global__ void split_vT_kernel(const float* __restrict__ kvm, bf16* p0, bf16* p1) {
    long i = (long)blockIdx.x * 256 + threadIdx.x;
    if (i >= (long)HEADS * VN * MK) return;
    int h = (int)(i / (VN * MK));
    int rem = (int)(i - (long)h * VN * MK);
    int n = rem >> 10, k = rem & (MK - 1);
    float v = (n < HD) ? kvm[(long)k * (2 * CC) + CC + h * HD + n] : 1.0f;
    wr_split(p0, p1, i, v);
}

// ---------------- fused LN -> xk, mnk, mk1 ----------------
__global__ void __launch_bounds__(256) ln_norm_kernel(float* __restrict__ xk,
    const float* __restrict__ g, const float* __restrict__ b,
    float* __restrict__ mnk, bf16* __restrict__ mk1)
{
    int row = blockIdx.x;
    float* p = xk + (long)row * CC;
    __shared__ float red[256];
    int tid = threadIdx.x;
    float v0 = p[tid], v1 = p[tid + 256], v2 = p[tid + 512];
    red[tid] = v0 + v1 + v2; __syncthreads();
    for (int off = 128; off; off >>= 1) { if (tid < off) red[tid] += red[tid + off]; __syncthreads(); }
    float mean = red[0] / (float)CC;
    __syncthreads();
    float d0 = v0 - mean, d1 = v1 - mean, d2 = v2 - mean;
    red[tid] = d0 * d0 + d1 * d1 + d2 * d2; __syncthreads();
    for (int off = 128; off; off >>= 1) { if (tid < off) red[tid] += red[tid + off]; __syncthreads(); }
    float var = red[0] / (float)CC;
    float inv = (float)(1.0 / sqrt((double)var + 1e-5));
    __syncthreads();
    float y0 = d0 * inv * g[tid] + b[tid];
    float y1 = d1 * inv * g[tid + 256] + b[tid + 256];
    float y2 = d2 * inv * g[tid + 512] + b[tid + 512];
    p[tid] = y0; p[tid + 256] = y1; p[tid + 512] = y2;
    red[tid] = y0 * y0 + y1 * y1 + y2 * y2; __syncthreads();
    for (int off = 128; off; off >>= 1) { if (tid < off) red[tid] += red[tid + off]; __syncthreads(); }
    float nrm = (float)(1.0 / sqrt((double)red[0]));
    float* q = mnk + (long)row * CC;
    bf16* q1 = mk1 + (long)row * CC;
    float n0 = y0 * nrm, n1 = y1 * nrm, n2 = y2 * nrm;
    q[tid] = n0; q[tid + 256] = n1; q[tid + 512] = n2;
    q1[tid] = __float2bfloat16(n0); q1[tid + 256] = __float2bfloat16(n1); q1[tid + 512] = __float2bfloat16(n2);
}

// ---------------- refine (candidates from fused rowmax) ----------------
__global__ void __launch_bounds__(256) refine_kernel(
    const float* __restrict__ S, int ncol, const float* __restrict__ mn,
    const int* __restrict__ a_idx, const int* __restrict__ b_idx,
    const uint32_t* __restrict__ rmaxu, u64* __restrict__ key, float margin)
{
    int row = blockIdx.x * 8 + (threadIdx.x >> 5);
    int lane = threadIdx.x & 31;
    const float* p = S + (long)row * ncol;
    float thr = decf(rmaxu[row]) - margin;
    const float* av = mn + (long)a_idx[row] * CC;
    float bestv = -3.4e38f;
    int bestd = 0;
    for (int base = 0; base < ncol; base += 32) {
        float s = p[base + lane];
        unsigned m = __ballot_sync(0xffffffffu, s >= thr);
        while (m) {
            int b = __ffs(m) - 1;
            m &= m - 1;
            int dst = base + b;
            const float* bv = mn + (long)b_idx[dst] * CC;
            float part = 0.f;
            for (int c = lane; c < CC; c += 32) part += av[c] * bv[c];
            for (int off = 16; off; off >>= 1) part += __shfl_xor_sync(0xffffffffu, part, off);
            if (part > bestv) { bestv = part; bestd = dst; }
        }
    }
    if (lane == 0) {
        key[row] = ((u64)encf(bestv) << 32) | (unsigned)(~bestd);
    }
}

// ---------------- BSM index machinery ----------------
// stable descending rank; values decoded inline from keys
__global__ void __launch_bounds__(256) rank_kernel(const u64* __restrict__ key, int* __restrict__ perm, int n) {
    int i = blockIdx.x * 256 + threadIdx.x;
    float vi = (i < n) ? decf((uint32_t)(key[i] >> 32)) : 0.f;
    int r = 0;
    __shared__ float sv[256];
    for (int base = 0; base < n; base += 256) {
        int j = base + threadIdx.x;
        sv[threadIdx.x] = (j < n) ? decf((uint32_t)(key[j] >> 32)) : -3.4e38f;
        __syncthreads();
        int lim = min(256, n - base);
        for (int t = 0; t < lim; t++) {
            float vj = sv[t];
            int j2 = base + t;
            if (vj > vi || (vj == vi && j2 < i)) r++;
        }
        __syncthreads();
    }
    if (i < n) perm[r] = i;
}
__global__ void fill_dst_kernel(const int* __restrict__ perm, const u64* __restrict__ key,
                                int* __restrict__ dst, int* __restrict__ cnt, int R) {
    int e = blockIdx.x * 256 + threadIdx.x;
    if (e >= R) return;
    int s = perm[e];
    uint32_t low = (uint32_t)(key[s]);
    int dd = (int)(~low);
    dst[e] = dd;
    atomicAdd(&cnt[dd], 1);
}
// unmerged rows -> bf16 planes directly; dst rows -> fp32 buf (for scatter-add)
__global__ void __launch_bounds__(256) merge_gather_kernel(const float* __restrict__ src, float* __restrict__ buf,
    bf16* __restrict__ p0, bf16* __restrict__ p1,
    const int* __restrict__ a_idx, const int* __restrict__ b_idx,
    const int* __restrict__ perm, int U, int R)
{
    int row = blockIdx.x;
    if (row < U) {
        int tok = a_idx[perm[R + row]];
        const float* s = src + (long)tok * CC;
        long b = (long)row * CC;
        for (int c = threadIdx.x; c < CC; c += 256) wr_split(p0, p1, b + c, s[c]);
    } else {
        int tok = b_idx[row - U];
        const float* s = src + (long)tok * CC;
        float* d = buf + (long)row * CC;
        for (int c = threadIdx.x; c < CC; c += 256) d[c] = s[c];
    }
}
__global__ void __launch_bounds__(256) scatter_add_kernel(const float* __restrict__ src, float* __restrict__ buf,
    const int* __restrict__ a_idx, const int* __restrict__ perm, const int* __restrict__ dst, int U)
{
    int e = blockIdx.x;
    int tok = a_idx[perm[e]];
    float* d = buf + (long)(U + dst[e]) * CC;
    const float* s = src + (long)tok * CC;
    for (int c = threadIdx.x; c < CC; c += 256) atomicAdd(&d[c], s[c]);
}
// dst rows: divide by count, emit bf16 planes
__global__ void __launch_bounds__(256) div_cnt_kernel(const float* __restrict__ buf, const int* __restrict__ cnt,
    bf16* __restrict__ p0, bf16* __restrict__ p1, int U)
{
    int dr = blockIdx.x;
    float cf = (float)cnt[dr];
    long b = (long)(U + dr) * CC;
    const float* p = buf + b;
    for (int c = threadIdx.x; c < CC; c += 256) wr_split(p0, p1, b + c, p[c] / cf);
}

// ---------------- normalize O_unnorm -> ao2 hi/lo planes ----------------
__global__ void __launch_bounds__(256) normalize_kernel(const float* __restrict__ O,
    bf16* __restrict__ p0, bf16* __restrict__ p1)
{
    int r = blockIdx.x, tid = threadIdx.x;
    for (int i = tid; i < CC; i += 256) {
        int h = i / HD, k = i - h * HD;
        const float* Orow = O + (long)h * MQ * OLD + (long)r * OLD;
        float inv = 1.0f / Orow[HD];       // ones-column sum (>= 1)
        wr_split(p0, p1, (long)r * CC + i, Orow[k] * inv);
    }
}

// ---------------- unmerge ----------------
__global__ void __launch_bounds__(256) unmerge_kernel(const float* __restrict__ proj, float* __restrict__ out,
    const int* __restrict__ a_idx, const int* __restrict__ b_idx,
    const int* __restrict__ perm, const int* __restrict__ dst)
{
    int rid = blockIdx.x;
    int srcrow, tok;
    if (rid < NDQ) { srcrow = UQ + rid; tok = b_idx[rid]; }
    else if (rid < NDQ + UQ) { int u = rid - NDQ; srcrow = u; tok = a_idx[perm[RQ + u]]; }
    else { int e = rid - (NDQ + UQ); srcrow = UQ + dst[e]; tok = a_idx[perm[e]]; }
    const float* s = proj + (long)srcrow * CC;
    float* d = out + (long)tok * CC;
    for (int c = threadIdx.x; c < CC; c += 256) d[c] = s[c];
}

// ---------------- host launcher ----------------
#define SM_6_64_2  (2 * (3 * 8192 + 3 * 8192))   // 96 KB
#define SM_3_64_3  (3 * (2 * 8192 + 2 * 8192))   // 96 KB
#define SM_1_128_3 (3 * (8192 + 16384))          // 72 KB
#define SM_1_64_3  (3 * (8192 + 8192))           // 48 KB

extern "C" void kernel_launch(void* const* d_in, const int* in_sizes, int n_in,
                              void* d_out, int out_size)
{
    (void)in_sizes; (void)n_in; (void)out_size;
    const float* x   = (const float*)d_in[0];
    const float* srw = (const float*)d_in[1];
    const float* srb = (const float*)d_in[2];
    const float* lng = (const float*)d_in[3];
    const float* lnb = (const float*)d_in[4];
    const float* Wq  = (const float*)d_in[5];
    const float* Wkv = (const float*)d_in[6];
    const float* Wp  = (const float*)d_in[7];
    const float* bp  = (const float*)d_in[8];
    float* out = (float*)d_out;

    cudaFuncSetAttribute(mmg<6, 64, 2, 0, false>,        cudaFuncAttributeMaxDynamicSharedMemorySize, SM_6_64_2);
    cudaFuncSetAttribute(mmg<3, 64, 3, 0, false>,        cudaFuncAttributeMaxDynamicSharedMemorySize, SM_3_64_3);
    cudaFuncSetAttribute(mmg<3, 64, 3, 1, true>,         cudaFuncAttributeMaxDynamicSharedMemorySize, SM_3_64_3);
    cudaFuncSetAttribute(mmg<3, 64, 3, 0, false, true>,  cudaFuncAttributeMaxDynamicSharedMemorySize, SM_3_64_3);
    cudaFuncSetAttribute(mmg<3, 64, 3, 2, false>,        cudaFuncAttributeMaxDynamicSharedMemorySize, SM_3_64_3);
    cudaFuncSetAttribute(mmg<1, 128, 3, 1, false>,       cudaFuncAttributeMaxDynamicSharedMemorySize, SM_1_128_3);
    cudaFuncSetAttribute(mmg<1, 64, 3, 1, false>,        cudaFuncAttributeMaxDynamicSharedMemorySize, SM_1_64_3);

    float *xk, *mnq, *mnk, *xq, *xkm, *kvm, *S, *ou, *proj;
    uint32_t* rmaxu;
    u64 *keyq, *keyk;
    int *permq, *permk, *dstq, *dstk, *cntq, *cntk, *aq, *bq, *ak, *bk, *ctok;
    bf16 *x3, *bt3, *mq1, *mk1, *xq2, *xkm2, *wq2, *wkv2, *wp2, *qp2, *kp2, *vp2, *ao2;
    cudaGetSymbolAddress((void**)&xk, g_xk);
    cudaGetSymbolAddress((void**)&mnq, g_mnq);
    cudaGetSymbolAddress((void**)&mnk, g_mnk);
    cudaGetSymbolAddress((void**)&rmaxu, g_rmaxu);
    cudaGetSymbolAddress((void**)&xq, g_xq);
    cudaGetSymbolAddress((void**)&xkm, g_xkm);
    cudaGetSymbolAddress((void**)&kvm, g_kvm);
    cudaGetSymbolAddress((void**)&S, g_S);
    cudaGetSymbolAddress((void**)&ou, g_ou);
    cudaGetSymbolAddress((void**)&proj, g_proj);
    cudaGetSymbolAddress((void**)&keyq, g_keyq);
    cudaGetSymbolAddress((void**)&keyk, g_keyk);
    cudaGetSymbolAddress((void**)&permq, g_permq);
    cudaGetSymbolAddress((void**)&permk, g_permk);
    cudaGetSymbolAddress((void**)&dstq, g_dstq);
    cudaGetSymbolAddress((void**)&dstk, g_dstk);
    cudaGetSymbolAddress((void**)&cntq, g_cntq);
    cudaGetSymbolAddress((void**)&cntk, g_cntk);
    cudaGetSymbolAddress((void**)&aq, g_aq);
    cudaGetSymbolAddress((void**)&bq, g_bq);
    cudaGetSymbolAddress((void**)&ak, g_ak);
    cudaGetSymbolAddress((void**)&bk, g_bk);
    cudaGetSymbolAddress((void**)&ctok, g_ctok);
    cudaGetSymbolAddress((void**)&x3, g_x3);
    cudaGetSymbolAddress((void**)&bt3, g_bt3);
    cudaGetSymbolAddress((void**)&mq1, g_mq1);
    cudaGetSymbolAddress((void**)&mk1, g_mk1);
    cudaGetSymbolAddress((void**)&xq2, g_xq2);
    cudaGetSymbolAddress((void**)&xkm2, g_xkm2);
    cudaGetSymbolAddress((void**)&wq2, g_wq2);
    cudaGetSymbolAddress((void**)&wkv2, g_wkv2);
    cudaGetSymbolAddress((void**)&wp2, g_wp2);
    cudaGetSymbolAddress((void**)&qp2, g_qp2);
    cudaGetSymbolAddress((void**)&kp2, g_kp2);
    cudaGetSymbolAddress((void**)&vp2, g_vp2);
    cudaGetSymbolAddress((void**)&ao2, g_ao2);

    const long PXQ = (long)NQ * CC;
    const long PBT = (long)8 * CC * CC;
    const long PQ2 = (long)MQ * CC;
    const long PK2 = (long)MK * CC;
    const long PWQ = (long)CC * CC;
    const long PWKV = (long)2 * CC * CC;
    const long PQP = (long)HEADS * MQ * HD;
    const long PKP = (long)HEADS * MK * HD;
    const long PVP = (long)HEADS * VN * MK;
    float* Skv = S + (long)NAQ * NDQ;

    // 1-3: conv prerequisites (prep_x also covers rownorm+cvt of x)
    prep_x_kernel<<<NQ, 256>>>(x, x3, x3 + PXQ, x3 + 2 * PXQ, mnq, mq1);
    split3_bt_kernel<<<(int)((PBT + 255) / 256), 256>>>(srw, bt3, bt3 + PBT, bt3 + 2 * PBT);
    conv_tok_kernel<<<(8 * N2 + 255) / 256, 256>>>(ctok);
    // 4: conv GEMM (profiled slot)
    mmg<6, 64, 2, 0, false><<<dim3(CC / 64, N2 / 64, 1), 512, SM_6_64_2>>>(
        x3, x3 + PXQ, x3 + 2 * PXQ, CC, 0,
        bt3, bt3 + PBT, bt3 + 2 * PBT, CC, 0, (long)CC * CC,
        xk, CC, 0, srb, 1.f, nullptr, nullptr, 0, nullptr,
        CC, CC, 8, ctok, N2, nullptr);
    // 5: fused LN + rownorm + cvt
    ln_norm_kernel<<<N2, 256>>>(xk, lng, lnb, mnk, mk1);
    build_idx_kernel<<<(NQ + 255) / 256, 256>>>(D0, H0, W0, aq, bq);
    build_idx_kernel<<<(N2 + 255) / 256, 256>>>(D0 / 2, H0 / 2, W0 / 2, ak, bk);

    // ---- q-side BSM ----
    set_u32_kernel<<<(NAQ + 255) / 256, 256>>>(rmaxu, NAQ, 0u);
    mmg<1, 128, 3, 1, false><<<dim3(NDQ / 128, NAQ / 64, 1), 512, SM_1_128_3>>>(
        mq1, nullptr, nullptr, CC, 0,
        mq1, nullptr, nullptr, CC, 0, 0,
        S, NDQ, 0, nullptr, 1.f, nullptr, nullptr, 0, rmaxu,
        NDQ, CC, 1, aq, 0, bq);
    refine_kernel<<<NAQ / 8, 256>>>(S, NDQ, mnq, aq, bq, rmaxu, keyq, 2e-3f);
    rank_kernel<<<NAQ / 256, 256>>>(keyq, permq, NAQ);
    set_int_kernel<<<(NDQ + 255) / 256, 256>>>(cntq, NDQ, 1);
    fill_dst_kernel<<<(RQ + 255) / 256, 256>>>(permq, keyq, dstq, cntq, RQ);
    merge_gather_kernel<<<MQ, 256>>>(x, xq, xq2, xq2 + PQ2, aq, bq, permq, UQ, RQ);
    scatter_add_kernel<<<RQ, 256>>>(x, xq, aq, permq, dstq, UQ);
    div_cnt_kernel<<<NDQ, 256>>>(xq, cntq, xq2, xq2 + PQ2, UQ);

    // ---- kv-side BSM ----
    set_u32_kernel<<<(NAK + 255) / 256, 256>>>(rmaxu, NAK, 0u);
    mmg<1, 64, 3, 1, false><<<dim3(NDK / 64, NAK / 64, 1), 512, SM_1_64_3>>>(
        mk1, nullptr, nullptr, CC, 0,
        mk1, nullptr, nullptr, CC, 0, 0,
        Skv, NDK, 0, nullptr, 1.f, nullptr, nullptr, 0, rmaxu,
        NDK, CC, 1, ak, 0, bk);
    refine_kernel<<<NAK / 8, 256>>>(Skv, NDK, mnk, ak, bk, rmaxu, keyk, 2e-3f);
    rank_kernel<<<NAK / 256, 256>>>(keyk, permk, NAK);
    set_int_kernel<<<1, 256>>>(cntk, NDK, 1);
    fill_dst_kernel<<<(RK + 255) / 256, 256>>>(permk, keyk, dstk, cntk, RK);
    merge_gather_kernel<<<MK, 256>>>(xk, xkm, xkm2, xkm2 + PK2, ak, bk, permk, UK, RK);
    scatter_add_kernel<<<RK, 256>>>(xk, xkm, ak, permk, dstk, UK);
    div_cnt_kernel<<<NDK, 256>>>(xkm, cntk, xkm2, xkm2 + PK2, UK);

    // ---- projections ----
    split2_kernel<<<(int)((PWQ + 255) / 256), 256>>>(Wq, wq2, wq2 + PWQ, PWQ);
    split2_kernel<<<(int)((PWKV + 255) / 256), 256>>>(Wkv, wkv2, wkv2 + PWKV, PWKV);
    split2_kernel<<<(int)((PWQ + 255) / 256), 256>>>(Wp, wp2, wp2 + PWQ, PWQ);
    // Wq -> head-major bf16 Q planes directly (EPI2)
    mmg<3, 64, 3, 2, false><<<dim3(CC / 64, MQ / 64, 1), 512, SM_3_64_3>>>(
        xq2, xq2 + PQ2, nullptr, CC, 0,
        wq2, wq2 + PWQ, nullptr, CC, 0, 0,
        nullptr, 0, 0, nullptr, 1.f, qp2, qp2 + PQP, (long)MQ * HD, nullptr,
        CC, CC, 1, nullptr, 0, nullptr);
    mmg<3, 64, 3, 0, false><<<dim3(2 * CC / 64, MK / 64, 1), 512, SM_3_64_3>>>(
        xkm2, xkm2 + PK2, nullptr, CC, 0,
        wkv2, wkv2 + PWKV, nullptr, CC, 0, 0,
        kvm, 2 * CC, 0, nullptr, 1.f, nullptr, nullptr, 0, nullptr,
        2 * CC, CC, 1, nullptr, 0, nullptr);

    // ---- head prep ----
    split_kpad_kernel<<<(int)((PKP + 255) / 256), 256>>>(kvm, kp2, kp2 + PKP);
    split_vT_kernel<<<(int)((PVP + 255) / 256), 256>>>(kvm, vp2, vp2 + PVP);

    // ---- attention: QK (K=96, TK) with fused per-(head,row) rowmax ----
    float scl = 1.0f / sqrtf((float)HD);
    set_u32_kernel<<<(HEADS * MQ + 255) / 256, 256>>>(rmaxu, HEADS * MQ, 0u);
    mmg<3, 64, 3, 1, true><<<dim3(MK / 64, MQ / 64, HEADS), 512, SM_3_64_3>>>(
        qp2, qp2 + PQP, nullptr, HD, (long)MQ * HD,
        kp2, kp2 + PKP, nullptr, HD, (long)MK * HD, 0,
        S, MK, (long)MQ * MK, nullptr, scl, nullptr, nullptr, MQ, rmaxu,
        MK, HD, 1, nullptr, 0, nullptr);
    // ---- AV with inline exp(S - rmax): A = fp32 S, B = V planes (+ones row) ----
    mmg<3, 64, 3, 0, false, true><<<dim3(2, MQ / 64, HEADS), 512, SM_3_64_3>>>(
        (const bf16*)S, nullptr, nullptr, MK, (long)MQ * MK,
        vp2, vp2 + PVP, nullptr, MK, (long)VN * MK, 0,
        ou, OLD, (long)MQ * OLD, nullptr, 1.f, nullptr, nullptr, MQ, rmaxu,
        VN, MK, 1, nullptr, 0, nullptr);
    // ---- normalize + split to ao2 planes ----
    normalize_kernel<<<MQ, 256>>>(ou, ao2, ao2 + PQ2);

    // ---- output projection + unmerge ----
    mmg<3, 64, 3, 0, false><<<dim3(CC / 64, MQ / 64, 1), 512, SM_3_64_3>>>(
        ao2, ao2 + PQ2, nullptr, CC, 0,
        wp2, wp2 + PWQ, nullptr, CC, 0, 0,
        proj, CC, 0, bp, 1.f, nullptr, nullptr, 0, nullptr,
        CC, CC, 1, nullptr, 0, nullptr);
    unmerge_kernel<<<NQ, 256>>>(proj, out, aq, bq, permq, dstq);
}

// round 17
// speedup vs baseline: 1.1406x; 1.0299x over previous
#include <cuda_runtime.h>
#include <cuda_bf16.h>
#include <math.h>
#include <stdint.h>

// ---------------- static problem sizes ----------------
#define CC    768
#define D0    16
#define H0    32
#define W0    32
#define NQ    16384
#define NDQ   2048
#define NAQ   14336
#define RQ    8192
#define UQ    6144
#define MQ    8192
#define N2    2048
#define NDK   256
#define NAK   1792
#define RK    1024
#define UK    768
#define MK    1024
#define HEADS 8
#define HD    96
#define VN    97            // V rows incl. ones row
#define OLD   104           // padded ldc for O_unnorm

typedef __nv_bfloat16 bf16;
typedef unsigned long long u64;

// ---------------- device scratch ----------------
__device__ float g_xk[N2 * CC];
__device__ float g_mnq[NQ * CC];
__device__ float g_mnk[N2 * CC];
__device__ u64   g_keyq[NAQ];
__device__ u64   g_keyk[NAK];
__device__ uint32_t g_rmaxu[HEADS * MQ];
__device__ uint32_t g_thr[2];
__device__ int g_need[2];
__device__ int g_ctr[4];
__device__ int g_permq[NAQ];
__device__ int g_permk[NAK];
__device__ int g_dstq[RQ];
__device__ int g_dstk[RK];
__device__ int g_cntq[NDQ];
__device__ int g_cntk[NDK];
__device__ int g_aq[NAQ];
__device__ int g_bq[NDQ];
__device__ int g_ak[NAK];
__device__ int g_bk[NDK];
__device__ int g_ctok[8 * N2];
__device__ float g_xq[MQ * CC];
__device__ float g_xkm[MK * CC];
__device__ float g_kvm[MK * 2 * CC];
__device__ float g_S[(long)HEADS * MQ * MK];
__device__ float g_ou[(long)HEADS * MQ * OLD];
__device__ float g_proj[MQ * CC];

// bf16 planes
__device__ bf16 g_x3[3][NQ * CC];
__device__ bf16 g_bt3[3][8 * CC * CC];
__device__ bf16 g_mq1[NQ * CC];
__device__ bf16 g_mk1[N2 * CC];
__device__ bf16 g_xq2[2][MQ * CC];
__device__ bf16 g_xkm2[2][MK * CC];
__device__ bf16 g_wq2[2][CC * CC];
__device__ bf16 g_wkv2[2][2 * CC * CC];
__device__ bf16 g_wp2[2][CC * CC];
__device__ bf16 g_qp2[2][HEADS * MQ * HD];
__device__ bf16 g_kp2[2][HEADS * MK * HD];
__device__ bf16 g_vp2[2][HEADS * VN * MK];
__device__ bf16 g_ao2[2][MQ * CC];

__device__ __forceinline__ uint32_t smem_u32(const void* p) {
    uint32_t a;
    asm("{ .reg .u64 t; cvta.to.shared.u64 t, %1; cvt.u32.u64 %0, t; }" : "=r"(a) : "l"(p));
    return a;
}
__device__ __forceinline__ uint32_t pkbf(bf16 a, bf16 b) {
    return (uint32_t)__bfloat16_as_ushort(a) | ((uint32_t)__bfloat16_as_ushort(b) << 16);
}
__device__ __forceinline__ uint32_t encf(float f) {
    uint32_t u = __float_as_uint(f);
    return (u & 0x80000000u) ? ~u : (u | 0x80000000u);
}
__device__ __forceinline__ float decf(uint32_t o) {
    uint32_t u = (o & 0x80000000u) ? (o ^ 0x80000000u) : ~o;
    return __uint_as_float(u);
}
__device__ __forceinline__ void wr_split(bf16* p0, bf16* p1, long idx, float v) {
    bf16 h = __float2bfloat16(v);
    p0[idx] = h;
    p1[idx] = __float2bfloat16(v - __bfloat162float(h));
}
#define SWZ(o) ((o) ^ (((o) >> 3) & 0x70))
#define MMA16816(d, a, b0v, b1v) \
    asm volatile("mma.sync.aligned.m16n8k16.row.col.f32.bf16.bf16.f32 " \
        "{%0,%1,%2,%3}, {%4,%5,%6,%7}, {%8,%9}, {%0,%1,%2,%3};" \
        : "+f"((d)[0]), "+f"((d)[1]), "+f"((d)[2]), "+f"((d)[3]) \
        : "r"((a)[0]), "r"((a)[1]), "r"((a)[2]), "r"((a)[3]), "r"(b0v), "r"(b1v))
#define LDSM4(r, a) \
    asm volatile("ldmatrix.sync.aligned.m8n8.x4.shared.b16 {%0,%1,%2,%3}, [%4];" \
        : "=r"((r)[0]), "=r"((r)[1]), "=r"((r)[2]), "=r"((r)[3]) : "r"(a))
#define CPA(dst, src, sz) \
    asm volatile("cp.async.cg.shared.global [%0], [%1], 16, %2;" :: "r"(dst), "l"(src), "r"(sz) : "memory")
#define CPCOMMIT() asm volatile("cp.async.commit_group;" ::: "memory")
#define CPWAIT1()  asm volatile("cp.async.wait_group 1;" ::: "memory")

// ---------------- pipelined ldmatrix mma.sync split-bf16 GEMM ----------------
// (unchanged from R16: TK tail flag, AEXP softmax-A path, EPI variants)
template <int NPR, int TN, int STAGES, int EPI, bool TK, bool AEXP = false>
__global__ void __launch_bounds__(512, 2) mmg(
    const bf16* A0, const bf16* A1, const bf16* A2, long lda, long ahs,
    const bf16* B0, const bf16* B1, const bf16* B2, long ldb, long bhs, long bseg,
    float* C, long ldc, long chs, const float* bias, float scale,
    bf16* P0, bf16* P1, long phs, uint32_t* rmaxu,
    int N, int K, int ntap, const int* gA, int gAs, const int* gB)
{
    constexpr int nA = (NPR == 6) ? 3 : (NPR == 3) ? 2 : 1;
    constexpr int nB = nA;
    constexpr int PLA = 8192;          // 64 rows x 128 B
    constexpr int PLB = TN * 128;
    constexpr int STG = nA * PLA + nB * PLB;
    constexpr int NJ = TN / 32;
    extern __shared__ char sm[];
    const uint32_t su = smem_u32(sm);

    const int tid = threadIdx.x, lane = tid & 31, wid = tid >> 5;
    const int wm = wid >> 2, wn = wid & 3;
    const int m0 = blockIdx.y * 64, n0 = blockIdx.x * TN, z = blockIdx.z;
    const int lq = lane >> 2, lr = lane & 3;

    const int lrA = tid >> 3, secA = tid & 7;
    const int lrB = (TN == 128) ? (tid >> 2) : (tid >> 3);
    const int secB = (TN == 128) ? (tid & 3) : (tid & 7);
    const int nrow = n0 + lrB;
    const bool bval = nrow < N;
    const long brow = bval ? (gB ? (long)gB[nrow] : (long)nrow) : 0;
    const uint32_t bsz = bval ? 16u : 0u;

    const uint32_t dA0 = SWZ((uint32_t)(lrA * 128 + secA * 16));
    const uint32_t dB0 = (TN == 128) ? SWZ((uint32_t)(lrB * 128 + secB * 32))
                                     : SWZ((uint32_t)(lrB * 128 + secB * 16));
    const uint32_t dB1 = (TN == 128) ? SWZ((uint32_t)(lrB * 128 + secB * 32 + 16)) : 0u;

    const int kcd = (K + 63) >> 6;
    const int nch = ntap * kcd;
    const bf16* Ap[3] = {A0, A1, A2};
    const bf16* Bp[3] = {B0, B1, B2};

    float acc[NJ][4];
#pragma unroll
    for (int j = 0; j < NJ; j++)
#pragma unroll
        for (int t = 0; t < 4; t++) acc[j][t] = 0.f;

    auto issue = [&](int c) {
        const int stg = c % STAGES;
        const uint32_t sb = su + stg * STG;
        const int tap = c / kcd;
        const int k0 = (c - tap * kcd) << 6;
        if constexpr (AEXP) {
            const long arow = m0 + lrA;
            const float rm = decf(rmaxu[(long)z * phs + arow]);
            const float* Af = reinterpret_cast<const float*>(A0)
                              + (long)z * ahs + arow * lda + k0 + secA * 8;
            float4 va = *(const float4*)(Af);
            float4 vb = *(const float4*)(Af + 4);
            float e0 = __expf(va.x - rm), e1 = __expf(va.y - rm);
            float e2 = __expf(va.z - rm), e3 = __expf(va.w - rm);
            float e4 = __expf(vb.x - rm), e5 = __expf(vb.y - rm);
            float e6 = __expf(vb.z - rm), e7 = __expf(vb.w - rm);
            bf16 h0 = __float2bfloat16(e0), h1 = __float2bfloat16(e1);
            bf16 h2 = __float2bfloat16(e2), h3 = __float2bfloat16(e3);
            bf16 h4 = __float2bfloat16(e4), h5 = __float2bfloat16(e5);
            bf16 h6 = __float2bfloat16(e6), h7 = __float2bfloat16(e7);
            uint4 hv = make_uint4(pkbf(h0, h1), pkbf(h2, h3), pkbf(h4, h5), pkbf(h6, h7));
            uint4 lv = make_uint4(
                pkbf(__float2bfloat16(e0 - __bfloat162float(h0)), __float2bfloat16(e1 - __bfloat162float(h1))),
                pkbf(__float2bfloat16(e2 - __bfloat162float(h2)), __float2bfloat16(e3 - __bfloat162float(h3))),
                pkbf(__float2bfloat16(e4 - __bfloat162float(h4)), __float2bfloat16(e5 - __bfloat162float(h5))),
                pkbf(__float2bfloat16(e6 - __bfloat162float(h6)), __float2bfloat16(e7 - __bfloat162float(h7))));
            *(uint4*)(sm + stg * STG + dA0) = hv;
            *(uint4*)(sm + stg * STG + PLA + dA0) = lv;
        } else if constexpr (!TK) {
            const long arow = gA ? (long)gA[tap * gAs + m0 + lrA] : (long)(m0 + lrA);
#pragma unroll
            for (int p = 0; p < nA; p++) {
                const bf16* s0 = Ap[p] + (long)z * ahs + arow * lda + k0 + secA * 8;
                CPA(sb + p * PLA + dA0, s0, 16u);
            }
        } else {
            const long arow = gA ? (long)gA[tap * gAs + m0 + lrA] : (long)(m0 + lrA);
            const uint32_t szA = (k0 + secA * 8 < K) ? 16u : 0u;
            const int kaA = szA ? (k0 + secA * 8) : 0;
#pragma unroll
            for (int p = 0; p < nA; p++) {
                const bf16* s0 = Ap[p] + (long)z * ahs + arow * lda + kaA;
                CPA(sb + p * PLA + dA0, s0, szA);
            }
        }
        if constexpr (!TK) {
#pragma unroll
            for (int p = 0; p < nB; p++) {
                const bf16* s0 = Bp[p] + (long)z * bhs + (long)tap * bseg + brow * ldb + k0
                               + secB * (TN == 128 ? 16 : 8);
                CPA(sb + nA * PLA + p * PLB + dB0, s0, bsz);
                if (TN == 128) CPA(sb + nA * PLA + p * PLB + dB1, s0 + 8, bsz);
            }
        } else {
            if (TN == 128) {
                const uint32_t sz0 = (k0 + secB * 16 < K) ? bsz : 0u;
                const uint32_t sz1 = (k0 + secB * 16 + 8 < K) ? bsz : 0u;
                const int kb0 = sz0 ? (k0 + secB * 16) : 0;
                const int kb1 = sz1 ? (k0 + secB * 16 + 8) : 0;
#pragma unroll
                for (int p = 0; p < nB; p++) {
                    const bf16* s0 = Bp[p] + (long)z * bhs + (long)tap * bseg + brow * ldb;
                    CPA(sb + nA * PLA + p * PLB + dB0, s0 + kb0, sz0);
                    CPA(sb + nA * PLA + p * PLB + dB1, s0 + kb1, sz1);
                }
            } else {
                const uint32_t sz0 = (k0 + secB * 8 < K) ? bsz : 0u;
                const int kb0 = sz0 ? (k0 + secB * 8) : 0;
#pragma unroll
                for (int p = 0; p < nB; p++) {
                    const bf16* s0 = Bp[p] + (long)z * bhs + (long)tap * bseg + brow * ldb;
                    CPA(sb + nA * PLA + p * PLB + dB0, s0 + kb0, sz0);
                }
            }
        }
        CPCOMMIT();
    };

    auto compute = [&](int stg, int kslim) {
        const uint32_t sb = su + stg * STG;
        const int pa6[6] = {0, 0, 1, 1, 0, 2}, pb6[6] = {0, 1, 0, 1, 2, 0};
#pragma unroll
        for (int ks = 0; ks < 4; ks++) {
            if constexpr (TK) { if (ks >= kslim) break; }
            uint32_t af[nA][4];
#pragma unroll
            for (int p = 0; p < nA; p++) {
                uint32_t off = (uint32_t)((wm * 16 + (lane & 15)) * 128
                                          + ks * 32 + ((lane >> 4) << 4));
                LDSM4(af[p], sb + p * PLA + SWZ(off));
            }
            uint32_t bl[nB][NJ], bh[nB][NJ];
            if constexpr (TN == 128) {
#pragma unroll
                for (int p = 0; p < nB; p++) {
                    uint32_t r0[4], r1[4];
                    uint32_t off0 = (uint32_t)((wn * 32 + (lane >> 3) * 8 + (lane & 7)) * 128 + ks * 32);
                    LDSM4(r0, sb + nA * PLA + p * PLB + SWZ(off0));
                    LDSM4(r1, sb + nA * PLA + p * PLB + SWZ(off0 + 16));
#pragma unroll
                    for (int j = 0; j < 4; j++) { bl[p][j] = r0[j]; bh[p][j] = r1[j]; }
                }
            } else {
#pragma unroll
                for (int p = 0; p < nB; p++) {
                    uint32_t r[4];
                    const int tileB = (lane >> 3) & 1, khB = lane >> 4;
                    uint32_t off = (uint32_t)((wn * 16 + tileB * 8 + (lane & 7)) * 128
                                              + ks * 32 + khB * 16);
                    LDSM4(r, sb + nA * PLA + p * PLB + SWZ(off));
                    bl[p][0] = r[0]; bl[p][1] = r[1]; bh[p][0] = r[2]; bh[p][1] = r[3];
                }
            }
#pragma unroll
            for (int pr = 0; pr < NPR; pr++) {
                const int pA = (NPR == 1) ? 0 : pa6[pr];
                const int pB = (NPR == 1) ? 0 : pb6[pr];
#pragma unroll
                for (int j = 0; j < NJ; j++)
                    MMA16816(acc[j], af[pA], bl[pB][j], bh[pB][j]);
            }
        }
    };

    issue(0);
    for (int c = 0; c < nch; c++) {
        if (c + 1 < nch) issue(c + 1);
        else CPCOMMIT();
        CPWAIT1();
        __syncthreads();
        if constexpr (TK) {
            const int k0c = (c % kcd) << 6;
            int kslim = (K - k0c + 15) >> 4; if (kslim > 4) kslim = 4;
            compute(c % STAGES, kslim);
        } else {
            compute(c % STAGES, 4);
        }
        if (STAGES == 2) __syncthreads();
    }

    // ---- epilogue ----
    const int r = m0 + wm * 16 + lq;
    if constexpr (EPI == 0 || EPI == 1) {
        float mx0 = -3.4e38f, mx1 = -3.4e38f;
#pragma unroll
        for (int j = 0; j < NJ; j++) {
            const int cb = n0 + wn * (TN / 4) + j * 8 + lr * 2;
            if (cb < N) {
                float bb0 = bias ? bias[cb] : 0.f;
                float bb1 = bias ? bias[cb + 1] : 0.f;
                float v0 = acc[j][0] * scale + bb0, v1 = acc[j][1] * scale + bb1;
                float v2 = acc[j][2] * scale + bb0, v3 = acc[j][3] * scale + bb1;
                float* p0 = C + (long)z * chs + (long)r * ldc + cb;
                float* p1 = C + (long)z * chs + (long)(r + 8) * ldc + cb;
                p0[0] = v0; p0[1] = v1; p1[0] = v2; p1[1] = v3;
                if (EPI == 1) {
                    mx0 = fmaxf(mx0, fmaxf(v0, v1));
                    mx1 = fmaxf(mx1, fmaxf(v2, v3));
                }
            }
        }
        if constexpr (EPI == 1) {
            mx0 = fmaxf(mx0, __shfl_xor_sync(0xffffffffu, mx0, 1));
            mx0 = fmaxf(mx0, __shfl_xor_sync(0xffffffffu, mx0, 2));
            mx1 = fmaxf(mx1, __shfl_xor_sync(0xffffffffu, mx1, 1));
            mx1 = fmaxf(mx1, __shfl_xor_sync(0xffffffffu, mx1, 2));
            if (lr == 0) {
                atomicMax(&rmaxu[(long)z * phs + r], encf(mx0));
                atomicMax(&rmaxu[(long)z * phs + r + 8], encf(mx1));
            }
        }
    } else if constexpr (EPI == 2) {
#pragma unroll
        for (int j = 0; j < NJ; j++) {
            const int cb = n0 + wn * (TN / 4) + j * 8 + lr * 2;
            if (cb < N) {
                int h = cb / HD, k = cb - h * HD;
                float v0 = acc[j][0] * scale, v1 = acc[j][1] * scale;
                float v2 = acc[j][2] * scale, v3 = acc[j][3] * scale;
                wr_split(P0 + (long)h * phs, P1 + (long)h * phs, (long)r * HD + k, v0);
                wr_split(P0 + (long)h * phs, P1 + (long)h * phs, (long)r * HD + k + 1, v1);
                wr_split(P0 + (long)h * phs, P1 + (long)h * phs, (long)(r + 8) * HD + k, v2);
                wr_split(P0 + (long)h * phs, P1 + (long)h * phs, (long)(r + 8) * HD + k + 1, v3);
            }
        }
    } else {   // EPI == 3
#pragma unroll
        for (int j = 0; j < NJ; j++) {
            const int cb = n0 + wn * (TN / 4) + j * 8 + lr * 2;
            if (cb < N) {
                float v0 = acc[j][0] * scale, v1 = acc[j][1] * scale;
                float v2 = acc[j][2] * scale, v3 = acc[j][3] * scale;
                long o0 = (long)z * chs + (long)r * ldc + cb;
                long o1 = (long)z * chs + (long)(r + 8) * ldc + cb;
                wr_split(P0, P1, o0, v0);
                wr_split(P0, P1, o0 + 1, v1);
                wr_split(P0, P1, o1, v2);
                wr_split(P0, P1, o1 + 1, v3);
            }
        }
    }
}

// ---------------- utility / prep kernels ----------------
__global__ void set_int_kernel(int* p, int n, int v) {
    int i = blockIdx.x * 256 + threadIdx.x;
    if (i < n) p[i] = v;
}
__global__ void set_u32_kernel(uint32_t* p, int n, uint32_t v) {
    int i = blockIdx.x * 256 + threadIdx.x;
    if (i < n) p[i] = v;
}
__global__ void build_idx_kernel(int D, int H, int W, int* a_idx, int* b_idx) {
    int n = D * H * W;
    int t = blockIdx.x * 256 + threadIdx.x;
    if (t >= n) return;
    int z = t / (H * W), y = (t / W) % H, xx = t % W;
    int hw2 = (H >> 1) * (W >> 1);
    if (((z | y | xx) & 1) == 0) {
        b_idx[(z >> 1) * hw2 + (y >> 1) * (W >> 1) + (xx >> 1)] = t;
    } else {
        int cez = (z + 1) >> 1, cey = (y + 1) >> 1, cex = (xx + 1) >> 1;
        int before = cez * hw2;
        if ((z & 1) == 0) { before += cey * (W >> 1); if ((y & 1) == 0) before += cex; }
        a_idx[t - before] = t;
    }
}
__global__ void conv_tok_kernel(int* t) {
    int i = blockIdx.x * 256 + threadIdx.x;
    if (i >= 8 * N2) return;
    int tap = i >> 11, m = i & 2047;
    int kz = tap >> 2, ky = (tap >> 1) & 1, kx = tap & 1;
    int z2 = m >> 8, y2 = (m >> 4) & 15, x2 = m & 15;
    t[i] = (2 * z2 + kz) * (H0 * W0) + (2 * y2 + ky) * W0 + (2 * x2 + kx);
}
__device__ __forceinline__ void split3_elem(float v, bf16* p0, bf16* p1, bf16* p2, long i) {
    bf16 h = __float2bfloat16(v); float r = v - __bfloat162float(h);
    bf16 m = __float2bfloat16(r); float r2 = r - __bfloat162float(m);
    p0[i] = h; p1[i] = m; p2[i] = __float2bfloat16(r2);
}
// fused: split3(x) + L2-rownorm -> mnq fp32 + mq1 bf16
__global__ void __launch_bounds__(256) prep_x_kernel(const float* __restrict__ x,
    bf16* p0, bf16* p1, bf16* p2, float* __restrict__ mnq, bf16* __restrict__ mq1)
{
    int row = blockIdx.x;
    const float* p = x + (long)row * CC;
    __shared__ float red[256];
    int tid = threadIdx.x;
    float v0 = p[tid], v1 = p[tid + 256], v2 = p[tid + 512];
    long b = (long)row * CC;
    split3_elem(v0, p0, p1, p2, b + tid);
    split3_elem(v1, p0, p1, p2, b + tid + 256);
    split3_elem(v2, p0, p1, p2, b + tid + 512);
    red[tid] = v0 * v0 + v1 * v1 + v2 * v2; __syncthreads();
    for (int off = 128; off; off >>= 1) { if (tid < off) red[tid] += red[tid + off]; __syncthreads(); }
    float inv = (float)(1.0 / sqrt((double)red[0]));
    float n0 = v0 * inv, n1 = v1 * inv, n2 = v2 * inv;
    mnq[b + tid] = n0; mnq[b + tid + 256] = n1; mnq[b + tid + 512] = n2;
    mq1[b + tid] = __float2bfloat16(n0);
    mq1[b + tid + 256] = __float2bfloat16(n1);
    mq1[b + tid + 512] = __float2bfloat16(n2);
}
// three weight tensors -> hi/lo planes, one launch
__global__ void split2_w3_kernel(const float* w1, bf16* o1h, bf16* o1l, long n1,
                                 const float* w2, bf16* o2h, bf16* o2l, long n2,
                                 const float* w3, bf16* o3h, bf16* o3l, long n3)
{
    long i = (long)blockIdx.x * 256 + threadIdx.x;
    if (i < n1) { wr_split(o1h, o1l, i, w1[i]); return; }
    long j = i - n1;
    if (j < n2) { wr_split(o2h, o2l, j, w2[j]); return; }
    long k = j - n2;
    if (k < n3) wr_split(o3h, o3l, k, w3[k]);
}
__global__ void split3_bt_kernel(const float* __restrict__ w, bf16* p0, bf16* p1, bf16* p2) {
    long i = (long)blockIdx.x * 256 + threadIdx.x;
    if (i >= (long)8 * CC * CC) return;
    int tap = (int)(i / (CC * CC));
    int rem = (int)(i - (long)tap * CC * CC);
    int n = rem / CC, k = rem - n * CC;
    split3_elem(w[(long)n * (CC * 8) + k * 8 + tap], p0, p1, p2, i);
}
// kvm k-part -> [8][MK][96] hi/lo
__global__ void split_kpad_kernel(const float* __restrict__ kvm, bf16* p0, bf16* p1) {
    long i = (long)blockIdx.x * 256 + threadIdx.x;
    if (i >= (long)HEADS * MK * HD) return;
    int h = (int)(i / (MK * HD));
    int rem = (int)(i - (long)h * MK * HD);
    int m = rem / HD, k = rem - m * HD;
    wr_split(p0, p1, i, kvm[(long)m * (2 * CC) + h * HD + k]);
}
// kvm v-part transposed -> [8][97][MK] hi/lo (row 96 = ones for row-sum)
__global__ void split_vT_kernel(const float* __restrict__ kvm, bf16* p0, bf16* p1) {
    long i = (long)blockIdx.x * 256 + threadIdx.x;
    if (i >= (long)HEADS * VN * MK) return;
    int h = (int)(i / (VN * MK));
    int rem = (int)(i - (long)h * VN * MK);
    int n = rem >> 10, k = rem & (MK - 1);
    float v = (n < HD) ? kvm[(long)k * (2 * CC) + CC + h * HD + n] : 1.0f;
    wr_split(p0, p1, i, v);
}

// ---------------- fused LN -> xk, mnk, mk1 ----------------
__global__ void __launch_bounds__(256) ln_norm_kernel(float* __restrict__ xk,
    const float* __restrict__ g, const float* __restrict__ b,
    float* __restrict__ mnk, bf16* __restrict__ mk1)
{
    int row = blockIdx.x;
    float* p = xk + (long)row * CC;
    __shared__ float red[256];
    int tid = threadIdx.x;
    float v0 = p[tid], v1 = p[tid + 256], v2 = p[tid + 512];
    red[tid] = v0 + v1 + v2; __syncthreads();
    for (int off = 128; off; off >>= 1) { if (tid < off) red[tid] += red[tid + off]; __syncthreads(); }
    float mean = red[0] / (float)CC;
    __syncthreads();
    float d0 = v0 - mean, d1 = v1 - mean, d2 = v2 - mean;
    red[tid] = d0 * d0 + d1 * d1 + d2 * d2; __syncthreads();
    for (int off = 128; off; off >>= 1) { if (tid < off) red[tid] += red[tid + off]; __syncthreads(); }
    float var = red[0] / (float)CC;
    float inv = (float)(1.0 / sqrt((double)var + 1e-5));
    __syncthreads();
    float y0 = d0 * inv * g[tid] + b[tid];
    float y1 = d1 * inv * g[tid + 256] + b[tid + 256];
    float y2 = d2 * inv * g[tid + 512] + b[tid + 512];
    p[tid] = y0; p[tid + 256] = y1; p[tid + 512] = y2;
    red[tid] = y0 * y0 + y1 * y1 + y2 * y2; __syncthreads();
    for (int off = 128; off; off >>= 1) { if (tid < off) red[tid] += red[tid + off]; __syncthreads(); }
    float nrm = (float)(1.0 / sqrt((double)red[0]));
    float* q = mnk + (long)row * CC;
    bf16* q1 = mk1 + (long)row * CC;
    float n0 = y0 * nrm, n1 = y1 * nrm, n2 = y2 * nrm;
    q[tid] = n0; q[tid + 256] = n1; q[tid + 512] = n2;
    q1[tid] = __float2bfloat16(n0); q1[tid + 256] = __float2bfloat16(n1); q1[tid + 512] = __float2bfloat16(n2);
}

// ---------------- refine (candidates from fused rowmax) ----------------
__global__ void __launch_bounds__(256) refine_kernel(
    const float* __restrict__ S, int ncol, const float* __restrict__ mn,
    const int* __restrict__ a_idx, const int* __restrict__ b_idx,
    const uint32_t* __restrict__ rmaxu, u64* __restrict__ key, float margin)
{
    int row = blockIdx.x * 8 + (threadIdx.x >> 5);
    int lane = threadIdx.x & 31;
    const float* p = S + (long)row * ncol;
    float thr = decf(rmaxu[row]) - margin;
    const float* av = mn + (long)a_idx[row] * CC;
    float bestv = -3.4e38f;
    int bestd = 0;
    for (int base = 0; base < ncol; base += 32) {
        float s = p[base + lane];
        unsigned m = __ballot_sync(0xffffffffu, s >= thr);
        while (m) {
            int b = __ffs(m) - 1;
            m &= m - 1;
            int dst = base + b;
            const float* bv = mn + (long)b_idx[dst] * CC;
            float part = 0.f;
            for (int c = lane; c < CC; c += 32) part += av[c] * bv[c];
            for (int off = 16; off; off >>= 1) part += __shfl_xor_sync(0xffffffffu, part, off);
            if (part > bestv) { bestv = part; bestd = dst; }
        }
    }
    if (lane == 0) {
        key[row] = ((u64)encf(bestv) << 32) | (unsigned)(~bestd);
    }
}

// ---------------- selection-based partition (replaces O(n^2) rank) ----------------
// Single block: 4-pass byte radix over encoded values; outputs exact threshold T
// (R-th largest) and number of T-ties to take; resets the two slot counters.
__global__ void __launch_bounds__(1024) select_kernel(const u64* __restrict__ key, int n, int R,
    uint32_t* thr_out, int* need_out, int* ctr)
{
    __shared__ int hist[256];
    __shared__ uint32_t sprefix;
    __shared__ int sremain;
    int tid = threadIdx.x;
    uint32_t prefix = 0;
    int remain = R;
    for (int byte = 3; byte >= 0; byte--) {
        const int shift = byte * 8;
        if (tid < 256) hist[tid] = 0;
        __syncthreads();
        for (int i = tid; i < n; i += 1024) {
            uint32_t v = (uint32_t)(key[i] >> 32);
            bool match = (byte == 3) || ((v >> (shift + 8)) == (prefix >> (shift + 8)));
            if (match) atomicAdd(&hist[(v >> shift) & 255], 1);
        }
        __syncthreads();
        if (tid == 0) {
            int acc = 0, b;
            for (b = 255; b >= 0; b--) {
                if (acc + hist[b] >= remain) break;
                acc += hist[b];
            }
            sprefix = prefix | ((uint32_t)b << shift);
            sremain = remain - acc;
        }
        __syncthreads();
        prefix = sprefix; remain = sremain;
        __syncthreads();
    }
    if (tid == 0) {
        *thr_out = prefix;
        *need_out = remain;     // ties at T to include (stable: smallest indices)
        ctr[0] = 0; ctr[1] = 0;
    }
}
// Partition into perm[0..R) = src set, perm[R..n) = unm set (order within sets
// is arbitrary; output-invariant by permutation equivariance of the pipeline).
__global__ void __launch_bounds__(256) partition_kernel(const u64* __restrict__ key, int n, int R,
    const uint32_t* __restrict__ thrp, const int* __restrict__ needp,
    int* __restrict__ ctr, int* __restrict__ perm)
{
    int i = blockIdx.x * 256 + threadIdx.x;
    if (i >= n) return;
    const uint32_t T = *thrp;
    uint32_t v = (uint32_t)(key[i] >> 32);
    bool src;
    if (v > T) src = true;
    else if (v < T) src = false;
    else {
        const int need = *needp;
        int c = 0;                          // ties are rare; only they pay
        for (int j = 0; j < i; j++)
            if ((uint32_t)(key[j] >> 32) == T) c++;
        src = (c < need);
    }
    if (src) perm[atomicAdd(&ctr[0], 1)] = i;
    else perm[R + atomicAdd(&ctr[1], 1)] = i;
}

// ---------------- BSM index machinery ----------------
__global__ void fill_dst_kernel(const int* __restrict__ perm, const u64* __restrict__ key,
                                int* __restrict__ dst, int* __restrict__ cnt, int R) {
    int e = blockIdx.x * 256 + threadIdx.x;
    if (e >= R) return;
    int s = perm[e];
    uint32_t low = (uint32_t)(key[s]);
    int dd = (int)(~low);
    dst[e] = dd;
    atomicAdd(&cnt[dd], 1);
}
// unmerged rows -> bf16 planes directly; dst rows -> fp32 buf (for scatter-add)
__global__ void __launch_bounds__(256) merge_gather_kernel(const float* __restrict__ src, float* __restrict__ buf,
    bf16* __restrict__ p0, bf16* __restrict__ p1,
    const int* __restrict__ a_idx, const int* __restrict__ b_idx,
    const int* __restrict__ perm, int U, int R)
{
    int row = blockIdx.x;
    if (row < U) {
        int tok = a_idx[perm[R + row]];
        const float* s = src + (long)tok * CC;
        long b = (long)row * CC;
        for (int c = threadIdx.x; c < CC; c += 256) wr_split(p0, p1, b + c, s[c]);
    } else {
        int tok = b_idx[row - U];
        const float* s = src + (long)tok * CC;
        float* d = buf + (long)row * CC;
        for (int c = threadIdx.x; c < CC; c += 256) d[c] = s[c];
    }
}
__global__ void __launch_bounds__(256) scatter_add_kernel(const float* __restrict__ src, float* __restrict__ buf,
    const int* __restrict__ a_idx, const int* __restrict__ perm, const int* __restrict__ dst, int U)
{
    int e = blockIdx.x;
    int tok = a_idx[perm[e]];
    float* d = buf + (long)(U + dst[e]) * CC;
    const float* s = src + (long)tok * CC;
    for (int c = threadIdx.x; c < CC; c += 256) atomicAdd(&d[c], s[c]);
}
// dst rows: divide by count, emit bf16 planes
__global__ void __launch_bounds__(256) div_cnt_kernel(const float* __restrict__ buf, const int* __restrict__ cnt,
    bf16* __restrict__ p0, bf16* __restrict__ p1, int U)
{
    int dr = blockIdx.x;
    float cf = (float)cnt[dr];
    long b = (long)(U + dr) * CC;
    const float* p = buf + b;
    for (int c = threadIdx.x; c < CC; c += 256) wr_split(p0, p1, b + c, p[c] / cf);
}

// ---------------- normalize O_unnorm -> ao2 hi/lo planes ----------------
__global__ void __launch_bounds__(256) normalize_kernel(const float* __restrict__ O,
    bf16* __restrict__ p0, bf16* __restrict__ p1)
{
    int r = blockIdx.x, tid = threadIdx.x;
    for (int i = tid; i < CC; i += 256) {
        int h = i / HD, k = i - h * HD;
        const float* Orow = O + (long)h * MQ * OLD + (long)r * OLD;
        float inv = 1.0f / Orow[HD];       // ones-column sum (>= 1)
        wr_split(p0, p1, (long)r * CC + i, Orow[k] * inv);
    }
}

// ---------------- unmerge ----------------
__global__ void __launch_bounds__(256) unmerge_kernel(const float* __restrict__ proj, float* __restrict__ out,
    const int* __restrict__ a_idx, const int* __restrict__ b_idx,
    const int* __restrict__ perm, const int* __restrict__ dst)
{
    int rid = blockIdx.x;
    int srcrow, tok;
    if (rid < NDQ) { srcrow = UQ + rid; tok = b_idx[rid]; }
    else if (rid < NDQ + UQ) { int u = rid - NDQ; srcrow = u; tok = a_idx[perm[RQ + u]]; }
    else { int e = rid - (NDQ + UQ); srcrow = UQ + dst[e]; tok = a_idx[perm[e]]; }
    const float* s = proj + (long)srcrow * CC;
    float* d = out + (long)tok * CC;
    for (int c = threadIdx.x; c < CC; c += 256) d[c] = s[c];
}

// ---------------- host launcher ----------------
#define SM_6_64_2  (2 * (3 * 8192 + 3 * 8192))   // 96 KB
#define SM_3_64_3  (3 * (2 * 8192 + 2 * 8192))   // 96 KB
#define SM_1_128_3 (3 * (8192 + 16384))          // 72 KB
#define SM_1_64_3  (3 * (8192 + 8192))           // 48 KB

extern "C" void kernel_launch(void* const* d_in, const int* in_sizes, int n_in,
                              void* d_out, int out_size)
{
    (void)in_sizes; (void)n_in; (void)out_size;
    const float* x   = (const float*)d_in[0];
    const float* srw = (const float*)d_in[1];
    const float* srb = (const float*)d_in[2];
    const float* lng = (const float*)d_in[3];
    const float* lnb = (const float*)d_in[4];
    const float* Wq  = (const float*)d_in[5];
    const float* Wkv = (const float*)d_in[6];
    const float* Wp  = (const float*)d_in[7];
    const float* bp  = (const float*)d_in[8];
    float* out = (float*)d_out;

    cudaFuncSetAttribute(mmg<6, 64, 2, 0, false>,        cudaFuncAttributeMaxDynamicSharedMemorySize, SM_6_64_2);
    cudaFuncSetAttribute(mmg<3, 64, 3, 0, false>,        cudaFuncAttributeMaxDynamicSharedMemorySize, SM_3_64_3);
    cudaFuncSetAttribute(mmg<3, 64, 3, 1, true>,         cudaFuncAttributeMaxDynamicSharedMemorySize, SM_3_64_3);
    cudaFuncSetAttribute(mmg<3, 64, 3, 0, false, true>,  cudaFuncAttributeMaxDynamicSharedMemorySize, SM_3_64_3);
    cudaFuncSetAttribute(mmg<3, 64, 3, 2, false>,        cudaFuncAttributeMaxDynamicSharedMemorySize, SM_3_64_3);
    cudaFuncSetAttribute(mmg<1, 128, 3, 1, false>,       cudaFuncAttributeMaxDynamicSharedMemorySize, SM_1_128_3);
    cudaFuncSetAttribute(mmg<1, 64, 3, 1, false>,        cudaFuncAttributeMaxDynamicSharedMemorySize, SM_1_64_3);

    float *xk, *mnq, *mnk, *xq, *xkm, *kvm, *S, *ou, *proj;
    uint32_t *rmaxu, *thr;
    int *needp, *ctr;
    u64 *keyq, *keyk;
    int *permq, *permk, *dstq, *dstk, *cntq, *cntk, *aq, *bq, *ak, *bk, *ctok;
    bf16 *x3, *bt3, *mq1, *mk1, *xq2, *xkm2, *wq2, *wkv2, *wp2, *qp2, *kp2, *vp2, *ao2;
    cudaGetSymbolAddress((void**)&xk, g_xk);
    cudaGetSymbolAddress((void**)&mnq, g_mnq);
    cudaGetSymbolAddress((void**)&mnk, g_mnk);
    cudaGetSymbolAddress((void**)&rmaxu, g_rmaxu);
    cudaGetSymbolAddress((void**)&thr, g_thr);
    cudaGetSymbolAddress((void**)&needp, g_need);
    cudaGetSymbolAddress((void**)&ctr, g_ctr);
    cudaGetSymbolAddress((void**)&xq, g_xq);
    cudaGetSymbolAddress((void**)&xkm, g_xkm);
    cudaGetSymbolAddress((void**)&kvm, g_kvm);
    cudaGetSymbolAddress((void**)&S, g_S);
    cudaGetSymbolAddress((void**)&ou, g_ou);
    cudaGetSymbolAddress((void**)&proj, g_proj);
    cudaGetSymbolAddress((void**)&keyq, g_keyq);
    cudaGetSymbolAddress((void**)&keyk, g_keyk);
    cudaGetSymbolAddress((void**)&permq, g_permq);
    cudaGetSymbolAddress((void**)&permk, g_permk);
    cudaGetSymbolAddress((void**)&dstq, g_dstq);
    cudaGetSymbolAddress((void**)&dstk, g_dstk);
    cudaGetSymbolAddress((void**)&cntq, g_cntq);
    cudaGetSymbolAddress((void**)&cntk, g_cntk);
    cudaGetSymbolAddress((void**)&aq, g_aq);
    cudaGetSymbolAddress((void**)&bq, g_bq);
    cudaGetSymbolAddress((void**)&ak, g_ak);
    cudaGetSymbolAddress((void**)&bk, g_bk);
    cudaGetSymbolAddress((void**)&ctok, g_ctok);
    cudaGetSymbolAddress((void**)&x3, g_x3);
    cudaGetSymbolAddress((void**)&bt3, g_bt3);
    cudaGetSymbolAddress((void**)&mq1, g_mq1);
    cudaGetSymbolAddress((void**)&mk1, g_mk1);
    cudaGetSymbolAddress((void**)&xq2, g_xq2);
    cudaGetSymbolAddress((void**)&xkm2, g_xkm2);
    cudaGetSymbolAddress((void**)&wq2, g_wq2);
    cudaGetSymbolAddress((void**)&wkv2, g_wkv2);
    cudaGetSymbolAddress((void**)&wp2, g_wp2);
    cudaGetSymbolAddress((void**)&qp2, g_qp2);
    cudaGetSymbolAddress((void**)&kp2, g_kp2);
    cudaGetSymbolAddress((void**)&vp2, g_vp2);
    cudaGetSymbolAddress((void**)&ao2, g_ao2);

    const long PXQ = (long)NQ * CC;
    const long PBT = (long)8 * CC * CC;
    const long PQ2 = (long)MQ * CC;
    const long PK2 = (long)MK * CC;
    const long PWQ = (long)CC * CC;
    const long PWKV = (long)2 * CC * CC;
    const long PQP = (long)HEADS * MQ * HD;
    const long PKP = (long)HEADS * MK * HD;
    const long PVP = (long)HEADS * VN * MK;
    float* Skv = S + (long)NAQ * NDQ;

    // 1-3: conv prerequisites (prep_x also covers rownorm+cvt of x)
    prep_x_kernel<<<NQ, 256>>>(x, x3, x3 + PXQ, x3 + 2 * PXQ, mnq, mq1);
    split3_bt_kernel<<<(int)((PBT + 255) / 256), 256>>>(srw, bt3, bt3 + PBT, bt3 + 2 * PBT);
    conv_tok_kernel<<<(8 * N2 + 255) / 256, 256>>>(ctok);
    // 4: conv GEMM (profiled slot)
    mmg<6, 64, 2, 0, false><<<dim3(CC / 64, N2 / 64, 1), 512, SM_6_64_2>>>(
        x3, x3 + PXQ, x3 + 2 * PXQ, CC, 0,
        bt3, bt3 + PBT, bt3 + 2 * PBT, CC, 0, (long)CC * CC,
        xk, CC, 0, srb, 1.f, nullptr, nullptr, 0, nullptr,
        CC, CC, 8, ctok, N2, nullptr);
    // 5: fused LN + rownorm + cvt
    ln_norm_kernel<<<N2, 256>>>(xk, lng, lnb, mnk, mk1);
    build_idx_kernel<<<(NQ + 255) / 256, 256>>>(D0, H0, W0, aq, bq);
    build_idx_kernel<<<(N2 + 255) / 256, 256>>>(D0 / 2, H0 / 2, W0 / 2, ak, bk);

    // ---- q-side BSM ----
    set_u32_kernel<<<(NAQ + 255) / 256, 256>>>(rmaxu, NAQ, 0u);
    mmg<1, 128, 3, 1, false><<<dim3(NDQ / 128, NAQ / 64, 1), 512, SM_1_128_3>>>(
        mq1, nullptr, nullptr, CC, 0,
        mq1, nullptr, nullptr, CC, 0, 0,
        S, NDQ, 0, nullptr, 1.f, nullptr, nullptr, 0, rmaxu,
        NDQ, CC, 1, aq, 0, bq);
    refine_kernel<<<NAQ / 8, 256>>>(S, NDQ, mnq, aq, bq, rmaxu, keyq, 2e-3f);
    select_kernel<<<1, 1024>>>(keyq, NAQ, RQ, thr, needp, ctr);
    partition_kernel<<<(NAQ + 255) / 256, 256>>>(keyq, NAQ, RQ, thr, needp, ctr, permq);
    set_int_kernel<<<(NDQ + 255) / 256, 256>>>(cntq, NDQ, 1);
    fill_dst_kernel<<<(RQ + 255) / 256, 256>>>(permq, keyq, dstq, cntq, RQ);
    merge_gather_kernel<<<MQ, 256>>>(x, xq, xq2, xq2 + PQ2, aq, bq, permq, UQ, RQ);
    scatter_add_kernel<<<RQ, 256>>>(x, xq, aq, permq, dstq, UQ);
    div_cnt_kernel<<<NDQ, 256>>>(xq, cntq, xq2, xq2 + PQ2, UQ);

    // ---- kv-side BSM ----
    set_u32_kernel<<<(NAK + 255) / 256, 256>>>(rmaxu, NAK, 0u);
    mmg<1, 64, 3, 1, false><<<dim3(NDK / 64, NAK / 64, 1), 512, SM_1_64_3>>>(
        mk1, nullptr, nullptr, CC, 0,
        mk1, nullptr, nullptr, CC, 0, 0,
        Skv, NDK, 0, nullptr, 1.f, nullptr, nullptr, 0, rmaxu,
        NDK, CC, 1, ak, 0, bk);
    refine_kernel<<<NAK / 8, 256>>>(Skv, NDK, mnk, ak, bk, rmaxu, keyk, 2e-3f);
    select_kernel<<<1, 1024>>>(keyk, NAK, RK, thr + 1, needp + 1, ctr + 2);
    partition_kernel<<<(NAK + 255) / 256, 256>>>(keyk, NAK, RK, thr + 1, needp + 1, ctr + 2, permk);
    set_int_kernel<<<1, 256>>>(cntk, NDK, 1);
    fill_dst_kernel<<<(RK + 255) / 256, 256>>>(permk, keyk, dstk, cntk, RK);
    merge_gather_kernel<<<MK, 256>>>(xk, xkm, xkm2, xkm2 + PK2, ak, bk, permk, UK, RK);
    scatter_add_kernel<<<RK, 256>>>(xk, xkm, ak, permk, dstk, UK);
    div_cnt_kernel<<<NDK, 256>>>(xkm, cntk, xkm2, xkm2 + PK2, UK);

    // ---- projections ----
    split2_w3_kernel<<<(int)((PWQ + PWKV + PWQ + 255) / 256), 256>>>(
        Wq, wq2, wq2 + PWQ, PWQ,
        Wkv, wkv2, wkv2 + PWKV, PWKV,
        Wp, wp2, wp2 + PWQ, PWQ);
    // Wq -> head-major bf16 Q planes directly (EPI2)
    mmg<3, 64, 3, 2, false><<<dim3(CC / 64, MQ / 64, 1), 512, SM_3_64_3>>>(
        xq2, xq2 + PQ2, nullptr, CC, 0,
        wq2, wq2 + PWQ, nullptr, CC, 0, 0,
        nullptr, 0, 0, nullptr, 1.f, qp2, qp2 + PQP, (long)MQ * HD, nullptr,
        CC, CC, 1, nullptr, 0, nullptr);
    mmg<3, 64, 3, 0, false><<<dim3(2 * CC / 64, MK / 64, 1), 512, SM_3_64_3>>>(
        xkm2, xkm2 + PK2, nullptr, CC, 0,
        wkv2, wkv2 + PWKV, nullptr, CC, 0, 0,
        kvm, 2 * CC, 0, nullptr, 1.f, nullptr, nullptr, 0, nullptr,
        2 * CC, CC, 1, nullptr, 0, nullptr);

    // ---- head prep ----
    split_kpad_kernel<<<(int)((PKP + 255) / 256), 256>>>(kvm, kp2, kp2 + PKP);
    split_vT_kernel<<<(int)((PVP + 255) / 256), 256>>>(kvm, vp2, vp2 + PVP);

    // ---- attention: QK (K=96, TK) with fused per-(head,row) rowmax ----
    float scl = 1.0f / sqrtf((float)HD);
    set_u32_kernel<<<(HEADS * MQ + 255) / 256, 256>>>(rmaxu, HEADS * MQ, 0u);
    mmg<3, 64, 3, 1, true><<<dim3(MK / 64, MQ / 64, HEADS), 512, SM_3_64_3>>>(
        qp2, qp2 + PQP, nullptr, HD, (long)MQ * HD,
        kp2, kp2 + PKP, nullptr, HD, (long)MK * HD, 0,
        S, MK, (long)MQ * MK, nullptr, scl, nullptr, nullptr, MQ, rmaxu,
        MK, HD, 1, nullptr, 0, nullptr);
    // ---- AV with inline exp(S - rmax): A = fp32 S, B = V planes (+ones row) ----
    mmg<3, 64, 3, 0, false, true><<<dim3(2, MQ / 64, HEADS), 512, SM_3_64_3>>>(
        (const bf16*)S, nullptr, nullptr, MK, (long)MQ * MK,
        vp2, vp2 + PVP, nullptr, MK, (long)VN * MK, 0,
        ou, OLD, (long)MQ * OLD, nullptr, 1.f, nullptr, nullptr, MQ, rmaxu,
        VN, MK, 1, nullptr, 0, nullptr);
    // ---- normalize + split to ao2 planes ----
    normalize_kernel<<<MQ, 256>>>(ou, ao2, ao2 + PQ2);

    // ---- output projection + unmerge ----
    mmg<3, 64, 3, 0, false><<<dim3(CC / 64, MQ / 64, 1), 512, SM_3_64_3>>>(
        ao2, ao2 + PQ2, nullptr, CC, 0,
        wp2, wp2 + PWQ, nullptr, CC, 0, 0,
        proj, CC, 0, bp, 1.f, nullptr, nullptr, 0, nullptr,
        CC, CC, 1, nullptr, 0, nullptr);
    unmerge_kernel<<<NQ, 256>>>(proj, out, aq, bq, permq, dstq);
}